// round 11
// baseline (speedup 1.0000x reference)
#include <cuda_runtime.h>
#include <cuda_bf16.h>
#include <cooperative_groups.h>
#include <cstdint>

namespace cg = cooperative_groups;

#define NODES 100000
#define EDGES 1600000

// ---- device scratch (allocation-free contract: __device__ globals) ----
__device__ __align__(16) float g_y0  [NODES*64];
__device__ __align__(16) float g_base[NODES*64];
__device__ __align__(16) float g_e0  [NODES*64];
__device__ __align__(16) float g_h   [NODES*64];
__device__ __align__(16) float g_y1  [NODES*16];
__device__ __align__(16) float g_r1  [NODES*16];
__device__ __align__(16) float g_er1 [NODES*16];
// CSR-by-dst
__device__ int g_cnt [NODES];
__device__ int g_off [NODES + 1];
__device__ int g_cur [NODES];
__device__ int g_esrc[EDGES];
__device__ int g_bsum[1024];

#if defined(__CUDA_ARCH__) && (defined(__CUDA_ARCH_FEAT_SM103_ALL) || defined(__CUDA_ARCH_FEAT_SM100_ALL))
#define HAS_TCGEN05 1
#else
#define HAS_TCGEN05 0
#endif

// ==================== cooperative CSR build (zero/hist/scan) ===========
__global__ void __launch_bounds__(256) k_csr_build(const int* __restrict__ ei,
                                                   int n, int E)
{
    cg::grid_group grid = cg::this_grid();
    const int tid = threadIdx.x;
    const int b   = blockIdx.x;
    const int G   = gridDim.x;
    const int lane = tid & 31;
    const int w    = tid >> 5;
    __shared__ int ws[8];

    for (int i = b * 256 + tid; i < n; i += G * 256) g_cnt[i] = 0;
    grid.sync();

    for (int e = b * 256 + tid; e < E; e += G * 256)
        atomicAdd(&g_cnt[ei[E + e]], 1);
    grid.sync();

    {
        int i = b * 256 + tid;
        int v = (i < n) ? g_cnt[i] : 0;
        int x = v;
        #pragma unroll
        for (int d = 1; d < 32; d <<= 1) {
            int t = __shfl_up_sync(0xFFFFFFFF, x, d);
            if (lane >= d) x += t;
        }
        if (lane == 31) ws[w] = x;
        __syncthreads();
        int base = 0;
        #pragma unroll
        for (int k = 0; k < 8; k++) base += (k < w) ? ws[k] : 0;
        int incl = base + x;
        if (i < n) g_off[i] = incl - v;
        if (tid == 0) {
            int tot = 0;
            #pragma unroll
            for (int k = 0; k < 8; k++) tot += ws[k];
            g_bsum[b] = tot;
        }
    }
    grid.sync();

    if (b == 0) {
        int per = (G + 255) / 256;
        int s[4];
        int sum = 0;
        #pragma unroll 4
        for (int j = 0; j < per; j++) {
            int idx = tid * per + j;
            s[j] = (idx < G) ? g_bsum[idx] : 0;
            sum += s[j];
        }
        int x = sum;
        #pragma unroll
        for (int d = 1; d < 32; d <<= 1) {
            int t = __shfl_up_sync(0xFFFFFFFF, x, d);
            if (lane >= d) x += t;
        }
        if (lane == 31) ws[w] = x;
        __syncthreads();
        int base = 0;
        #pragma unroll
        for (int k = 0; k < 8; k++) base += (k < w) ? ws[k] : 0;
        int run = base + x - sum;
        #pragma unroll 4
        for (int j = 0; j < per; j++) {
            int idx = tid * per + j;
            if (idx < G) { g_bsum[idx] = run; run += s[j]; }
        }
    }
    grid.sync();

    {
        int i = b * 256 + tid;
        if (i < n) {
            int o = g_off[i] + g_bsum[b];
            g_off[i] = o;
            g_cur[i] = o;
        }
        if (b == 0 && tid == 0) g_off[n] = E;
    }
}

__global__ void k_fill(const int* __restrict__ ei, int E) {
    int e = blockIdx.x * blockDim.x + threadIdx.x;
    if (e >= E) return;
    int dst = ei[E + e];
    int pos = atomicAdd(&g_cur[dst], 1);
    g_esrc[pos] = ei[e];
}

// ================= persistent transform0 smem layout =================
static constexpr int SM_BH   = 0;        // B hi 128x128 bf16 = 32KB
static constexpr int SM_BL   = 32768;    // B lo
static constexpr int SM_A0H  = 65536;    // A buf0 hi
static constexpr int SM_A0L  = 98304;    // A buf0 lo
static constexpr int SM_A1H  = 131072;   // A buf1 hi
static constexpr int SM_A1L  = 163840;   // A buf1 lo
static constexpr int SM_TMEM = 196608;
static constexpr int SM_MBAR0= 196616;
static constexpr int SM_MBAR1= 196624;
static constexpr int SM_TOTAL_MMA = 196640;

#if HAS_TCGEN05
__device__ __forceinline__ uint32_t smem_u32(const void* p) {
    uint32_t a;
    asm("{ .reg .u64 t; cvta.to.shared.u64 t, %1; cvt.u32.u64 %0, t; }"
        : "=r"(a) : "l"(p));
    return a;
}

__device__ __forceinline__ uint32_t elect_one() {
    uint32_t pred;
    asm volatile("{ .reg .pred p; elect.sync _|p, 0xFFFFFFFF; selp.b32 %0, 1, 0, p; }"
                 : "=r"(pred));
    return pred;
}

static constexpr uint32_t MMA_IDESC = (1u<<4) | (1u<<7) | (1u<<10)
                                    | ((128u/8u)<<17) | ((128u/16u)<<24);

static constexpr uint64_t DESC_BASE =
    (uint64_t(2) << 61) | (uint64_t(1) << 46) | (uint64_t(64) << 32) | (uint64_t(1) << 16);

__device__ __forceinline__ uint64_t make_desc(uint32_t addr) {
    return DESC_BASE | ((uint64_t)(addr >> 4) & 0x3FFF);
}

__device__ __forceinline__ void mma_bf16_ss(uint32_t d_tmem, uint64_t a_desc,
                                            uint64_t b_desc, uint32_t en) {
    asm volatile(
        "{\n\t"
        ".reg .pred p;\n\t"
        "setp.ne.u32 p, %4, 0;\n\t"
        "tcgen05.mma.cta_group::1.kind::f16 [%0], %1, %2, %3, {%5, %5, %5, %5}, p;\n\t"
        "}"
        :: "r"(d_tmem), "l"(a_desc), "l"(b_desc), "r"(MMA_IDESC),
           "r"(en), "r"(0u)
        : "memory");
}

__device__ __forceinline__ void mbar_wait(uint32_t mbar, uint32_t parity) {
    uint32_t done;
    asm volatile(
        "{\n\t.reg .pred p;\n\t"
        "mbarrier.try_wait.parity.acquire.cta.shared::cta.b64 p, [%1], %2;\n\t"
        "selp.b32 %0, 1, 0, p;\n\t}"
        : "=r"(done) : "r"(mbar), "r"(parity) : "memory");
    if (!done) {
        asm volatile(
            "{\n\t.reg .pred P1;\n\t"
            "WAIT_LOOP_%=:\n\t"
            "mbarrier.try_wait.parity.acquire.cta.shared::cta.b64 P1, [%0], %1, 0x989680;\n\t"
            "@P1 bra.uni WAIT_DONE_%=;\n\t"
            "bra.uni WAIT_LOOP_%=;\n\t"
            "WAIT_DONE_%=:\n\t}"
            :: "r"(mbar), "r"(parity) : "memory");
    }
}

#define TCLD_X32(r, addr) \
    asm volatile( \
        "tcgen05.ld.sync.aligned.32x32b.x32.b32 " \
        "{%0, %1, %2, %3, %4, %5, %6, %7, " \
        " %8, %9, %10, %11, %12, %13, %14, %15, " \
        " %16, %17, %18, %19, %20, %21, %22, %23, " \
        " %24, %25, %26, %27, %28, %29, %30, %31}, [%32];" \
        : "=r"((r)[0]), "=r"((r)[1]), "=r"((r)[2]), "=r"((r)[3]), \
          "=r"((r)[4]), "=r"((r)[5]), "=r"((r)[6]), "=r"((r)[7]), \
          "=r"((r)[8]), "=r"((r)[9]), "=r"((r)[10]), "=r"((r)[11]), \
          "=r"((r)[12]), "=r"((r)[13]), "=r"((r)[14]), "=r"((r)[15]), \
          "=r"((r)[16]), "=r"((r)[17]), "=r"((r)[18]), "=r"((r)[19]), \
          "=r"((r)[20]), "=r"((r)[21]), "=r"((r)[22]), "=r"((r)[23]), \
          "=r"((r)[24]), "=r"((r)[25]), "=r"((r)[26]), "=r"((r)[27]), \
          "=r"((r)[28]), "=r"((r)[29]), "=r"((r)[30]), "=r"((r)[31]) \
        : "r"(addr))
#endif

__device__ __forceinline__ uint32_t tile_off(int row, int k) {
    uint32_t off = (uint32_t)((row >> 3) + (k >> 6) * 16) * 1024
                 + (uint32_t)(row & 7) * 128 + (uint32_t)(k & 63) * 2;
    return off ^ ((off >> 3) & 0x70);
}

__device__ __forceinline__ void cvt_store_hl(char* ph, char* pl, float4 v) {
    __nv_bfloat16 h0 = __float2bfloat16(v.x);
    __nv_bfloat16 h1 = __float2bfloat16(v.y);
    __nv_bfloat16 h2 = __float2bfloat16(v.z);
    __nv_bfloat16 h3 = __float2bfloat16(v.w);
    __nv_bfloat16 l0 = __float2bfloat16(v.x - __bfloat162float(h0));
    __nv_bfloat16 l1 = __float2bfloat16(v.y - __bfloat162float(h1));
    __nv_bfloat16 l2 = __float2bfloat16(v.z - __bfloat162float(h2));
    __nv_bfloat16 l3 = __float2bfloat16(v.w - __bfloat162float(h3));
    union { __nv_bfloat162 b[2]; uint64_t u; } uh, ul;
    uh.b[0] = __halves2bfloat162(h0, h1);
    uh.b[1] = __halves2bfloat162(h2, h3);
    ul.b[0] = __halves2bfloat162(l0, l1);
    ul.b[1] = __halves2bfloat162(l2, l3);
    *(uint64_t*)ph = uh.u;
    *(uint64_t*)pl = ul.u;
}

// ---------------------------------------------------------------------
// persistent transform0: [y0 | base] = x_feat @ [Wl0 ; Wr0]^T
__global__ void __launch_bounds__(256) k_transform0(
    const float* __restrict__ x, const float* __restrict__ Wl,
    const float* __restrict__ Wr, const float* __restrict__ bl, int n)
{
    extern __shared__ __align__(1024) char smem[];
    const int tid = threadIdx.x;
    const int T = (n + 127) / 128;

#if HAS_TCGEN05
    const int wid = tid >> 5;
    const int lid = tid & 31;
    const uint32_t sbase = smem_u32(smem);

    if (wid == 0) {
        asm volatile("tcgen05.alloc.cta_group::1.sync.aligned.shared::cta.b32 [%0], %1;"
                     :: "r"(sbase + SM_TMEM), "r"(256u) : "memory");
    }
    if (tid == 0) {
        asm volatile("mbarrier.init.shared.b64 [%0], %1;"
                     :: "r"(sbase + SM_MBAR0), "r"(1u) : "memory");
        asm volatile("mbarrier.init.shared.b64 [%0], %1;"
                     :: "r"(sbase + SM_MBAR1), "r"(1u) : "memory");
    }

    const float4* Wl4 = (const float4*)Wl;
    const float4* Wr4 = (const float4*)Wr;
    for (int m = tid; m < 128 * 32; m += 256) {
        int row = m >> 5, kq = m & 31;
        float4 v = (row < 64) ? Wl4[row * 32 + kq] : Wr4[(row - 64) * 32 + kq];
        uint32_t off = tile_off(row, kq * 4);
        cvt_store_hl(smem + SM_BH + off, smem + SM_BL + off, v);
    }
    __syncthreads();

    uint32_t tmem_base;
    asm volatile("ld.shared.b32 %0, [%1];" : "=r"(tmem_base) : "r"(sbase + SM_TMEM));

    const float4* X4 = (const float4*)x;
    const uint32_t abufH[2] = { sbase + SM_A0H, sbase + SM_A1H };
    const uint32_t mbar[2]  = { sbase + SM_MBAR0, sbase + SM_MBAR1 };
    uint64_t dB_h = make_desc(sbase + SM_BH);
    uint64_t dB_l = make_desc(sbase + SM_BL);
    int ph0 = 0, ph1 = 0;

    #define STAGE_A(tile, buf) do {                                         \
        int _n0 = (tile) * 128;                                             \
        char* _ah = smem + SM_A0H + (buf) * 65536;                          \
        char* _al = _ah + 32768;                                            \
        for (int m = tid; m < 128 * 32; m += 256) {                         \
            int row = m >> 5, kq = m & 31;                                  \
            int gi = _n0 + row;                                             \
            float4 v = make_float4(0.f, 0.f, 0.f, 0.f);                     \
            if (gi < n) v = X4[gi * 32 + kq];                               \
            uint32_t off = tile_off(row, kq * 4);                           \
            cvt_store_hl(_ah + off, _al + off, v);                          \
        }                                                                   \
    } while (0)

    #define ISSUE_MMA(buf) do {                                             \
        if (wid == 0) {                                                      \
            if (elect_one()) {                                               \
                asm volatile("fence.proxy.async.shared::cta;" ::: "memory"); \
                uint64_t dAh = make_desc(abufH[buf]);                        \
                uint64_t dAl = make_desc(abufH[buf] + 32768);                \
                uint64_t pA[3] = { dAh, dAh, dAl };                          \
                uint64_t pB[3] = { dB_h, dB_l, dB_h };                       \
                uint32_t dst = tmem_base + (buf) * 128;                      \
                uint32_t en = 0;                                             \
                _Pragma("unroll")                                            \
                for (int p = 0; p < 3; p++) {                                \
                    _Pragma("unroll")                                        \
                    for (int ks = 0; ks < 8; ks++) {                         \
                        uint64_t doff = (uint64_t)((ks & 3) * 2 + (ks >> 2) * 1024); \
                        mma_bf16_ss(dst, pA[p] + doff, pB[p] + doff, en);    \
                        en = 1;                                              \
                    }                                                        \
                }                                                            \
                asm volatile(                                                \
                    "tcgen05.commit.cta_group::1.mbarrier::arrive::one.shared::cluster.b64 [%0];" \
                    :: "r"(mbar[buf]) : "memory");                           \
            }                                                                \
        }                                                                    \
    } while (0)

    int t = blockIdx.x;
    int k = 0;
    if (t < T) {
        STAGE_A(t, 0);
        __syncthreads();
        ISSUE_MMA(0);
    }
    for (; t < T; t += gridDim.x, k++) {
        int buf = k & 1;
        int tn = t + gridDim.x;
        if (tn < T) {
            STAGE_A(tn, buf ^ 1);
            __syncthreads();
            ISSUE_MMA(buf ^ 1);
        }
        if (buf == 0) { mbar_wait(mbar[0], ph0); ph0 ^= 1; }
        else          { mbar_wait(mbar[1], ph1); ph1 ^= 1; }
        asm volatile("tcgen05.fence::after_thread_sync;" ::: "memory");

        {
            int row = (wid & 3) * 32 + lid;
            int gi = t * 128 + row;
            uint32_t taddr = tmem_base + buf * 128 + ((uint32_t)(wid & 3) << 21)
                           + ((wid < 4) ? 0u : 64u);
            uint32_t r0[32], r1[32];
            TCLD_X32(r0, taddr);
            TCLD_X32(r1, taddr + 32);
            asm volatile("tcgen05.wait::ld.sync.aligned;" ::: "memory");
            if (gi < n) {
                if (wid < 4) {
                    #pragma unroll
                    for (int j = 0; j < 8; j++) {
                        float4 v = make_float4(__uint_as_float(r0[j*4+0]),
                                               __uint_as_float(r0[j*4+1]),
                                               __uint_as_float(r0[j*4+2]),
                                               __uint_as_float(r0[j*4+3]));
                        ((float4*)g_y0)[gi * 16 + j] = v;
                    }
                    #pragma unroll
                    for (int j = 0; j < 8; j++) {
                        float4 v = make_float4(__uint_as_float(r1[j*4+0]),
                                               __uint_as_float(r1[j*4+1]),
                                               __uint_as_float(r1[j*4+2]),
                                               __uint_as_float(r1[j*4+3]));
                        ((float4*)g_y0)[gi * 16 + 8 + j] = v;
                    }
                } else {
                    #pragma unroll
                    for (int j = 0; j < 8; j++) {
                        float4 bb = ((const float4*)bl)[j];
                        float4 v = make_float4(__uint_as_float(r0[j*4+0]) + bb.x,
                                               __uint_as_float(r0[j*4+1]) + bb.y,
                                               __uint_as_float(r0[j*4+2]) + bb.z,
                                               __uint_as_float(r0[j*4+3]) + bb.w);
                        ((float4*)g_base)[gi * 16 + j] = v;
                    }
                    #pragma unroll
                    for (int j = 0; j < 8; j++) {
                        float4 bb = ((const float4*)bl)[8 + j];
                        float4 v = make_float4(__uint_as_float(r1[j*4+0]) + bb.x,
                                               __uint_as_float(r1[j*4+1]) + bb.y,
                                               __uint_as_float(r1[j*4+2]) + bb.z,
                                               __uint_as_float(r1[j*4+3]) + bb.w);
                        ((float4*)g_base)[gi * 16 + 8 + j] = v;
                    }
                }
            }
            asm volatile("tcgen05.fence::before_thread_sync;" ::: "memory");
        }
        __syncthreads();
    }
    if (wid == 0) {
        asm volatile("tcgen05.dealloc.cta_group::1.sync.aligned.b32 %0, %1;"
                     :: "r"(tmem_base), "r"(256u));
    }
    #undef STAGE_A
    #undef ISSUE_MMA

#else  // ---------------- FFMA fallback (compute_103 PTX pass) ----------------
    float* Ws = (float*)smem;
    float* Xs = (float*)smem + 128 * 128;

    const float4* Wl4 = (const float4*)Wl;
    const float4* Wr4 = (const float4*)Wr;
    for (int m = tid; m < 64 * 32; m += 256) {
        int o  = m & 63;
        int kq = m >> 6;
        float4 a = Wl4[o * 32 + kq];
        float4 b = Wr4[o * 32 + kq];
        int k = kq * 4;
        Ws[(k+0)*128 + o] = a.x;  Ws[(k+1)*128 + o] = a.y;
        Ws[(k+2)*128 + o] = a.z;  Ws[(k+3)*128 + o] = a.w;
        Ws[(k+0)*128 + 64 + o] = b.x;  Ws[(k+1)*128 + 64 + o] = b.y;
        Ws[(k+2)*128 + 64 + o] = b.z;  Ws[(k+3)*128 + 64 + o] = b.w;
    }
    const float4* X4 = (const float4*)x;
    float4* Xs4 = (float4*)Xs;

    for (int t = blockIdx.x; t < T; t += gridDim.x) {
        int n0 = t * 128;
        __syncthreads();
        for (int m = tid; m < 128 * 32; m += 256) {
            int node = m >> 5;
            int kq   = m & 31;
            int gi = n0 + node;
            float4 v = make_float4(0.f, 0.f, 0.f, 0.f);
            if (gi < n) v = X4[gi * 32 + kq];
            Xs4[node * 32 + kq] = v;
        }
        __syncthreads();

        const int tx = tid & 15;
        const int ty = tid >> 4;
        float acc[8][8];
        #pragma unroll
        for (int s = 0; s < 8; s++)
            #pragma unroll
            for (int r = 0; r < 8; r++) acc[s][r] = 0.f;

        const float4* Ws4c = (const float4*)Ws;
        const float4* Xs4c = (const float4*)Xs;

        for (int k = 0; k < 128; k += 4) {
            float4 xv[8];
            #pragma unroll
            for (int s = 0; s < 8; s++)
                xv[s] = Xs4c[((ty + 16 * s) * 128 + k) >> 2];
            #pragma unroll
            for (int kk = 0; kk < 4; kk++) {
                float4 wa = Ws4c[((k + kk) * 128 >> 2) + tx];
                float4 wb = Ws4c[(((k + kk) * 128 + 64) >> 2) + tx];
                #pragma unroll
                for (int s = 0; s < 8; s++) {
                    float xs = (kk == 0) ? xv[s].x : (kk == 1) ? xv[s].y
                             : (kk == 2) ? xv[s].z : xv[s].w;
                    acc[s][0] = fmaf(xs, wa.x, acc[s][0]);
                    acc[s][1] = fmaf(xs, wa.y, acc[s][1]);
                    acc[s][2] = fmaf(xs, wa.z, acc[s][2]);
                    acc[s][3] = fmaf(xs, wa.w, acc[s][3]);
                    acc[s][4] = fmaf(xs, wb.x, acc[s][4]);
                    acc[s][5] = fmaf(xs, wb.y, acc[s][5]);
                    acc[s][6] = fmaf(xs, wb.z, acc[s][6]);
                    acc[s][7] = fmaf(xs, wb.w, acc[s][7]);
                }
            }
        }

        float4 bb = ((const float4*)bl)[tx];
        #pragma unroll
        for (int s = 0; s < 8; s++) {
            int gi = n0 + ty + 16 * s;
            if (gi >= n) continue;
            float4 v0 = make_float4(acc[s][0], acc[s][1], acc[s][2], acc[s][3]);
            float4 v1 = make_float4(acc[s][4] + bb.x, acc[s][5] + bb.y,
                                    acc[s][6] + bb.z, acc[s][7] + bb.w);
            ((float4*)g_y0)  [gi * 16 + tx] = v0;
            ((float4*)g_base)[gi * 16 + tx] = v1;
        }
    }
#endif
}

// ---------------------------------------------------------------------
// FUSED gather0 + emb0 + combine0: grid-stride, one warp per node.
// e0 = mean(x_emb) @ We0^T + be0 (computed in-warp, FMA fills idle issue)
// h  = relu(mean_agg(y0) + base + e0);  also writes g_e0 for transform1.
__global__ void __launch_bounds__(256) k_gather0(
    const float* __restrict__ xe, const float* __restrict__ We,
    const float* __restrict__ be, int n)
{
    __shared__ __align__(16) float Ws[64 * 64];   // [k][o] fp32
    const int tid = threadIdx.x;

    // stage We0 transposed to k-major
    const float4* W4 = (const float4*)We;
    for (int m = tid; m < 64 * 16; m += 256) {
        int o  = m & 63;
        int kq = m >> 6;
        float4 a = W4[o * 16 + kq];
        int k = kq * 4;
        Ws[(k+0)*64 + o] = a.x;  Ws[(k+1)*64 + o] = a.y;
        Ws[(k+2)*64 + o] = a.z;  Ws[(k+3)*64 + o] = a.w;
    }
    __syncthreads();

    const int lane = tid & 31;
    const int warp0 = (blockIdx.x * 256 + tid) >> 5;
    const int nwarps = (gridDim.x * 256) >> 5;
    const float2* Y   = (const float2*)g_y0;
    const float2* XE2 = (const float2*)xe;
    const float2* Ws2 = (const float2*)Ws;
    float be0x = be[2 * lane];
    float be0y = be[2 * lane + 1];

    for (int node = warp0; node < n; node += nwarps) {
        // ---- e0 for this node (lane owns outputs 2*lane, 2*lane+1) ----
        float2 a = XE2[node * 64 + lane];          // x_emb[node,0,2l..2l+1]
        float2 b = XE2[node * 64 + 32 + lane];     // x_emb[node,1,2l..2l+1]
        float2 mean = make_float2(0.5f * (a.x + b.x), 0.5f * (a.y + b.y));
        float2 e0 = make_float2(be0x, be0y);
        #pragma unroll
        for (int kk = 0; kk < 32; kk++) {
            float mx = __shfl_sync(0xFFFFFFFF, mean.x, kk);
            float my = __shfl_sync(0xFFFFFFFF, mean.y, kk);
            float2 w0 = Ws2[(2 * kk) * 32 + lane];
            float2 w1 = Ws2[(2 * kk + 1) * 32 + lane];
            e0.x = fmaf(mx, w0.x, e0.x);
            e0.y = fmaf(mx, w0.y, e0.y);
            e0.x = fmaf(my, w1.x, e0.x);
            e0.y = fmaf(my, w1.y, e0.y);
        }

        // ---- neighbor aggregation (unroll 4) ----
        int beg = g_off[node];
        int end = g_off[node + 1];
        float2 acc = make_float2(0.f, 0.f);
        int e = beg;
        for (; e + 3 < end; e += 4) {
            int s0 = g_esrc[e];
            int s1 = g_esrc[e + 1];
            int s2 = g_esrc[e + 2];
            int s3 = g_esrc[e + 3];
            float2 v0 = Y[s0 * 32 + lane];
            float2 v1 = Y[s1 * 32 + lane];
            float2 v2 = Y[s2 * 32 + lane];
            float2 v3 = Y[s3 * 32 + lane];
            acc.x += (v0.x + v1.x) + (v2.x + v3.x);
            acc.y += (v0.y + v1.y) + (v2.y + v3.y);
        }
        for (; e < end; e++) {
            int s0 = g_esrc[e];
            float2 v0 = Y[s0 * 32 + lane];
            acc.x += v0.x;
            acc.y += v0.y;
        }
        float inv = 1.0f / fmaxf((float)(end - beg), 1.0f);
        float2 bs = ((const float2*)g_base)[node * 32 + lane];
        float2 h;
        h.x = fmaxf(fmaf(acc.x, inv, bs.x + e0.x), 0.f);
        h.y = fmaxf(fmaf(acc.y, inv, bs.y + e0.y), 0.f);
        ((float2*)g_h )[node * 32 + lane] = h;
        ((float2*)g_e0)[node * 32 + lane] = e0;
    }
}

// ---------------------------------------------------------------------
// Layer-1 node transforms: y1 = h@Wl1^T, r1 = h@Wr1^T, er1 = e0@We1^T.
__global__ void __launch_bounds__(96) k_transform1(
    const float* __restrict__ Wl1, const float* __restrict__ Wr1,
    const float* __restrict__ We1, int n)
{
    __shared__ __align__(16) float Hs[64 * 64];
    __shared__ __align__(16) float Es[64 * 64];
    __shared__ __align__(16) float Ws[64 * 48];
    const int tid = threadIdx.x;
    const int n0 = blockIdx.x * 64;

    for (int m = tid; m < 48 * 16; m += 96) {
        int o  = m % 48;
        int kq = m / 48;
        const float4* src = (o < 16) ? ((const float4*)Wl1) + o * 16
                          : (o < 32) ? ((const float4*)Wr1) + (o - 16) * 16
                                     : ((const float4*)We1) + (o - 32) * 16;
        float4 a = src[kq];
        int k = kq * 4;
        Ws[(k+0)*48 + o] = a.x;  Ws[(k+1)*48 + o] = a.y;
        Ws[(k+2)*48 + o] = a.z;  Ws[(k+3)*48 + o] = a.w;
    }
    for (int m = tid; m < 64 * 16; m += 96) {
        int node = m >> 4;
        int kq   = m & 15;
        int gi = n0 + node;
        float4 v = make_float4(0.f, 0.f, 0.f, 0.f);
        float4 w = v;
        if (gi < n) {
            v = ((const float4*)g_h )[gi * 16 + kq];
            w = ((const float4*)g_e0)[gi * 16 + kq];
        }
        ((float4*)Hs)[node * 16 + kq] = v;
        ((float4*)Es)[node * 16 + kq] = w;
    }
    __syncthreads();

    const int g  = tid % 12;
    const int ty = tid / 12;
    const float* In = (g < 8) ? Hs : Es;
    float acc[8][4];
    #pragma unroll
    for (int s = 0; s < 8; s++)
        #pragma unroll
        for (int r = 0; r < 4; r++) acc[s][r] = 0.f;

    for (int k = 0; k < 64; k++) {
        float4 w = ((const float4*)Ws)[k * 12 + g];
        float xv[8];
        #pragma unroll
        for (int s = 0; s < 8; s++) xv[s] = In[(ty + 8 * s) * 64 + k];
        #pragma unroll
        for (int s = 0; s < 8; s++) {
            acc[s][0] = fmaf(xv[s], w.x, acc[s][0]);
            acc[s][1] = fmaf(xv[s], w.y, acc[s][1]);
            acc[s][2] = fmaf(xv[s], w.z, acc[s][2]);
            acc[s][3] = fmaf(xv[s], w.w, acc[s][3]);
        }
    }

    #pragma unroll
    for (int s = 0; s < 8; s++) {
        int gi = n0 + ty + 8 * s;
        if (gi >= n) continue;
        float4 v = make_float4(acc[s][0], acc[s][1], acc[s][2], acc[s][3]);
        if (g < 4)       ((float4*)g_y1 )[gi * 4 + g]       = v;
        else if (g < 8)  ((float4*)g_r1 )[gi * 4 + (g - 4)] = v;
        else             ((float4*)g_er1)[gi * 4 + (g - 8)] = v;
    }
}

// ---------------------------------------------------------------------
// gather1 + final fused: 8 lanes per node, unroll 2.
__global__ void __launch_bounds__(256) k_gather1(
    const float* __restrict__ bl1, const float* __restrict__ be1,
    float* __restrict__ out, int n)
{
    int t = blockIdx.x * 256 + threadIdx.x;
    int node = t >> 3;
    int sub = t & 7;
    if (node >= n) return;
    int beg = g_off[node];
    int end = g_off[node + 1];
    const float2* Y = (const float2*)g_y1;

    float2 acc = make_float2(0.f, 0.f);
    int e = beg;
    for (; e + 1 < end; e += 2) {
        int s0 = g_esrc[e];
        int s1 = g_esrc[e + 1];
        float2 v0 = Y[s0 * 8 + sub];
        float2 v1 = Y[s1 * 8 + sub];
        acc.x += v0.x + v1.x;
        acc.y += v0.y + v1.y;
    }
    if (e < end) {
        int s0 = g_esrc[e];
        float2 v0 = Y[s0 * 8 + sub];
        acc.x += v0.x;
        acc.y += v0.y;
    }
    float inv = 1.0f / fmaxf((float)(end - beg), 1.0f);
    float2 r = ((const float2*)g_r1 )[node * 8 + sub];
    float2 er = ((const float2*)g_er1)[node * 8 + sub];
    float2 o;
    o.x = fmaf(acc.x, inv, r.x + er.x + bl1[2*sub+0] + be1[2*sub+0]);
    o.y = fmaf(acc.y, inv, r.y + er.y + bl1[2*sub+1] + be1[2*sub+1]);
    ((float2*)out)[node * 8 + sub] = o;
}

// ---------------------------------------------------------------------
extern "C" void kernel_launch(void* const* d_in, const int* in_sizes, int n_in,
                              void* d_out, int out_size)
{
    const float* x_feat = (const float*)d_in[0];
    const float* x_emb  = (const float*)d_in[1];
    const int*   ei     = (const int*)  d_in[2];
    const float* Wl0 = (const float*)d_in[3];
    const float* bl0 = (const float*)d_in[4];
    const float* Wr0 = (const float*)d_in[5];
    const float* We0 = (const float*)d_in[6];
    const float* be0 = (const float*)d_in[7];
    const float* Wl1 = (const float*)d_in[8];
    const float* bl1 = (const float*)d_in[9];
    const float* Wr1 = (const float*)d_in[10];
    const float* We1 = (const float*)d_in[11];
    const float* be1 = (const float*)d_in[12];

    int n = in_sizes[0] / 128;
    int E = in_sizes[2] / 2;

    cudaFuncSetAttribute(k_transform0,
                         cudaFuncAttributeMaxDynamicSharedMemorySize, SM_TOTAL_MMA);

    // (1) CSR build: cooperative zero/hist/scan
    {
        int G = (n + 255) / 256;
        void* args[] = { (void*)&ei, (void*)&n, (void*)&E };
        cudaLaunchCooperativeKernel((void*)k_csr_build, dim3(G), dim3(256), args, 0, 0);
    }
    // (2) CSR fill
    k_fill<<<(E + 255) / 256, 256>>>(ei, E);

    // (3) transform0 (persistent MMA)
    k_transform0<<<148, 256, SM_TOTAL_MMA>>>(x_feat, Wl0, Wr0, bl0, n);

    // (4) FUSED gather0 + emb0 + combine0  <-- profiled slot
    k_gather0<<<1184, 256>>>(x_emb, We0, be0, n);

    // (5)(6) layer 1
    k_transform1<<<(n + 63) / 64, 96>>>(Wl1, Wr1, We1, n);
    k_gather1<<<(n * 8 + 255) / 256, 256>>>(bl1, be1, (float*)d_out, n);
}

// round 12
// speedup vs baseline: 1.1205x; 1.1205x over previous
#include <cuda_runtime.h>
#include <cuda_bf16.h>
#include <cooperative_groups.h>
#include <cstdint>

namespace cg = cooperative_groups;

#define NODES 100000
#define EDGES 1600000

// ---- device scratch (allocation-free contract: __device__ globals) ----
__device__ __align__(16) float g_y0  [NODES*64];
__device__ __align__(16) float g_base[NODES*64];
__device__ __align__(16) float g_e0  [NODES*64];
__device__ __align__(16) float g_h   [NODES*64];
__device__ __align__(16) float g_y1  [NODES*16];
__device__ __align__(16) float g_r1  [NODES*16];
__device__ __align__(16) float g_er1 [NODES*16];
// CSR-by-dst
__device__ int g_cnt [NODES];
__device__ int g_off [NODES + 1];
__device__ int g_cur [NODES];
__device__ int g_esrc[EDGES];
__device__ int g_bsum[1024];

#if defined(__CUDA_ARCH__) && (defined(__CUDA_ARCH_FEAT_SM103_ALL) || defined(__CUDA_ARCH_FEAT_SM100_ALL))
#define HAS_TCGEN05 1
#else
#define HAS_TCGEN05 0
#endif

// ==================== cooperative CSR build (zero/hist/scan) ===========
__global__ void __launch_bounds__(256) k_csr_build(const int* __restrict__ ei,
                                                   int n, int E)
{
    cg::grid_group grid = cg::this_grid();
    const int tid = threadIdx.x;
    const int b   = blockIdx.x;
    const int G   = gridDim.x;
    const int lane = tid & 31;
    const int w    = tid >> 5;
    __shared__ int ws[8];

    for (int i = b * 256 + tid; i < n; i += G * 256) g_cnt[i] = 0;
    grid.sync();

    // histogram of dst, int4-vectorized (E is a multiple of 4 here; tail-safe)
    {
        const int4* D4 = (const int4*)(ei + E);
        int q = E >> 2;
        for (int i = b * 256 + tid; i < q; i += G * 256) {
            int4 d = D4[i];
            atomicAdd(&g_cnt[d.x], 1);
            atomicAdd(&g_cnt[d.y], 1);
            atomicAdd(&g_cnt[d.z], 1);
            atomicAdd(&g_cnt[d.w], 1);
        }
        for (int e = (q << 2) + b * 256 + tid; e < E; e += G * 256)
            atomicAdd(&g_cnt[ei[E + e]], 1);
    }
    grid.sync();

    {
        int i = b * 256 + tid;
        int v = (i < n) ? g_cnt[i] : 0;
        int x = v;
        #pragma unroll
        for (int d = 1; d < 32; d <<= 1) {
            int t = __shfl_up_sync(0xFFFFFFFF, x, d);
            if (lane >= d) x += t;
        }
        if (lane == 31) ws[w] = x;
        __syncthreads();
        int base = 0;
        #pragma unroll
        for (int k = 0; k < 8; k++) base += (k < w) ? ws[k] : 0;
        int incl = base + x;
        if (i < n) g_off[i] = incl - v;
        if (tid == 0) {
            int tot = 0;
            #pragma unroll
            for (int k = 0; k < 8; k++) tot += ws[k];
            g_bsum[b] = tot;
        }
    }
    grid.sync();

    if (b == 0) {
        int per = (G + 255) / 256;
        int s[4];
        int sum = 0;
        #pragma unroll 4
        for (int j = 0; j < per; j++) {
            int idx = tid * per + j;
            s[j] = (idx < G) ? g_bsum[idx] : 0;
            sum += s[j];
        }
        int x = sum;
        #pragma unroll
        for (int d = 1; d < 32; d <<= 1) {
            int t = __shfl_up_sync(0xFFFFFFFF, x, d);
            if (lane >= d) x += t;
        }
        if (lane == 31) ws[w] = x;
        __syncthreads();
        int base = 0;
        #pragma unroll
        for (int k = 0; k < 8; k++) base += (k < w) ? ws[k] : 0;
        int run = base + x - sum;
        #pragma unroll 4
        for (int j = 0; j < per; j++) {
            int idx = tid * per + j;
            if (idx < G) { g_bsum[idx] = run; run += s[j]; }
        }
    }
    grid.sync();

    {
        int i = b * 256 + tid;
        if (i < n) {
            int o = g_off[i] + g_bsum[b];
            g_off[i] = o;
            g_cur[i] = o;
        }
        if (b == 0 && tid == 0) g_off[n] = E;
    }
}

// fill edge sources; int4-vectorized loads of src and dst
__global__ void k_fill(const int* __restrict__ ei, int E) {
    int q = E >> 2;
    int i = blockIdx.x * blockDim.x + threadIdx.x;
    const int4* S4 = (const int4*)ei;
    const int4* D4 = (const int4*)(ei + E);
    if (i < q) {
        int4 s = S4[i];
        int4 d = D4[i];
        g_esrc[atomicAdd(&g_cur[d.x], 1)] = s.x;
        g_esrc[atomicAdd(&g_cur[d.y], 1)] = s.y;
        g_esrc[atomicAdd(&g_cur[d.z], 1)] = s.z;
        g_esrc[atomicAdd(&g_cur[d.w], 1)] = s.w;
    }
    // tail
    int e = (q << 2) + i;
    if (i < (E - (q << 2))) {
        int dst = ei[E + e];
        g_esrc[atomicAdd(&g_cur[dst], 1)] = ei[e];
    }
}

// ================= persistent transform0 smem layout =================
static constexpr int SM_BH   = 0;
static constexpr int SM_BL   = 32768;
static constexpr int SM_A0H  = 65536;
static constexpr int SM_A0L  = 98304;
static constexpr int SM_A1H  = 131072;
static constexpr int SM_A1L  = 163840;
static constexpr int SM_TMEM = 196608;
static constexpr int SM_MBAR0= 196616;
static constexpr int SM_MBAR1= 196624;
static constexpr int SM_TOTAL_MMA = 196640;

#if HAS_TCGEN05
__device__ __forceinline__ uint32_t smem_u32(const void* p) {
    uint32_t a;
    asm("{ .reg .u64 t; cvta.to.shared.u64 t, %1; cvt.u32.u64 %0, t; }"
        : "=r"(a) : "l"(p));
    return a;
}

__device__ __forceinline__ uint32_t elect_one() {
    uint32_t pred;
    asm volatile("{ .reg .pred p; elect.sync _|p, 0xFFFFFFFF; selp.b32 %0, 1, 0, p; }"
                 : "=r"(pred));
    return pred;
}

static constexpr uint32_t MMA_IDESC = (1u<<4) | (1u<<7) | (1u<<10)
                                    | ((128u/8u)<<17) | ((128u/16u)<<24);

static constexpr uint64_t DESC_BASE =
    (uint64_t(2) << 61) | (uint64_t(1) << 46) | (uint64_t(64) << 32) | (uint64_t(1) << 16);

__device__ __forceinline__ uint64_t make_desc(uint32_t addr) {
    return DESC_BASE | ((uint64_t)(addr >> 4) & 0x3FFF);
}

__device__ __forceinline__ void mma_bf16_ss(uint32_t d_tmem, uint64_t a_desc,
                                            uint64_t b_desc, uint32_t en) {
    asm volatile(
        "{\n\t"
        ".reg .pred p;\n\t"
        "setp.ne.u32 p, %4, 0;\n\t"
        "tcgen05.mma.cta_group::1.kind::f16 [%0], %1, %2, %3, {%5, %5, %5, %5}, p;\n\t"
        "}"
        :: "r"(d_tmem), "l"(a_desc), "l"(b_desc), "r"(MMA_IDESC),
           "r"(en), "r"(0u)
        : "memory");
}

__device__ __forceinline__ void mbar_wait(uint32_t mbar, uint32_t parity) {
    uint32_t done;
    asm volatile(
        "{\n\t.reg .pred p;\n\t"
        "mbarrier.try_wait.parity.acquire.cta.shared::cta.b64 p, [%1], %2;\n\t"
        "selp.b32 %0, 1, 0, p;\n\t}"
        : "=r"(done) : "r"(mbar), "r"(parity) : "memory");
    if (!done) {
        asm volatile(
            "{\n\t.reg .pred P1;\n\t"
            "WAIT_LOOP_%=:\n\t"
            "mbarrier.try_wait.parity.acquire.cta.shared::cta.b64 P1, [%0], %1, 0x989680;\n\t"
            "@P1 bra.uni WAIT_DONE_%=;\n\t"
            "bra.uni WAIT_LOOP_%=;\n\t"
            "WAIT_DONE_%=:\n\t}"
            :: "r"(mbar), "r"(parity) : "memory");
    }
}

#define TCLD_X32(r, addr) \
    asm volatile( \
        "tcgen05.ld.sync.aligned.32x32b.x32.b32 " \
        "{%0, %1, %2, %3, %4, %5, %6, %7, " \
        " %8, %9, %10, %11, %12, %13, %14, %15, " \
        " %16, %17, %18, %19, %20, %21, %22, %23, " \
        " %24, %25, %26, %27, %28, %29, %30, %31}, [%32];" \
        : "=r"((r)[0]), "=r"((r)[1]), "=r"((r)[2]), "=r"((r)[3]), \
          "=r"((r)[4]), "=r"((r)[5]), "=r"((r)[6]), "=r"((r)[7]), \
          "=r"((r)[8]), "=r"((r)[9]), "=r"((r)[10]), "=r"((r)[11]), \
          "=r"((r)[12]), "=r"((r)[13]), "=r"((r)[14]), "=r"((r)[15]), \
          "=r"((r)[16]), "=r"((r)[17]), "=r"((r)[18]), "=r"((r)[19]), \
          "=r"((r)[20]), "=r"((r)[21]), "=r"((r)[22]), "=r"((r)[23]), \
          "=r"((r)[24]), "=r"((r)[25]), "=r"((r)[26]), "=r"((r)[27]), \
          "=r"((r)[28]), "=r"((r)[29]), "=r"((r)[30]), "=r"((r)[31]) \
        : "r"(addr))
#endif

__device__ __forceinline__ uint32_t tile_off(int row, int k) {
    uint32_t off = (uint32_t)((row >> 3) + (k >> 6) * 16) * 1024
                 + (uint32_t)(row & 7) * 128 + (uint32_t)(k & 63) * 2;
    return off ^ ((off >> 3) & 0x70);
}

__device__ __forceinline__ void cvt_store_hl(char* ph, char* pl, float4 v) {
    __nv_bfloat16 h0 = __float2bfloat16(v.x);
    __nv_bfloat16 h1 = __float2bfloat16(v.y);
    __nv_bfloat16 h2 = __float2bfloat16(v.z);
    __nv_bfloat16 h3 = __float2bfloat16(v.w);
    __nv_bfloat16 l0 = __float2bfloat16(v.x - __bfloat162float(h0));
    __nv_bfloat16 l1 = __float2bfloat16(v.y - __bfloat162float(h1));
    __nv_bfloat16 l2 = __float2bfloat16(v.z - __bfloat162float(h2));
    __nv_bfloat16 l3 = __float2bfloat16(v.w - __bfloat162float(h3));
    union { __nv_bfloat162 b[2]; uint64_t u; } uh, ul;
    uh.b[0] = __halves2bfloat162(h0, h1);
    uh.b[1] = __halves2bfloat162(h2, h3);
    ul.b[0] = __halves2bfloat162(l0, l1);
    ul.b[1] = __halves2bfloat162(l2, l3);
    *(uint64_t*)ph = uh.u;
    *(uint64_t*)pl = ul.u;
}

// ---------------------------------------------------------------------
// persistent transform0: [y0 | base] = x_feat @ [Wl0 ; Wr0]^T
__global__ void __launch_bounds__(256) k_transform0(
    const float* __restrict__ x, const float* __restrict__ Wl,
    const float* __restrict__ Wr, const float* __restrict__ bl, int n)
{
    extern __shared__ __align__(1024) char smem[];
    const int tid = threadIdx.x;
    const int T = (n + 127) / 128;

#if HAS_TCGEN05
    const int wid = tid >> 5;
    const int lid = tid & 31;
    const uint32_t sbase = smem_u32(smem);

    if (wid == 0) {
        asm volatile("tcgen05.alloc.cta_group::1.sync.aligned.shared::cta.b32 [%0], %1;"
                     :: "r"(sbase + SM_TMEM), "r"(256u) : "memory");
    }
    if (tid == 0) {
        asm volatile("mbarrier.init.shared.b64 [%0], %1;"
                     :: "r"(sbase + SM_MBAR0), "r"(1u) : "memory");
        asm volatile("mbarrier.init.shared.b64 [%0], %1;"
                     :: "r"(sbase + SM_MBAR1), "r"(1u) : "memory");
    }

    const float4* Wl4 = (const float4*)Wl;
    const float4* Wr4 = (const float4*)Wr;
    for (int m = tid; m < 128 * 32; m += 256) {
        int row = m >> 5, kq = m & 31;
        float4 v = (row < 64) ? Wl4[row * 32 + kq] : Wr4[(row - 64) * 32 + kq];
        uint32_t off = tile_off(row, kq * 4);
        cvt_store_hl(smem + SM_BH + off, smem + SM_BL + off, v);
    }
    __syncthreads();

    uint32_t tmem_base;
    asm volatile("ld.shared.b32 %0, [%1];" : "=r"(tmem_base) : "r"(sbase + SM_TMEM));

    const float4* X4 = (const float4*)x;
    const uint32_t abufH[2] = { sbase + SM_A0H, sbase + SM_A1H };
    const uint32_t mbar[2]  = { sbase + SM_MBAR0, sbase + SM_MBAR1 };
    uint64_t dB_h = make_desc(sbase + SM_BH);
    uint64_t dB_l = make_desc(sbase + SM_BL);
    int ph0 = 0, ph1 = 0;

    #define STAGE_A(tile, buf) do {                                         \
        int _n0 = (tile) * 128;                                             \
        char* _ah = smem + SM_A0H + (buf) * 65536;                          \
        char* _al = _ah + 32768;                                            \
        for (int m = tid; m < 128 * 32; m += 256) {                         \
            int row = m >> 5, kq = m & 31;                                  \
            int gi = _n0 + row;                                             \
            float4 v = make_float4(0.f, 0.f, 0.f, 0.f);                     \
            if (gi < n) v = X4[gi * 32 + kq];                               \
            uint32_t off = tile_off(row, kq * 4);                           \
            cvt_store_hl(_ah + off, _al + off, v);                          \
        }                                                                   \
    } while (0)

    #define ISSUE_MMA(buf) do {                                             \
        if (wid == 0) {                                                      \
            if (elect_one()) {                                               \
                asm volatile("fence.proxy.async.shared::cta;" ::: "memory"); \
                uint64_t dAh = make_desc(abufH[buf]);                        \
                uint64_t dAl = make_desc(abufH[buf] + 32768);                \
                uint64_t pA[3] = { dAh, dAh, dAl };                          \
                uint64_t pB[3] = { dB_h, dB_l, dB_h };                       \
                uint32_t dst = tmem_base + (buf) * 128;                      \
                uint32_t en = 0;                                             \
                _Pragma("unroll")                                            \
                for (int p = 0; p < 3; p++) {                                \
                    _Pragma("unroll")                                        \
                    for (int ks = 0; ks < 8; ks++) {                         \
                        uint64_t doff = (uint64_t)((ks & 3) * 2 + (ks >> 2) * 1024); \
                        mma_bf16_ss(dst, pA[p] + doff, pB[p] + doff, en);    \
                        en = 1;                                              \
                    }                                                        \
                }                                                            \
                asm volatile(                                                \
                    "tcgen05.commit.cta_group::1.mbarrier::arrive::one.shared::cluster.b64 [%0];" \
                    :: "r"(mbar[buf]) : "memory");                           \
            }                                                                \
        }                                                                    \
    } while (0)

    int t = blockIdx.x;
    int k = 0;
    if (t < T) {
        STAGE_A(t, 0);
        __syncthreads();
        ISSUE_MMA(0);
    }
    for (; t < T; t += gridDim.x, k++) {
        int buf = k & 1;
        int tn = t + gridDim.x;
        if (tn < T) {
            STAGE_A(tn, buf ^ 1);
            __syncthreads();
            ISSUE_MMA(buf ^ 1);
        }
        if (buf == 0) { mbar_wait(mbar[0], ph0); ph0 ^= 1; }
        else          { mbar_wait(mbar[1], ph1); ph1 ^= 1; }
        asm volatile("tcgen05.fence::after_thread_sync;" ::: "memory");

        {
            int row = (wid & 3) * 32 + lid;
            int gi = t * 128 + row;
            uint32_t taddr = tmem_base + buf * 128 + ((uint32_t)(wid & 3) << 21)
                           + ((wid < 4) ? 0u : 64u);
            uint32_t r0[32], r1[32];
            TCLD_X32(r0, taddr);
            TCLD_X32(r1, taddr + 32);
            asm volatile("tcgen05.wait::ld.sync.aligned;" ::: "memory");
            if (gi < n) {
                if (wid < 4) {
                    #pragma unroll
                    for (int j = 0; j < 8; j++) {
                        float4 v = make_float4(__uint_as_float(r0[j*4+0]),
                                               __uint_as_float(r0[j*4+1]),
                                               __uint_as_float(r0[j*4+2]),
                                               __uint_as_float(r0[j*4+3]));
                        ((float4*)g_y0)[gi * 16 + j] = v;
                    }
                    #pragma unroll
                    for (int j = 0; j < 8; j++) {
                        float4 v = make_float4(__uint_as_float(r1[j*4+0]),
                                               __uint_as_float(r1[j*4+1]),
                                               __uint_as_float(r1[j*4+2]),
                                               __uint_as_float(r1[j*4+3]));
                        ((float4*)g_y0)[gi * 16 + 8 + j] = v;
                    }
                } else {
                    #pragma unroll
                    for (int j = 0; j < 8; j++) {
                        float4 bb = ((const float4*)bl)[j];
                        float4 v = make_float4(__uint_as_float(r0[j*4+0]) + bb.x,
                                               __uint_as_float(r0[j*4+1]) + bb.y,
                                               __uint_as_float(r0[j*4+2]) + bb.z,
                                               __uint_as_float(r0[j*4+3]) + bb.w);
                        ((float4*)g_base)[gi * 16 + j] = v;
                    }
                    #pragma unroll
                    for (int j = 0; j < 8; j++) {
                        float4 bb = ((const float4*)bl)[8 + j];
                        float4 v = make_float4(__uint_as_float(r1[j*4+0]) + bb.x,
                                               __uint_as_float(r1[j*4+1]) + bb.y,
                                               __uint_as_float(r1[j*4+2]) + bb.z,
                                               __uint_as_float(r1[j*4+3]) + bb.w);
                        ((float4*)g_base)[gi * 16 + 8 + j] = v;
                    }
                }
            }
            asm volatile("tcgen05.fence::before_thread_sync;" ::: "memory");
        }
        __syncthreads();
    }
    if (wid == 0) {
        asm volatile("tcgen05.dealloc.cta_group::1.sync.aligned.b32 %0, %1;"
                     :: "r"(tmem_base), "r"(256u));
    }
    #undef STAGE_A
    #undef ISSUE_MMA

#else  // ---------------- FFMA fallback (compute_103 PTX pass) ----------------
    float* Ws = (float*)smem;
    float* Xs = (float*)smem + 128 * 128;

    const float4* Wl4 = (const float4*)Wl;
    const float4* Wr4 = (const float4*)Wr;
    for (int m = tid; m < 64 * 32; m += 256) {
        int o  = m & 63;
        int kq = m >> 6;
        float4 a = Wl4[o * 32 + kq];
        float4 b = Wr4[o * 32 + kq];
        int k = kq * 4;
        Ws[(k+0)*128 + o] = a.x;  Ws[(k+1)*128 + o] = a.y;
        Ws[(k+2)*128 + o] = a.z;  Ws[(k+3)*128 + o] = a.w;
        Ws[(k+0)*128 + 64 + o] = b.x;  Ws[(k+1)*128 + 64 + o] = b.y;
        Ws[(k+2)*128 + 64 + o] = b.z;  Ws[(k+3)*128 + 64 + o] = b.w;
    }
    const float4* X4 = (const float4*)x;
    float4* Xs4 = (float4*)Xs;

    for (int t = blockIdx.x; t < T; t += gridDim.x) {
        int n0 = t * 128;
        __syncthreads();
        for (int m = tid; m < 128 * 32; m += 256) {
            int node = m >> 5;
            int kq   = m & 31;
            int gi = n0 + node;
            float4 v = make_float4(0.f, 0.f, 0.f, 0.f);
            if (gi < n) v = X4[gi * 32 + kq];
            Xs4[node * 32 + kq] = v;
        }
        __syncthreads();

        const int tx = tid & 15;
        const int ty = tid >> 4;
        float acc[8][8];
        #pragma unroll
        for (int s = 0; s < 8; s++)
            #pragma unroll
            for (int r = 0; r < 8; r++) acc[s][r] = 0.f;

        const float4* Ws4c = (const float4*)Ws;
        const float4* Xs4c = (const float4*)Xs;

        for (int k = 0; k < 128; k += 4) {
            float4 xv[8];
            #pragma unroll
            for (int s = 0; s < 8; s++)
                xv[s] = Xs4c[((ty + 16 * s) * 128 + k) >> 2];
            #pragma unroll
            for (int kk = 0; kk < 4; kk++) {
                float4 wa = Ws4c[((k + kk) * 128 >> 2) + tx];
                float4 wb = Ws4c[(((k + kk) * 128 + 64) >> 2) + tx];
                #pragma unroll
                for (int s = 0; s < 8; s++) {
                    float xs = (kk == 0) ? xv[s].x : (kk == 1) ? xv[s].y
                             : (kk == 2) ? xv[s].z : xv[s].w;
                    acc[s][0] = fmaf(xs, wa.x, acc[s][0]);
                    acc[s][1] = fmaf(xs, wa.y, acc[s][1]);
                    acc[s][2] = fmaf(xs, wa.z, acc[s][2]);
                    acc[s][3] = fmaf(xs, wa.w, acc[s][3]);
                    acc[s][4] = fmaf(xs, wb.x, acc[s][4]);
                    acc[s][5] = fmaf(xs, wb.y, acc[s][5]);
                    acc[s][6] = fmaf(xs, wb.z, acc[s][6]);
                    acc[s][7] = fmaf(xs, wb.w, acc[s][7]);
                }
            }
        }

        float4 bb = ((const float4*)bl)[tx];
        #pragma unroll
        for (int s = 0; s < 8; s++) {
            int gi = n0 + ty + 16 * s;
            if (gi >= n) continue;
            float4 v0 = make_float4(acc[s][0], acc[s][1], acc[s][2], acc[s][3]);
            float4 v1 = make_float4(acc[s][4] + bb.x, acc[s][5] + bb.y,
                                    acc[s][6] + bb.z, acc[s][7] + bb.w);
            ((float4*)g_y0)  [gi * 16 + tx] = v0;
            ((float4*)g_base)[gi * 16 + tx] = v1;
        }
    }
#endif
}

// ---------------------------------------------------------------------
// e0 = mean(x_emb, axis=1) @ We0^T + be0   (K=64, 64 outputs)  [R10]
__global__ void __launch_bounds__(128) k_emb0(
    const float* __restrict__ xe, const float* __restrict__ We,
    const float* __restrict__ be, int n)
{
    __shared__ __align__(16) float Ws[64 * 64];
    __shared__ __align__(16) float Xs[64 * 64];
    const int tid = threadIdx.x;
    const int n0 = blockIdx.x * 64;

    const float4* W4 = (const float4*)We;
    for (int m = tid; m < 64 * 16; m += 128) {
        int o  = m & 63;
        int kq = m >> 6;
        float4 a = W4[o * 16 + kq];
        int k = kq * 4;
        Ws[(k+0)*64 + o] = a.x;  Ws[(k+1)*64 + o] = a.y;
        Ws[(k+2)*64 + o] = a.z;  Ws[(k+3)*64 + o] = a.w;
    }
    const float4* E4 = (const float4*)xe;
    float4* Xs4 = (float4*)Xs;
    for (int m = tid; m < 64 * 16; m += 128) {
        int node = m >> 4;
        int kq   = m & 15;
        int gi = n0 + node;
        float4 v = make_float4(0.f, 0.f, 0.f, 0.f);
        if (gi < n) {
            float4 a = E4[gi * 32 + kq];
            float4 b = E4[gi * 32 + 16 + kq];
            v = make_float4(0.5f*(a.x+b.x), 0.5f*(a.y+b.y),
                            0.5f*(a.z+b.z), 0.5f*(a.w+b.w));
        }
        Xs4[node * 16 + kq] = v;
    }
    __syncthreads();

    const int tx = tid & 15;
    const int ty = tid >> 4;
    float acc[8][4];
    #pragma unroll
    for (int s = 0; s < 8; s++)
        #pragma unroll
        for (int r = 0; r < 4; r++) acc[s][r] = 0.f;

    const float4* Ws4c = (const float4*)Ws;
    const float4* Xs4c = (const float4*)Xs;

    for (int k = 0; k < 64; k += 4) {
        float4 xv[8];
        #pragma unroll
        for (int s = 0; s < 8; s++)
            xv[s] = Xs4c[((ty + 8 * s) * 64 + k) >> 2];
        #pragma unroll
        for (int kk = 0; kk < 4; kk++) {
            float4 w = Ws4c[((k + kk) * 64 >> 2) + tx];
            #pragma unroll
            for (int s = 0; s < 8; s++) {
                float xs = (kk == 0) ? xv[s].x : (kk == 1) ? xv[s].y
                         : (kk == 2) ? xv[s].z : xv[s].w;
                acc[s][0] = fmaf(xs, w.x, acc[s][0]);
                acc[s][1] = fmaf(xs, w.y, acc[s][1]);
                acc[s][2] = fmaf(xs, w.z, acc[s][2]);
                acc[s][3] = fmaf(xs, w.w, acc[s][3]);
            }
        }
    }

    float4 bb = ((const float4*)be)[tx];
    #pragma unroll
    for (int s = 0; s < 8; s++) {
        int gi = n0 + ty + 8 * s;
        if (gi >= n) continue;
        float4 v = make_float4(acc[s][0] + bb.x, acc[s][1] + bb.y,
                               acc[s][2] + bb.z, acc[s][3] + bb.w);
        ((float4*)g_e0)[gi * 16 + tx] = v;
    }
}

// ---------------------------------------------------------------------
// gather0 + combine0 fused: one warp per node, unroll 4.  [R10]
__global__ void __launch_bounds__(256) k_gather0(int n) {
    int warp = (blockIdx.x * 256 + threadIdx.x) >> 5;
    int lane = threadIdx.x & 31;
    if (warp >= n) return;
    int beg = g_off[warp];
    int end = g_off[warp + 1];
    const float2* Y = (const float2*)g_y0;

    float2 acc = make_float2(0.f, 0.f);
    int e = beg;
    for (; e + 3 < end; e += 4) {
        int s0 = g_esrc[e];
        int s1 = g_esrc[e + 1];
        int s2 = g_esrc[e + 2];
        int s3 = g_esrc[e + 3];
        float2 v0 = Y[s0 * 32 + lane];
        float2 v1 = Y[s1 * 32 + lane];
        float2 v2 = Y[s2 * 32 + lane];
        float2 v3 = Y[s3 * 32 + lane];
        acc.x += (v0.x + v1.x) + (v2.x + v3.x);
        acc.y += (v0.y + v1.y) + (v2.y + v3.y);
    }
    for (; e < end; e++) {
        int s0 = g_esrc[e];
        float2 v0 = Y[s0 * 32 + lane];
        acc.x += v0.x;
        acc.y += v0.y;
    }
    float inv = 1.0f / fmaxf((float)(end - beg), 1.0f);
    float2 b = ((const float2*)g_base)[warp * 32 + lane];
    float2 e0 = ((const float2*)g_e0)[warp * 32 + lane];
    float2 h;
    h.x = fmaxf(fmaf(acc.x, inv, b.x + e0.x), 0.f);
    h.y = fmaxf(fmaf(acc.y, inv, b.y + e0.y), 0.f);
    ((float2*)g_h)[warp * 32 + lane] = h;
}

// ---------------------------------------------------------------------
// Layer-1 node transforms: y1 = h@Wl1^T, r1 = h@Wr1^T, er1 = e0@We1^T.
__global__ void __launch_bounds__(96) k_transform1(
    const float* __restrict__ Wl1, const float* __restrict__ Wr1,
    const float* __restrict__ We1, int n)
{
    __shared__ __align__(16) float Hs[64 * 64];
    __shared__ __align__(16) float Es[64 * 64];
    __shared__ __align__(16) float Ws[64 * 48];
    const int tid = threadIdx.x;
    const int n0 = blockIdx.x * 64;

    for (int m = tid; m < 48 * 16; m += 96) {
        int o  = m % 48;
        int kq = m / 48;
        const float4* src = (o < 16) ? ((const float4*)Wl1) + o * 16
                          : (o < 32) ? ((const float4*)Wr1) + (o - 16) * 16
                                     : ((const float4*)We1) + (o - 32) * 16;
        float4 a = src[kq];
        int k = kq * 4;
        Ws[(k+0)*48 + o] = a.x;  Ws[(k+1)*48 + o] = a.y;
        Ws[(k+2)*48 + o] = a.z;  Ws[(k+3)*48 + o] = a.w;
    }
    for (int m = tid; m < 64 * 16; m += 96) {
        int node = m >> 4;
        int kq   = m & 15;
        int gi = n0 + node;
        float4 v = make_float4(0.f, 0.f, 0.f, 0.f);
        float4 w = v;
        if (gi < n) {
            v = ((const float4*)g_h )[gi * 16 + kq];
            w = ((const float4*)g_e0)[gi * 16 + kq];
        }
        ((float4*)Hs)[node * 16 + kq] = v;
        ((float4*)Es)[node * 16 + kq] = w;
    }
    __syncthreads();

    const int g  = tid % 12;
    const int ty = tid / 12;
    const float* In = (g < 8) ? Hs : Es;
    float acc[8][4];
    #pragma unroll
    for (int s = 0; s < 8; s++)
        #pragma unroll
        for (int r = 0; r < 4; r++) acc[s][r] = 0.f;

    for (int k = 0; k < 64; k++) {
        float4 w = ((const float4*)Ws)[k * 12 + g];
        float xv[8];
        #pragma unroll
        for (int s = 0; s < 8; s++) xv[s] = In[(ty + 8 * s) * 64 + k];
        #pragma unroll
        for (int s = 0; s < 8; s++) {
            acc[s][0] = fmaf(xv[s], w.x, acc[s][0]);
            acc[s][1] = fmaf(xv[s], w.y, acc[s][1]);
            acc[s][2] = fmaf(xv[s], w.z, acc[s][2]);
            acc[s][3] = fmaf(xv[s], w.w, acc[s][3]);
        }
    }

    #pragma unroll
    for (int s = 0; s < 8; s++) {
        int gi = n0 + ty + 8 * s;
        if (gi >= n) continue;
        float4 v = make_float4(acc[s][0], acc[s][1], acc[s][2], acc[s][3]);
        if (g < 4)       ((float4*)g_y1 )[gi * 4 + g]       = v;
        else if (g < 8)  ((float4*)g_r1 )[gi * 4 + (g - 4)] = v;
        else             ((float4*)g_er1)[gi * 4 + (g - 8)] = v;
    }
}

// ---------------------------------------------------------------------
// gather1 + final fused: 8 lanes per node, unroll 2.
__global__ void __launch_bounds__(256) k_gather1(
    const float* __restrict__ bl1, const float* __restrict__ be1,
    float* __restrict__ out, int n)
{
    int t = blockIdx.x * 256 + threadIdx.x;
    int node = t >> 3;
    int sub = t & 7;
    if (node >= n) return;
    int beg = g_off[node];
    int end = g_off[node + 1];
    const float2* Y = (const float2*)g_y1;

    float2 acc = make_float2(0.f, 0.f);
    int e = beg;
    for (; e + 1 < end; e += 2) {
        int s0 = g_esrc[e];
        int s1 = g_esrc[e + 1];
        float2 v0 = Y[s0 * 8 + sub];
        float2 v1 = Y[s1 * 8 + sub];
        acc.x += v0.x + v1.x;
        acc.y += v0.y + v1.y;
    }
    if (e < end) {
        int s0 = g_esrc[e];
        float2 v0 = Y[s0 * 8 + sub];
        acc.x += v0.x;
        acc.y += v0.y;
    }
    float inv = 1.0f / fmaxf((float)(end - beg), 1.0f);
    float2 r = ((const float2*)g_r1 )[node * 8 + sub];
    float2 er = ((const float2*)g_er1)[node * 8 + sub];
    float2 o;
    o.x = fmaf(acc.x, inv, r.x + er.x + bl1[2*sub+0] + be1[2*sub+0]);
    o.y = fmaf(acc.y, inv, r.y + er.y + bl1[2*sub+1] + be1[2*sub+1]);
    ((float2*)out)[node * 8 + sub] = o;
}

// ---------------------------------------------------------------------
extern "C" void kernel_launch(void* const* d_in, const int* in_sizes, int n_in,
                              void* d_out, int out_size)
{
    const float* x_feat = (const float*)d_in[0];
    const float* x_emb  = (const float*)d_in[1];
    const int*   ei     = (const int*)  d_in[2];
    const float* Wl0 = (const float*)d_in[3];
    const float* bl0 = (const float*)d_in[4];
    const float* Wr0 = (const float*)d_in[5];
    const float* We0 = (const float*)d_in[6];
    const float* be0 = (const float*)d_in[7];
    const float* Wl1 = (const float*)d_in[8];
    const float* bl1 = (const float*)d_in[9];
    const float* Wr1 = (const float*)d_in[10];
    const float* We1 = (const float*)d_in[11];
    const float* be1 = (const float*)d_in[12];

    int n = in_sizes[0] / 128;
    int E = in_sizes[2] / 2;

    cudaFuncSetAttribute(k_transform0,
                         cudaFuncAttributeMaxDynamicSharedMemorySize, SM_TOTAL_MMA);

    // (1) CSR build: cooperative zero/hist/scan (int4 histogram)
    {
        int G = (n + 255) / 256;
        void* args[] = { (void*)&ei, (void*)&n, (void*)&E };
        cudaLaunchCooperativeKernel((void*)k_csr_build, dim3(G), dim3(256), args, 0, 0);
    }

    // (2) emb transform (independent; placed here so fill lands in slot 4)
    k_emb0<<<(n + 63) / 64, 128>>>(x_emb, We0, be0, n);

    // (3) transform0 (persistent MMA)
    k_transform0<<<148, 256, SM_TOTAL_MMA>>>(x_feat, Wl0, Wr0, bl0, n);

    // (4) CSR fill (int4 loads)  <-- profiled slot
    k_fill<<<(E / 4 + 255) / 256, 256>>>(ei, E);

    // (5) layer-0 aggregate + combine
    k_gather0<<<(n + 7) / 8, 256>>>(n);

    // (6)(7) layer 1
    k_transform1<<<(n + 63) / 64, 96>>>(Wl1, Wr1, We1, n);
    k_gather1<<<(n * 8 + 255) / 256, 256>>>(bl1, be1, (float*)d_out, n);
}

// round 13
// speedup vs baseline: 1.1932x; 1.0649x over previous
#include <cuda_runtime.h>
#include <cuda_bf16.h>
#include <cooperative_groups.h>
#include <cstdint>

namespace cg = cooperative_groups;

#define NODES 100000
#define EDGES 1600000

// ---- device scratch (allocation-free contract: __device__ globals) ----
__device__ __align__(16) float g_y0  [NODES*64];
__device__ __align__(16) float g_base[NODES*64];
__device__ __align__(16) float g_e0  [NODES*64];
__device__ __align__(16) float g_h   [NODES*64];
__device__ __align__(16) float g_y1  [NODES*16];
__device__ __align__(16) float g_r1  [NODES*16];
__device__ __align__(16) float g_er1 [NODES*16];
// CSR-by-dst
__device__ int g_cnt [NODES];
__device__ int g_off [NODES + 1];
__device__ int g_cur [NODES];
__device__ int g_esrc[EDGES];
__device__ int g_bsum[1024];

#if defined(__CUDA_ARCH__) && (defined(__CUDA_ARCH_FEAT_SM103_ALL) || defined(__CUDA_ARCH_FEAT_SM100_ALL))
#define HAS_TCGEN05 1
#else
#define HAS_TCGEN05 0
#endif

// ======================= CSR build =====================================
__global__ void k_zero_cnt(int n) {
    int i = blockIdx.x * blockDim.x + threadIdx.x;
    if (i < n) g_cnt[i] = 0;
}

// cooperative hist + scan (zero hoisted out; 4 grid.syncs -> 3)
__global__ void __launch_bounds__(256) k_csr_build(const int* __restrict__ ei,
                                                   int n, int E)
{
    cg::grid_group grid = cg::this_grid();
    const int tid = threadIdx.x;
    const int b   = blockIdx.x;
    const int G   = gridDim.x;
    const int lane = tid & 31;
    const int w    = tid >> 5;
    __shared__ int ws[8];

    // phase 1: histogram of dst (int4)
    {
        const int4* D4 = (const int4*)(ei + E);
        int q = E >> 2;
        for (int i = b * 256 + tid; i < q; i += G * 256) {
            int4 d = D4[i];
            atomicAdd(&g_cnt[d.x], 1);
            atomicAdd(&g_cnt[d.y], 1);
            atomicAdd(&g_cnt[d.z], 1);
            atomicAdd(&g_cnt[d.w], 1);
        }
        for (int e = (q << 2) + b * 256 + tid; e < E; e += G * 256)
            atomicAdd(&g_cnt[ei[E + e]], 1);
    }
    grid.sync();

    // phase 2: per-256-chunk exclusive scan
    {
        int i = b * 256 + tid;
        int v = (i < n) ? g_cnt[i] : 0;
        int x = v;
        #pragma unroll
        for (int d = 1; d < 32; d <<= 1) {
            int t = __shfl_up_sync(0xFFFFFFFF, x, d);
            if (lane >= d) x += t;
        }
        if (lane == 31) ws[w] = x;
        __syncthreads();
        int base = 0;
        #pragma unroll
        for (int k = 0; k < 8; k++) base += (k < w) ? ws[k] : 0;
        int incl = base + x;
        if (i < n) g_off[i] = incl - v;
        if (tid == 0) {
            int tot = 0;
            #pragma unroll
            for (int k = 0; k < 8; k++) tot += ws[k];
            g_bsum[b] = tot;
        }
    }
    grid.sync();

    // phase 3: block 0 scans G block sums (exclusive)
    if (b == 0) {
        int per = (G + 255) / 256;
        int s[4];
        int sum = 0;
        #pragma unroll 4
        for (int j = 0; j < per; j++) {
            int idx = tid * per + j;
            s[j] = (idx < G) ? g_bsum[idx] : 0;
            sum += s[j];
        }
        int x = sum;
        #pragma unroll
        for (int d = 1; d < 32; d <<= 1) {
            int t = __shfl_up_sync(0xFFFFFFFF, x, d);
            if (lane >= d) x += t;
        }
        if (lane == 31) ws[w] = x;
        __syncthreads();
        int base = 0;
        #pragma unroll
        for (int k = 0; k < 8; k++) base += (k < w) ? ws[k] : 0;
        int run = base + x - sum;
        #pragma unroll 4
        for (int j = 0; j < per; j++) {
            int idx = tid * per + j;
            if (idx < G) { g_bsum[idx] = run; run += s[j]; }
        }
    }
    grid.sync();

    // phase 4: add block bases; init cur
    {
        int i = b * 256 + tid;
        if (i < n) {
            int o = g_off[i] + g_bsum[b];
            g_off[i] = o;
            g_cur[i] = o;
        }
        if (b == 0 && tid == 0) g_off[n] = E;
    }
}

// fill edge sources; int4-vectorized loads of src and dst
__global__ void k_fill(const int* __restrict__ ei, int E) {
    int q = E >> 2;
    int i = blockIdx.x * blockDim.x + threadIdx.x;
    const int4* S4 = (const int4*)ei;
    const int4* D4 = (const int4*)(ei + E);
    if (i < q) {
        int4 s = S4[i];
        int4 d = D4[i];
        g_esrc[atomicAdd(&g_cur[d.x], 1)] = s.x;
        g_esrc[atomicAdd(&g_cur[d.y], 1)] = s.y;
        g_esrc[atomicAdd(&g_cur[d.z], 1)] = s.z;
        g_esrc[atomicAdd(&g_cur[d.w], 1)] = s.w;
    }
    int e = (q << 2) + i;
    if (i < (E - (q << 2))) {
        int dst = ei[E + e];
        g_esrc[atomicAdd(&g_cur[dst], 1)] = ei[e];
    }
}

// ================= persistent transform0 smem layout =================
static constexpr int SM_BH   = 0;
static constexpr int SM_BL   = 32768;
static constexpr int SM_A0H  = 65536;
static constexpr int SM_A0L  = 98304;
static constexpr int SM_A1H  = 131072;
static constexpr int SM_A1L  = 163840;
static constexpr int SM_TMEM = 196608;
static constexpr int SM_MBAR0= 196616;
static constexpr int SM_MBAR1= 196624;
static constexpr int SM_TOTAL_MMA = 196640;

#if HAS_TCGEN05
__device__ __forceinline__ uint32_t smem_u32(const void* p) {
    uint32_t a;
    asm("{ .reg .u64 t; cvta.to.shared.u64 t, %1; cvt.u32.u64 %0, t; }"
        : "=r"(a) : "l"(p));
    return a;
}

__device__ __forceinline__ uint32_t elect_one() {
    uint32_t pred;
    asm volatile("{ .reg .pred p; elect.sync _|p, 0xFFFFFFFF; selp.b32 %0, 1, 0, p; }"
                 : "=r"(pred));
    return pred;
}

static constexpr uint32_t MMA_IDESC = (1u<<4) | (1u<<7) | (1u<<10)
                                    | ((128u/8u)<<17) | ((128u/16u)<<24);

static constexpr uint64_t DESC_BASE =
    (uint64_t(2) << 61) | (uint64_t(1) << 46) | (uint64_t(64) << 32) | (uint64_t(1) << 16);

__device__ __forceinline__ uint64_t make_desc(uint32_t addr) {
    return DESC_BASE | ((uint64_t)(addr >> 4) & 0x3FFF);
}

__device__ __forceinline__ void mma_bf16_ss(uint32_t d_tmem, uint64_t a_desc,
                                            uint64_t b_desc, uint32_t en) {
    asm volatile(
        "{\n\t"
        ".reg .pred p;\n\t"
        "setp.ne.u32 p, %4, 0;\n\t"
        "tcgen05.mma.cta_group::1.kind::f16 [%0], %1, %2, %3, {%5, %5, %5, %5}, p;\n\t"
        "}"
        :: "r"(d_tmem), "l"(a_desc), "l"(b_desc), "r"(MMA_IDESC),
           "r"(en), "r"(0u)
        : "memory");
}

__device__ __forceinline__ void mbar_wait(uint32_t mbar, uint32_t parity) {
    uint32_t done;
    asm volatile(
        "{\n\t.reg .pred p;\n\t"
        "mbarrier.try_wait.parity.acquire.cta.shared::cta.b64 p, [%1], %2;\n\t"
        "selp.b32 %0, 1, 0, p;\n\t}"
        : "=r"(done) : "r"(mbar), "r"(parity) : "memory");
    if (!done) {
        asm volatile(
            "{\n\t.reg .pred P1;\n\t"
            "WAIT_LOOP_%=:\n\t"
            "mbarrier.try_wait.parity.acquire.cta.shared::cta.b64 P1, [%0], %1, 0x989680;\n\t"
            "@P1 bra.uni WAIT_DONE_%=;\n\t"
            "bra.uni WAIT_LOOP_%=;\n\t"
            "WAIT_DONE_%=:\n\t}"
            :: "r"(mbar), "r"(parity) : "memory");
    }
}

#define TCLD_X32(r, addr) \
    asm volatile( \
        "tcgen05.ld.sync.aligned.32x32b.x32.b32 " \
        "{%0, %1, %2, %3, %4, %5, %6, %7, " \
        " %8, %9, %10, %11, %12, %13, %14, %15, " \
        " %16, %17, %18, %19, %20, %21, %22, %23, " \
        " %24, %25, %26, %27, %28, %29, %30, %31}, [%32];" \
        : "=r"((r)[0]), "=r"((r)[1]), "=r"((r)[2]), "=r"((r)[3]), \
          "=r"((r)[4]), "=r"((r)[5]), "=r"((r)[6]), "=r"((r)[7]), \
          "=r"((r)[8]), "=r"((r)[9]), "=r"((r)[10]), "=r"((r)[11]), \
          "=r"((r)[12]), "=r"((r)[13]), "=r"((r)[14]), "=r"((r)[15]), \
          "=r"((r)[16]), "=r"((r)[17]), "=r"((r)[18]), "=r"((r)[19]), \
          "=r"((r)[20]), "=r"((r)[21]), "=r"((r)[22]), "=r"((r)[23]), \
          "=r"((r)[24]), "=r"((r)[25]), "=r"((r)[26]), "=r"((r)[27]), \
          "=r"((r)[28]), "=r"((r)[29]), "=r"((r)[30]), "=r"((r)[31]) \
        : "r"(addr))
#endif

__device__ __forceinline__ uint32_t tile_off(int row, int k) {
    uint32_t off = (uint32_t)((row >> 3) + (k >> 6) * 16) * 1024
                 + (uint32_t)(row & 7) * 128 + (uint32_t)(k & 63) * 2;
    return off ^ ((off >> 3) & 0x70);
}

__device__ __forceinline__ void cvt_store_hl(char* ph, char* pl, float4 v) {
    __nv_bfloat16 h0 = __float2bfloat16(v.x);
    __nv_bfloat16 h1 = __float2bfloat16(v.y);
    __nv_bfloat16 h2 = __float2bfloat16(v.z);
    __nv_bfloat16 h3 = __float2bfloat16(v.w);
    __nv_bfloat16 l0 = __float2bfloat16(v.x - __bfloat162float(h0));
    __nv_bfloat16 l1 = __float2bfloat16(v.y - __bfloat162float(h1));
    __nv_bfloat16 l2 = __float2bfloat16(v.z - __bfloat162float(h2));
    __nv_bfloat16 l3 = __float2bfloat16(v.w - __bfloat162float(h3));
    union { __nv_bfloat162 b[2]; uint64_t u; } uh, ul;
    uh.b[0] = __halves2bfloat162(h0, h1);
    uh.b[1] = __halves2bfloat162(h2, h3);
    ul.b[0] = __halves2bfloat162(l0, l1);
    ul.b[1] = __halves2bfloat162(l2, l3);
    *(uint64_t*)ph = uh.u;
    *(uint64_t*)pl = ul.u;
}

// ---------------------------------------------------------------------
// persistent transform0: [y0 | base] = x_feat @ [Wl0 ; Wr0]^T
__global__ void __launch_bounds__(256) k_transform0(
    const float* __restrict__ x, const float* __restrict__ Wl,
    const float* __restrict__ Wr, const float* __restrict__ bl, int n)
{
    extern __shared__ __align__(1024) char smem[];
    const int tid = threadIdx.x;
    const int T = (n + 127) / 128;

#if HAS_TCGEN05
    const int wid = tid >> 5;
    const int lid = tid & 31;
    const uint32_t sbase = smem_u32(smem);

    if (wid == 0) {
        asm volatile("tcgen05.alloc.cta_group::1.sync.aligned.shared::cta.b32 [%0], %1;"
                     :: "r"(sbase + SM_TMEM), "r"(256u) : "memory");
    }
    if (tid == 0) {
        asm volatile("mbarrier.init.shared.b64 [%0], %1;"
                     :: "r"(sbase + SM_MBAR0), "r"(1u) : "memory");
        asm volatile("mbarrier.init.shared.b64 [%0], %1;"
                     :: "r"(sbase + SM_MBAR1), "r"(1u) : "memory");
    }

    const float4* Wl4 = (const float4*)Wl;
    const float4* Wr4 = (const float4*)Wr;
    for (int m = tid; m < 128 * 32; m += 256) {
        int row = m >> 5, kq = m & 31;
        float4 v = (row < 64) ? Wl4[row * 32 + kq] : Wr4[(row - 64) * 32 + kq];
        uint32_t off = tile_off(row, kq * 4);
        cvt_store_hl(smem + SM_BH + off, smem + SM_BL + off, v);
    }
    __syncthreads();

    uint32_t tmem_base;
    asm volatile("ld.shared.b32 %0, [%1];" : "=r"(tmem_base) : "r"(sbase + SM_TMEM));

    const float4* X4 = (const float4*)x;
    const uint32_t abufH[2] = { sbase + SM_A0H, sbase + SM_A1H };
    const uint32_t mbar[2]  = { sbase + SM_MBAR0, sbase + SM_MBAR1 };
    uint64_t dB_h = make_desc(sbase + SM_BH);
    uint64_t dB_l = make_desc(sbase + SM_BL);
    int ph0 = 0, ph1 = 0;

    // stage A with 4-deep load batching (MLP=4 on the LDG chain)
    #define STAGE_A(tile, buf) do {                                         \
        int _n0 = (tile) * 128;                                             \
        char* _ah = smem + SM_A0H + (buf) * 65536;                          \
        char* _al = _ah + 32768;                                            \
        _Pragma("unroll")                                                   \
        for (int c = 0; c < 4; c++) {                                       \
            float4 v[4];                                                    \
            uint32_t off[4];                                                \
            _Pragma("unroll")                                               \
            for (int j = 0; j < 4; j++) {                                   \
                int m = tid + (c * 4 + j) * 256;                            \
                int row = m >> 5, kq = m & 31;                              \
                int gi = _n0 + row;                                         \
                v[j] = make_float4(0.f, 0.f, 0.f, 0.f);                     \
                if (gi < n) v[j] = X4[gi * 32 + kq];                        \
                off[j] = tile_off(row, kq * 4);                             \
            }                                                               \
            _Pragma("unroll")                                               \
            for (int j = 0; j < 4; j++)                                     \
                cvt_store_hl(_ah + off[j], _al + off[j], v[j]);             \
        }                                                                   \
    } while (0)

    #define ISSUE_MMA(buf) do {                                             \
        if (wid == 0) {                                                      \
            if (elect_one()) {                                               \
                asm volatile("fence.proxy.async.shared::cta;" ::: "memory"); \
                uint64_t dAh = make_desc(abufH[buf]);                        \
                uint64_t dAl = make_desc(abufH[buf] + 32768);                \
                uint64_t pA[3] = { dAh, dAh, dAl };                          \
                uint64_t pB[3] = { dB_h, dB_l, dB_h };                       \
                uint32_t dst = tmem_base + (buf) * 128;                      \
                uint32_t en = 0;                                             \
                _Pragma("unroll")                                            \
                for (int p = 0; p < 3; p++) {                                \
                    _Pragma("unroll")                                        \
                    for (int ks = 0; ks < 8; ks++) {                         \
                        uint64_t doff = (uint64_t)((ks & 3) * 2 + (ks >> 2) * 1024); \
                        mma_bf16_ss(dst, pA[p] + doff, pB[p] + doff, en);    \
                        en = 1;                                              \
                    }                                                        \
                }                                                            \
                asm volatile(                                                \
                    "tcgen05.commit.cta_group::1.mbarrier::arrive::one.shared::cluster.b64 [%0];" \
                    :: "r"(mbar[buf]) : "memory");                           \
            }                                                                \
        }                                                                    \
    } while (0)

    int t = blockIdx.x;
    int k = 0;
    if (t < T) {
        STAGE_A(t, 0);
        __syncthreads();
        ISSUE_MMA(0);
    }
    for (; t < T; t += gridDim.x, k++) {
        int buf = k & 1;
        int tn = t + gridDim.x;
        if (tn < T) {
            STAGE_A(tn, buf ^ 1);
            __syncthreads();
            ISSUE_MMA(buf ^ 1);
        }
        if (buf == 0) { mbar_wait(mbar[0], ph0); ph0 ^= 1; }
        else          { mbar_wait(mbar[1], ph1); ph1 ^= 1; }
        asm volatile("tcgen05.fence::after_thread_sync;" ::: "memory");

        {
            int row = (wid & 3) * 32 + lid;
            int gi = t * 128 + row;
            uint32_t taddr = tmem_base + buf * 128 + ((uint32_t)(wid & 3) << 21)
                           + ((wid < 4) ? 0u : 64u);
            uint32_t r0[32], r1[32];
            TCLD_X32(r0, taddr);
            TCLD_X32(r1, taddr + 32);
            asm volatile("tcgen05.wait::ld.sync.aligned;" ::: "memory");
            if (gi < n) {
                if (wid < 4) {
                    #pragma unroll
                    for (int j = 0; j < 8; j++) {
                        float4 v = make_float4(__uint_as_float(r0[j*4+0]),
                                               __uint_as_float(r0[j*4+1]),
                                               __uint_as_float(r0[j*4+2]),
                                               __uint_as_float(r0[j*4+3]));
                        ((float4*)g_y0)[gi * 16 + j] = v;
                    }
                    #pragma unroll
                    for (int j = 0; j < 8; j++) {
                        float4 v = make_float4(__uint_as_float(r1[j*4+0]),
                                               __uint_as_float(r1[j*4+1]),
                                               __uint_as_float(r1[j*4+2]),
                                               __uint_as_float(r1[j*4+3]));
                        ((float4*)g_y0)[gi * 16 + 8 + j] = v;
                    }
                } else {
                    #pragma unroll
                    for (int j = 0; j < 8; j++) {
                        float4 bb = ((const float4*)bl)[j];
                        float4 v = make_float4(__uint_as_float(r0[j*4+0]) + bb.x,
                                               __uint_as_float(r0[j*4+1]) + bb.y,
                                               __uint_as_float(r0[j*4+2]) + bb.z,
                                               __uint_as_float(r0[j*4+3]) + bb.w);
                        ((float4*)g_base)[gi * 16 + j] = v;
                    }
                    #pragma unroll
                    for (int j = 0; j < 8; j++) {
                        float4 bb = ((const float4*)bl)[8 + j];
                        float4 v = make_float4(__uint_as_float(r1[j*4+0]) + bb.x,
                                               __uint_as_float(r1[j*4+1]) + bb.y,
                                               __uint_as_float(r1[j*4+2]) + bb.z,
                                               __uint_as_float(r1[j*4+3]) + bb.w);
                        ((float4*)g_base)[gi * 16 + 8 + j] = v;
                    }
                }
            }
            asm volatile("tcgen05.fence::before_thread_sync;" ::: "memory");
        }
        __syncthreads();
    }
    if (wid == 0) {
        asm volatile("tcgen05.dealloc.cta_group::1.sync.aligned.b32 %0, %1;"
                     :: "r"(tmem_base), "r"(256u));
    }
    #undef STAGE_A
    #undef ISSUE_MMA

#else  // ---------------- FFMA fallback (compute_103 PTX pass) ----------------
    float* Ws = (float*)smem;
    float* Xs = (float*)smem + 128 * 128;

    const float4* Wl4 = (const float4*)Wl;
    const float4* Wr4 = (const float4*)Wr;
    for (int m = tid; m < 64 * 32; m += 256) {
        int o  = m & 63;
        int kq = m >> 6;
        float4 a = Wl4[o * 32 + kq];
        float4 b = Wr4[o * 32 + kq];
        int k = kq * 4;
        Ws[(k+0)*128 + o] = a.x;  Ws[(k+1)*128 + o] = a.y;
        Ws[(k+2)*128 + o] = a.z;  Ws[(k+3)*128 + o] = a.w;
        Ws[(k+0)*128 + 64 + o] = b.x;  Ws[(k+1)*128 + 64 + o] = b.y;
        Ws[(k+2)*128 + 64 + o] = b.z;  Ws[(k+3)*128 + 64 + o] = b.w;
    }
    const float4* X4 = (const float4*)x;
    float4* Xs4 = (float4*)Xs;

    for (int t = blockIdx.x; t < T; t += gridDim.x) {
        int n0 = t * 128;
        __syncthreads();
        for (int m = tid; m < 128 * 32; m += 256) {
            int node = m >> 5;
            int kq   = m & 31;
            int gi = n0 + node;
            float4 v = make_float4(0.f, 0.f, 0.f, 0.f);
            if (gi < n) v = X4[gi * 32 + kq];
            Xs4[node * 32 + kq] = v;
        }
        __syncthreads();

        const int tx = tid & 15;
        const int ty = tid >> 4;
        float acc[8][8];
        #pragma unroll
        for (int s = 0; s < 8; s++)
            #pragma unroll
            for (int r = 0; r < 8; r++) acc[s][r] = 0.f;

        const float4* Ws4c = (const float4*)Ws;
        const float4* Xs4c = (const float4*)Xs;

        for (int k = 0; k < 128; k += 4) {
            float4 xv[8];
            #pragma unroll
            for (int s = 0; s < 8; s++)
                xv[s] = Xs4c[((ty + 16 * s) * 128 + k) >> 2];
            #pragma unroll
            for (int kk = 0; kk < 4; kk++) {
                float4 wa = Ws4c[((k + kk) * 128 >> 2) + tx];
                float4 wb = Ws4c[(((k + kk) * 128 + 64) >> 2) + tx];
                #pragma unroll
                for (int s = 0; s < 8; s++) {
                    float xs = (kk == 0) ? xv[s].x : (kk == 1) ? xv[s].y
                             : (kk == 2) ? xv[s].z : xv[s].w;
                    acc[s][0] = fmaf(xs, wa.x, acc[s][0]);
                    acc[s][1] = fmaf(xs, wa.y, acc[s][1]);
                    acc[s][2] = fmaf(xs, wa.z, acc[s][2]);
                    acc[s][3] = fmaf(xs, wa.w, acc[s][3]);
                    acc[s][4] = fmaf(xs, wb.x, acc[s][4]);
                    acc[s][5] = fmaf(xs, wb.y, acc[s][5]);
                    acc[s][6] = fmaf(xs, wb.z, acc[s][6]);
                    acc[s][7] = fmaf(xs, wb.w, acc[s][7]);
                }
            }
        }

        float4 bb = ((const float4*)bl)[tx];
        #pragma unroll
        for (int s = 0; s < 8; s++) {
            int gi = n0 + ty + 16 * s;
            if (gi >= n) continue;
            float4 v0 = make_float4(acc[s][0], acc[s][1], acc[s][2], acc[s][3]);
            float4 v1 = make_float4(acc[s][4] + bb.x, acc[s][5] + bb.y,
                                    acc[s][6] + bb.z, acc[s][7] + bb.w);
            ((float4*)g_y0)  [gi * 16 + tx] = v0;
            ((float4*)g_base)[gi * 16 + tx] = v1;
        }
    }
#endif
}

// ---------------------------------------------------------------------
// e0 = mean(x_emb, axis=1) @ We0^T + be0   (K=64, 64 outputs)
__global__ void __launch_bounds__(128) k_emb0(
    const float* __restrict__ xe, const float* __restrict__ We,
    const float* __restrict__ be, int n)
{
    __shared__ __align__(16) float Ws[64 * 64];
    __shared__ __align__(16) float Xs[64 * 64];
    const int tid = threadIdx.x;
    const int n0 = blockIdx.x * 64;

    const float4* W4 = (const float4*)We;
    for (int m = tid; m < 64 * 16; m += 128) {
        int o  = m & 63;
        int kq = m >> 6;
        float4 a = W4[o * 16 + kq];
        int k = kq * 4;
        Ws[(k+0)*64 + o] = a.x;  Ws[(k+1)*64 + o] = a.y;
        Ws[(k+2)*64 + o] = a.z;  Ws[(k+3)*64 + o] = a.w;
    }
    const float4* E4 = (const float4*)xe;
    float4* Xs4 = (float4*)Xs;
    for (int m = tid; m < 64 * 16; m += 128) {
        int node = m >> 4;
        int kq   = m & 15;
        int gi = n0 + node;
        float4 v = make_float4(0.f, 0.f, 0.f, 0.f);
        if (gi < n) {
            float4 a = E4[gi * 32 + kq];
            float4 b = E4[gi * 32 + 16 + kq];
            v = make_float4(0.5f*(a.x+b.x), 0.5f*(a.y+b.y),
                            0.5f*(a.z+b.z), 0.5f*(a.w+b.w));
        }
        Xs4[node * 16 + kq] = v;
    }
    __syncthreads();

    const int tx = tid & 15;
    const int ty = tid >> 4;
    float acc[8][4];
    #pragma unroll
    for (int s = 0; s < 8; s++)
        #pragma unroll
        for (int r = 0; r < 4; r++) acc[s][r] = 0.f;

    const float4* Ws4c = (const float4*)Ws;
    const float4* Xs4c = (const float4*)Xs;

    for (int k = 0; k < 64; k += 4) {
        float4 xv[8];
        #pragma unroll
        for (int s = 0; s < 8; s++)
            xv[s] = Xs4c[((ty + 8 * s) * 64 + k) >> 2];
        #pragma unroll
        for (int kk = 0; kk < 4; kk++) {
            float4 w = Ws4c[((k + kk) * 64 >> 2) + tx];
            #pragma unroll
            for (int s = 0; s < 8; s++) {
                float xs = (kk == 0) ? xv[s].x : (kk == 1) ? xv[s].y
                         : (kk == 2) ? xv[s].z : xv[s].w;
                acc[s][0] = fmaf(xs, w.x, acc[s][0]);
                acc[s][1] = fmaf(xs, w.y, acc[s][1]);
                acc[s][2] = fmaf(xs, w.z, acc[s][2]);
                acc[s][3] = fmaf(xs, w.w, acc[s][3]);
            }
        }
    }

    float4 bb = ((const float4*)be)[tx];
    #pragma unroll
    for (int s = 0; s < 8; s++) {
        int gi = n0 + ty + 8 * s;
        if (gi >= n) continue;
        float4 v = make_float4(acc[s][0] + bb.x, acc[s][1] + bb.y,
                               acc[s][2] + bb.z, acc[s][3] + bb.w);
        ((float4*)g_e0)[gi * 16 + tx] = v;
    }
}

// ---------------------------------------------------------------------
// gather0 + combine0 fused: one warp per node, unroll 4.
__global__ void __launch_bounds__(256) k_gather0(int n) {
    int warp = (blockIdx.x * 256 + threadIdx.x) >> 5;
    int lane = threadIdx.x & 31;
    if (warp >= n) return;
    int beg = g_off[warp];
    int end = g_off[warp + 1];
    const float2* Y = (const float2*)g_y0;

    float2 acc = make_float2(0.f, 0.f);
    int e = beg;
    for (; e + 3 < end; e += 4) {
        int s0 = g_esrc[e];
        int s1 = g_esrc[e + 1];
        int s2 = g_esrc[e + 2];
        int s3 = g_esrc[e + 3];
        float2 v0 = Y[s0 * 32 + lane];
        float2 v1 = Y[s1 * 32 + lane];
        float2 v2 = Y[s2 * 32 + lane];
        float2 v3 = Y[s3 * 32 + lane];
        acc.x += (v0.x + v1.x) + (v2.x + v3.x);
        acc.y += (v0.y + v1.y) + (v2.y + v3.y);
    }
    for (; e < end; e++) {
        int s0 = g_esrc[e];
        float2 v0 = Y[s0 * 32 + lane];
        acc.x += v0.x;
        acc.y += v0.y;
    }
    float inv = 1.0f / fmaxf((float)(end - beg), 1.0f);
    float2 b = ((const float2*)g_base)[warp * 32 + lane];
    float2 e0 = ((const float2*)g_e0)[warp * 32 + lane];
    float2 h;
    h.x = fmaxf(fmaf(acc.x, inv, b.x + e0.x), 0.f);
    h.y = fmaxf(fmaf(acc.y, inv, b.y + e0.y), 0.f);
    ((float2*)g_h)[warp * 32 + lane] = h;
}

// ---------------------------------------------------------------------
// Layer-1 node transforms: y1 = h@Wl1^T, r1 = h@Wr1^T, er1 = e0@We1^T.
__global__ void __launch_bounds__(96) k_transform1(
    const float* __restrict__ Wl1, const float* __restrict__ Wr1,
    const float* __restrict__ We1, int n)
{
    __shared__ __align__(16) float Hs[64 * 64];
    __shared__ __align__(16) float Es[64 * 64];
    __shared__ __align__(16) float Ws[64 * 48];
    const int tid = threadIdx.x;
    const int n0 = blockIdx.x * 64;

    for (int m = tid; m < 48 * 16; m += 96) {
        int o  = m % 48;
        int kq = m / 48;
        const float4* src = (o < 16) ? ((const float4*)Wl1) + o * 16
                          : (o < 32) ? ((const float4*)Wr1) + (o - 16) * 16
                                     : ((const float4*)We1) + (o - 32) * 16;
        float4 a = src[kq];
        int k = kq * 4;
        Ws[(k+0)*48 + o] = a.x;  Ws[(k+1)*48 + o] = a.y;
        Ws[(k+2)*48 + o] = a.z;  Ws[(k+3)*48 + o] = a.w;
    }
    for (int m = tid; m < 64 * 16; m += 96) {
        int node = m >> 4;
        int kq   = m & 15;
        int gi = n0 + node;
        float4 v = make_float4(0.f, 0.f, 0.f, 0.f);
        float4 w = v;
        if (gi < n) {
            v = ((const float4*)g_h )[gi * 16 + kq];
            w = ((const float4*)g_e0)[gi * 16 + kq];
        }
        ((float4*)Hs)[node * 16 + kq] = v;
        ((float4*)Es)[node * 16 + kq] = w;
    }
    __syncthreads();

    const int g  = tid % 12;
    const int ty = tid / 12;
    const float* In = (g < 8) ? Hs : Es;
    float acc[8][4];
    #pragma unroll
    for (int s = 0; s < 8; s++)
        #pragma unroll
        for (int r = 0; r < 4; r++) acc[s][r] = 0.f;

    for (int k = 0; k < 64; k++) {
        float4 w = ((const float4*)Ws)[k * 12 + g];
        float xv[8];
        #pragma unroll
        for (int s = 0; s < 8; s++) xv[s] = In[(ty + 8 * s) * 64 + k];
        #pragma unroll
        for (int s = 0; s < 8; s++) {
            acc[s][0] = fmaf(xv[s], w.x, acc[s][0]);
            acc[s][1] = fmaf(xv[s], w.y, acc[s][1]);
            acc[s][2] = fmaf(xv[s], w.z, acc[s][2]);
            acc[s][3] = fmaf(xv[s], w.w, acc[s][3]);
        }
    }

    #pragma unroll
    for (int s = 0; s < 8; s++) {
        int gi = n0 + ty + 8 * s;
        if (gi >= n) continue;
        float4 v = make_float4(acc[s][0], acc[s][1], acc[s][2], acc[s][3]);
        if (g < 4)       ((float4*)g_y1 )[gi * 4 + g]       = v;
        else if (g < 8)  ((float4*)g_r1 )[gi * 4 + (g - 4)] = v;
        else             ((float4*)g_er1)[gi * 4 + (g - 8)] = v;
    }
}

// ---------------------------------------------------------------------
// gather1 + final fused: 8 lanes per node, unroll 2.
__global__ void __launch_bounds__(256) k_gather1(
    const float* __restrict__ bl1, const float* __restrict__ be1,
    float* __restrict__ out, int n)
{
    int t = blockIdx.x * 256 + threadIdx.x;
    int node = t >> 3;
    int sub = t & 7;
    if (node >= n) return;
    int beg = g_off[node];
    int end = g_off[node + 1];
    const float2* Y = (const float2*)g_y1;

    float2 acc = make_float2(0.f, 0.f);
    int e = beg;
    for (; e + 1 < end; e += 2) {
        int s0 = g_esrc[e];
        int s1 = g_esrc[e + 1];
        float2 v0 = Y[s0 * 8 + sub];
        float2 v1 = Y[s1 * 8 + sub];
        acc.x += v0.x + v1.x;
        acc.y += v0.y + v1.y;
    }
    if (e < end) {
        int s0 = g_esrc[e];
        float2 v0 = Y[s0 * 8 + sub];
        acc.x += v0.x;
        acc.y += v0.y;
    }
    float inv = 1.0f / fmaxf((float)(end - beg), 1.0f);
    float2 r = ((const float2*)g_r1 )[node * 8 + sub];
    float2 er = ((const float2*)g_er1)[node * 8 + sub];
    float2 o;
    o.x = fmaf(acc.x, inv, r.x + er.x + bl1[2*sub+0] + be1[2*sub+0]);
    o.y = fmaf(acc.y, inv, r.y + er.y + bl1[2*sub+1] + be1[2*sub+1]);
    ((float2*)out)[node * 8 + sub] = o;
}

// ---------------------------------------------------------------------
extern "C" void kernel_launch(void* const* d_in, const int* in_sizes, int n_in,
                              void* d_out, int out_size)
{
    const float* x_feat = (const float*)d_in[0];
    const float* x_emb  = (const float*)d_in[1];
    const int*   ei     = (const int*)  d_in[2];
    const float* Wl0 = (const float*)d_in[3];
    const float* bl0 = (const float*)d_in[4];
    const float* Wr0 = (const float*)d_in[5];
    const float* We0 = (const float*)d_in[6];
    const float* be0 = (const float*)d_in[7];
    const float* Wl1 = (const float*)d_in[8];
    const float* bl1 = (const float*)d_in[9];
    const float* Wr1 = (const float*)d_in[10];
    const float* We1 = (const float*)d_in[11];
    const float* be1 = (const float*)d_in[12];

    int n = in_sizes[0] / 128;
    int E = in_sizes[2] / 2;

    cudaFuncSetAttribute(k_transform0,
                         cudaFuncAttributeMaxDynamicSharedMemorySize, SM_TOTAL_MMA);

    // (1)(2) independent node transforms
    k_emb0<<<(n + 63) / 64, 128>>>(x_emb, We0, be0, n);
    k_transform0<<<148, 256, SM_TOTAL_MMA>>>(x_feat, Wl0, Wr0, bl0, n);

    // (3) zero counts (hoisted out of coop kernel)
    k_zero_cnt<<<(n + 255) / 256, 256>>>(n);

    // (4) CSR hist+scan (cooperative)  <-- profiled slot
    {
        int G = (n + 255) / 256;
        void* args[] = { (void*)&ei, (void*)&n, (void*)&E };
        cudaLaunchCooperativeKernel((void*)k_csr_build, dim3(G), dim3(256), args, 0, 0);
    }

    // (5) CSR fill
    k_fill<<<(E / 4 + 255) / 256, 256>>>(ei, E);

    // (6) layer-0 aggregate + combine
    k_gather0<<<(n + 7) / 8, 256>>>(n);

    // (7)(8) layer 1
    k_transform1<<<(n + 63) / 64, 96>>>(Wl1, Wr1, We1, n);
    k_gather1<<<(n * 8 + 255) / 256, 256>>>(bl1, be1, (float*)d_out, n);
}

// round 15
// speedup vs baseline: 1.2082x; 1.0125x over previous
#include <cuda_runtime.h>
#include <cuda_bf16.h>
#include <cooperative_groups.h>
#include <cstdint>

namespace cg = cooperative_groups;

#define NODES 100000
#define EDGES 1600000

// ---- device scratch (allocation-free contract: __device__ globals) ----
__device__ __align__(16) float g_y0  [NODES*64];
__device__ __align__(16) float g_base[NODES*64];
__device__ __align__(16) float g_e0  [NODES*64];
__device__ __align__(16) float g_h   [NODES*64];
__device__ __align__(16) float g_y1  [NODES*16];
__device__ __align__(16) float g_r1  [NODES*16];
__device__ __align__(16) float g_er1 [NODES*16];
// CSR-by-dst
__device__ int g_cnt [NODES];
__device__ int g_off [NODES + 1];
__device__ int g_cur [NODES];
__device__ int g_esrc[EDGES];
__device__ int g_bsum[1024];

#if defined(__CUDA_ARCH__) && (defined(__CUDA_ARCH_FEAT_SM103_ALL) || defined(__CUDA_ARCH_FEAT_SM100_ALL))
#define HAS_TCGEN05 1
#else
#define HAS_TCGEN05 0
#endif

// ======================= CSR build =====================================
__global__ void k_zero_cnt(int n) {
    int i = blockIdx.x * blockDim.x + threadIdx.x;
    if (i < n) g_cnt[i] = 0;
}

__global__ void __launch_bounds__(256) k_csr_build(const int* __restrict__ ei,
                                                   int n, int E)
{
    cg::grid_group grid = cg::this_grid();
    const int tid = threadIdx.x;
    const int b   = blockIdx.x;
    const int G   = gridDim.x;
    const int lane = tid & 31;
    const int w    = tid >> 5;
    __shared__ int ws[8];

    {
        const int4* D4 = (const int4*)(ei + E);
        int q = E >> 2;
        for (int i = b * 256 + tid; i < q; i += G * 256) {
            int4 d = D4[i];
            atomicAdd(&g_cnt[d.x], 1);
            atomicAdd(&g_cnt[d.y], 1);
            atomicAdd(&g_cnt[d.z], 1);
            atomicAdd(&g_cnt[d.w], 1);
        }
        for (int e = (q << 2) + b * 256 + tid; e < E; e += G * 256)
            atomicAdd(&g_cnt[ei[E + e]], 1);
    }
    grid.sync();

    {
        int i = b * 256 + tid;
        int v = (i < n) ? g_cnt[i] : 0;
        int x = v;
        #pragma unroll
        for (int d = 1; d < 32; d <<= 1) {
            int t = __shfl_up_sync(0xFFFFFFFF, x, d);
            if (lane >= d) x += t;
        }
        if (lane == 31) ws[w] = x;
        __syncthreads();
        int base = 0;
        #pragma unroll
        for (int k = 0; k < 8; k++) base += (k < w) ? ws[k] : 0;
        int incl = base + x;
        if (i < n) g_off[i] = incl - v;
        if (tid == 0) {
            int tot = 0;
            #pragma unroll
            for (int k = 0; k < 8; k++) tot += ws[k];
            g_bsum[b] = tot;
        }
    }
    grid.sync();

    if (b == 0) {
        int per = (G + 255) / 256;
        int s[4];
        int sum = 0;
        #pragma unroll 4
        for (int j = 0; j < per; j++) {
            int idx = tid * per + j;
            s[j] = (idx < G) ? g_bsum[idx] : 0;
            sum += s[j];
        }
        int x = sum;
        #pragma unroll
        for (int d = 1; d < 32; d <<= 1) {
            int t = __shfl_up_sync(0xFFFFFFFF, x, d);
            if (lane >= d) x += t;
        }
        if (lane == 31) ws[w] = x;
        __syncthreads();
        int base = 0;
        #pragma unroll
        for (int k = 0; k < 8; k++) base += (k < w) ? ws[k] : 0;
        int run = base + x - sum;
        #pragma unroll 4
        for (int j = 0; j < per; j++) {
            int idx = tid * per + j;
            if (idx < G) { g_bsum[idx] = run; run += s[j]; }
        }
    }
    grid.sync();

    {
        int i = b * 256 + tid;
        if (i < n) {
            int o = g_off[i] + g_bsum[b];
            g_off[i] = o;
            g_cur[i] = o;
        }
        if (b == 0 && tid == 0) g_off[n] = E;
    }
}

__global__ void k_fill(const int* __restrict__ ei, int E) {
    int q = E >> 2;
    int i = blockIdx.x * blockDim.x + threadIdx.x;
    const int4* S4 = (const int4*)ei;
    const int4* D4 = (const int4*)(ei + E);
    if (i < q) {
        int4 s = S4[i];
        int4 d = D4[i];
        g_esrc[atomicAdd(&g_cur[d.x], 1)] = s.x;
        g_esrc[atomicAdd(&g_cur[d.y], 1)] = s.y;
        g_esrc[atomicAdd(&g_cur[d.z], 1)] = s.z;
        g_esrc[atomicAdd(&g_cur[d.w], 1)] = s.w;
    }
    int e = (q << 2) + i;
    if (i < (E - (q << 2))) {
        int dst = ei[E + e];
        g_esrc[atomicAdd(&g_cur[dst], 1)] = ei[e];
    }
}

// ================= persistent transform0 smem layout =================
static constexpr int SM_BH   = 0;
static constexpr int SM_BL   = 32768;
static constexpr int SM_A0H  = 65536;
static constexpr int SM_A0L  = 98304;
static constexpr int SM_A1H  = 131072;
static constexpr int SM_A1L  = 163840;
static constexpr int SM_TMEM = 196608;
static constexpr int SM_MBAR0= 196616;
static constexpr int SM_MBAR1= 196624;
static constexpr int SM_TOTAL_MMA = 196640;

#if HAS_TCGEN05
__device__ __forceinline__ uint32_t smem_u32(const void* p) {
    uint32_t a;
    asm("{ .reg .u64 t; cvta.to.shared.u64 t, %1; cvt.u32.u64 %0, t; }"
        : "=r"(a) : "l"(p));
    return a;
}

__device__ __forceinline__ uint32_t elect_one() {
    uint32_t pred;
    asm volatile("{ .reg .pred p; elect.sync _|p, 0xFFFFFFFF; selp.b32 %0, 1, 0, p; }"
                 : "=r"(pred));
    return pred;
}

static constexpr uint32_t MMA_IDESC = (1u<<4) | (1u<<7) | (1u<<10)
                                    | ((128u/8u)<<17) | ((128u/16u)<<24);

static constexpr uint64_t DESC_BASE =
    (uint64_t(2) << 61) | (uint64_t(1) << 46) | (uint64_t(64) << 32) | (uint64_t(1) << 16);

__device__ __forceinline__ uint64_t make_desc(uint32_t addr) {
    return DESC_BASE | ((uint64_t)(addr >> 4) & 0x3FFF);
}

__device__ __forceinline__ void mma_bf16_ss(uint32_t d_tmem, uint64_t a_desc,
                                            uint64_t b_desc, uint32_t en) {
    asm volatile(
        "{\n\t"
        ".reg .pred p;\n\t"
        "setp.ne.u32 p, %4, 0;\n\t"
        "tcgen05.mma.cta_group::1.kind::f16 [%0], %1, %2, %3, {%5, %5, %5, %5}, p;\n\t"
        "}"
        :: "r"(d_tmem), "l"(a_desc), "l"(b_desc), "r"(MMA_IDESC),
           "r"(en), "r"(0u)
        : "memory");
}

__device__ __forceinline__ void mbar_wait(uint32_t mbar, uint32_t parity) {
    uint32_t done;
    asm volatile(
        "{\n\t.reg .pred p;\n\t"
        "mbarrier.try_wait.parity.acquire.cta.shared::cta.b64 p, [%1], %2;\n\t"
        "selp.b32 %0, 1, 0, p;\n\t}"
        : "=r"(done) : "r"(mbar), "r"(parity) : "memory");
    if (!done) {
        asm volatile(
            "{\n\t.reg .pred P1;\n\t"
            "WAIT_LOOP_%=:\n\t"
            "mbarrier.try_wait.parity.acquire.cta.shared::cta.b64 P1, [%0], %1, 0x989680;\n\t"
            "@P1 bra.uni WAIT_DONE_%=;\n\t"
            "bra.uni WAIT_LOOP_%=;\n\t"
            "WAIT_DONE_%=:\n\t}"
            :: "r"(mbar), "r"(parity) : "memory");
    }
}

#define TCLD_X32(r, addr) \
    asm volatile( \
        "tcgen05.ld.sync.aligned.32x32b.x32.b32 " \
        "{%0, %1, %2, %3, %4, %5, %6, %7, " \
        " %8, %9, %10, %11, %12, %13, %14, %15, " \
        " %16, %17, %18, %19, %20, %21, %22, %23, " \
        " %24, %25, %26, %27, %28, %29, %30, %31}, [%32];" \
        : "=r"((r)[0]), "=r"((r)[1]), "=r"((r)[2]), "=r"((r)[3]), \
          "=r"((r)[4]), "=r"((r)[5]), "=r"((r)[6]), "=r"((r)[7]), \
          "=r"((r)[8]), "=r"((r)[9]), "=r"((r)[10]), "=r"((r)[11]), \
          "=r"((r)[12]), "=r"((r)[13]), "=r"((r)[14]), "=r"((r)[15]), \
          "=r"((r)[16]), "=r"((r)[17]), "=r"((r)[18]), "=r"((r)[19]), \
          "=r"((r)[20]), "=r"((r)[21]), "=r"((r)[22]), "=r"((r)[23]), \
          "=r"((r)[24]), "=r"((r)[25]), "=r"((r)[26]), "=r"((r)[27]), \
          "=r"((r)[28]), "=r"((r)[29]), "=r"((r)[30]), "=r"((r)[31]) \
        : "r"(addr))
#endif

__device__ __forceinline__ uint32_t tile_off(int row, int k) {
    uint32_t off = (uint32_t)((row >> 3) + (k >> 6) * 16) * 1024
                 + (uint32_t)(row & 7) * 128 + (uint32_t)(k & 63) * 2;
    return off ^ ((off >> 3) & 0x70);
}

__device__ __forceinline__ void cvt_store_hl(char* ph, char* pl, float4 v) {
    __nv_bfloat16 h0 = __float2bfloat16(v.x);
    __nv_bfloat16 h1 = __float2bfloat16(v.y);
    __nv_bfloat16 h2 = __float2bfloat16(v.z);
    __nv_bfloat16 h3 = __float2bfloat16(v.w);
    __nv_bfloat16 l0 = __float2bfloat16(v.x - __bfloat162float(h0));
    __nv_bfloat16 l1 = __float2bfloat16(v.y - __bfloat162float(h1));
    __nv_bfloat16 l2 = __float2bfloat16(v.z - __bfloat162float(h2));
    __nv_bfloat16 l3 = __float2bfloat16(v.w - __bfloat162float(h3));
    union { __nv_bfloat162 b[2]; uint64_t u; } uh, ul;
    uh.b[0] = __halves2bfloat162(h0, h1);
    uh.b[1] = __halves2bfloat162(h2, h3);
    ul.b[0] = __halves2bfloat162(l0, l1);
    ul.b[1] = __halves2bfloat162(l2, l3);
    *(uint64_t*)ph = uh.u;
    *(uint64_t*)pl = ul.u;
}

// ---------------------------------------------------------------------
// persistent transform0: [y0 | base] = x_feat @ [Wl0 ; Wr0]^T
__global__ void __launch_bounds__(256) k_transform0(
    const float* __restrict__ x, const float* __restrict__ Wl,
    const float* __restrict__ Wr, const float* __restrict__ bl, int n)
{
    extern __shared__ __align__(1024) char smem[];
    const int tid = threadIdx.x;
    const int T = (n + 127) / 128;

#if HAS_TCGEN05
    const int wid = tid >> 5;
    const int lid = tid & 31;
    const uint32_t sbase = smem_u32(smem);

    if (wid == 0) {
        asm volatile("tcgen05.alloc.cta_group::1.sync.aligned.shared::cta.b32 [%0], %1;"
                     :: "r"(sbase + SM_TMEM), "r"(256u) : "memory");
    }
    if (tid == 0) {
        asm volatile("mbarrier.init.shared.b64 [%0], %1;"
                     :: "r"(sbase + SM_MBAR0), "r"(1u) : "memory");
        asm volatile("mbarrier.init.shared.b64 [%0], %1;"
                     :: "r"(sbase + SM_MBAR1), "r"(1u) : "memory");
    }

    const float4* Wl4 = (const float4*)Wl;
    const float4* Wr4 = (const float4*)Wr;
    for (int m = tid; m < 128 * 32; m += 256) {
        int row = m >> 5, kq = m & 31;
        float4 v = (row < 64) ? Wl4[row * 32 + kq] : Wr4[(row - 64) * 32 + kq];
        uint32_t off = tile_off(row, kq * 4);
        cvt_store_hl(smem + SM_BH + off, smem + SM_BL + off, v);
    }
    __syncthreads();

    uint32_t tmem_base;
    asm volatile("ld.shared.b32 %0, [%1];" : "=r"(tmem_base) : "r"(sbase + SM_TMEM));

    const float4* X4 = (const float4*)x;
    const uint32_t abufH[2] = { sbase + SM_A0H, sbase + SM_A1H };
    const uint32_t mbar[2]  = { sbase + SM_MBAR0, sbase + SM_MBAR1 };
    uint64_t dB_h = make_desc(sbase + SM_BH);
    uint64_t dB_l = make_desc(sbase + SM_BL);
    int ph0 = 0, ph1 = 0;

    #define STAGE_A(tile, buf) do {                                         \
        int _n0 = (tile) * 128;                                             \
        char* _ah = smem + SM_A0H + (buf) * 65536;                          \
        char* _al = _ah + 32768;                                            \
        _Pragma("unroll")                                                   \
        for (int c = 0; c < 4; c++) {                                       \
            float4 v[4];                                                    \
            uint32_t off[4];                                                \
            _Pragma("unroll")                                               \
            for (int j = 0; j < 4; j++) {                                   \
                int m = tid + (c * 4 + j) * 256;                            \
                int row = m >> 5, kq = m & 31;                              \
                int gi = _n0 + row;                                         \
                v[j] = make_float4(0.f, 0.f, 0.f, 0.f);                     \
                if (gi < n) v[j] = X4[gi * 32 + kq];                        \
                off[j] = tile_off(row, kq * 4);                             \
            }                                                               \
            _Pragma("unroll")                                               \
            for (int j = 0; j < 4; j++)                                     \
                cvt_store_hl(_ah + off[j], _al + off[j], v[j]);             \
        }                                                                   \
    } while (0)

    #define ISSUE_MMA(buf) do {                                             \
        if (wid == 0) {                                                      \
            if (elect_one()) {                                               \
                asm volatile("fence.proxy.async.shared::cta;" ::: "memory"); \
                uint64_t dAh = make_desc(abufH[buf]);                        \
                uint64_t dAl = make_desc(abufH[buf] + 32768);                \
                uint64_t pA[3] = { dAh, dAh, dAl };                          \
                uint64_t pB[3] = { dB_h, dB_l, dB_h };                       \
                uint32_t dst = tmem_base + (buf) * 128;                      \
                uint32_t en = 0;                                             \
                _Pragma("unroll")                                            \
                for (int p = 0; p < 3; p++) {                                \
                    _Pragma("unroll")                                        \
                    for (int ks = 0; ks < 8; ks++) {                         \
                        uint64_t doff = (uint64_t)((ks & 3) * 2 + (ks >> 2) * 1024); \
                        mma_bf16_ss(dst, pA[p] + doff, pB[p] + doff, en);    \
                        en = 1;                                              \
                    }                                                        \
                }                                                            \
                asm volatile(                                                \
                    "tcgen05.commit.cta_group::1.mbarrier::arrive::one.shared::cluster.b64 [%0];" \
                    :: "r"(mbar[buf]) : "memory");                           \
            }                                                                \
        }                                                                    \
    } while (0)

    int t = blockIdx.x;
    int k = 0;
    if (t < T) {
        STAGE_A(t, 0);
        __syncthreads();
        ISSUE_MMA(0);
    }
    for (; t < T; t += gridDim.x, k++) {
        int buf = k & 1;
        int tn = t + gridDim.x;
        if (tn < T) {
            STAGE_A(tn, buf ^ 1);
            __syncthreads();
            ISSUE_MMA(buf ^ 1);
        }
        if (buf == 0) { mbar_wait(mbar[0], ph0); ph0 ^= 1; }
        else          { mbar_wait(mbar[1], ph1); ph1 ^= 1; }
        asm volatile("tcgen05.fence::after_thread_sync;" ::: "memory");

        {
            int row = (wid & 3) * 32 + lid;
            int gi = t * 128 + row;
            uint32_t taddr = tmem_base + buf * 128 + ((uint32_t)(wid & 3) << 21)
                           + ((wid < 4) ? 0u : 64u);
            uint32_t r0[32], r1[32];
            TCLD_X32(r0, taddr);
            TCLD_X32(r1, taddr + 32);
            asm volatile("tcgen05.wait::ld.sync.aligned;" ::: "memory");
            if (gi < n) {
                if (wid < 4) {
                    #pragma unroll
                    for (int j = 0; j < 8; j++) {
                        float4 v = make_float4(__uint_as_float(r0[j*4+0]),
                                               __uint_as_float(r0[j*4+1]),
                                               __uint_as_float(r0[j*4+2]),
                                               __uint_as_float(r0[j*4+3]));
                        ((float4*)g_y0)[gi * 16 + j] = v;
                    }
                    #pragma unroll
                    for (int j = 0; j < 8; j++) {
                        float4 v = make_float4(__uint_as_float(r1[j*4+0]),
                                               __uint_as_float(r1[j*4+1]),
                                               __uint_as_float(r1[j*4+2]),
                                               __uint_as_float(r1[j*4+3]));
                        ((float4*)g_y0)[gi * 16 + 8 + j] = v;
                    }
                } else {
                    #pragma unroll
                    for (int j = 0; j < 8; j++) {
                        float4 bb = ((const float4*)bl)[j];
                        float4 v = make_float4(__uint_as_float(r0[j*4+0]) + bb.x,
                                               __uint_as_float(r0[j*4+1]) + bb.y,
                                               __uint_as_float(r0[j*4+2]) + bb.z,
                                               __uint_as_float(r0[j*4+3]) + bb.w);
                        ((float4*)g_base)[gi * 16 + j] = v;
                    }
                    #pragma unroll
                    for (int j = 0; j < 8; j++) {
                        float4 bb = ((const float4*)bl)[8 + j];
                        float4 v = make_float4(__uint_as_float(r1[j*4+0]) + bb.x,
                                               __uint_as_float(r1[j*4+1]) + bb.y,
                                               __uint_as_float(r1[j*4+2]) + bb.z,
                                               __uint_as_float(r1[j*4+3]) + bb.w);
                        ((float4*)g_base)[gi * 16 + 8 + j] = v;
                    }
                }
            }
            asm volatile("tcgen05.fence::before_thread_sync;" ::: "memory");
        }
        __syncthreads();
    }
    if (wid == 0) {
        asm volatile("tcgen05.dealloc.cta_group::1.sync.aligned.b32 %0, %1;"
                     :: "r"(tmem_base), "r"(256u));
    }
    #undef STAGE_A
    #undef ISSUE_MMA

#else  // ---------------- FFMA fallback (compute_103 PTX pass) ----------------
    float* Ws = (float*)smem;
    float* Xs = (float*)smem + 128 * 128;

    const float4* Wl4 = (const float4*)Wl;
    const float4* Wr4 = (const float4*)Wr;
    for (int m = tid; m < 64 * 32; m += 256) {
        int o  = m & 63;
        int kq = m >> 6;
        float4 a = Wl4[o * 32 + kq];
        float4 b = Wr4[o * 32 + kq];
        int k = kq * 4;
        Ws[(k+0)*128 + o] = a.x;  Ws[(k+1)*128 + o] = a.y;
        Ws[(k+2)*128 + o] = a.z;  Ws[(k+3)*128 + o] = a.w;
        Ws[(k+0)*128 + 64 + o] = b.x;  Ws[(k+1)*128 + 64 + o] = b.y;
        Ws[(k+2)*128 + 64 + o] = b.z;  Ws[(k+3)*128 + 64 + o] = b.w;
    }
    const float4* X4 = (const float4*)x;
    float4* Xs4 = (float4*)Xs;

    for (int t = blockIdx.x; t < T; t += gridDim.x) {
        int n0 = t * 128;
        __syncthreads();
        for (int m = tid; m < 128 * 32; m += 256) {
            int node = m >> 5;
            int kq   = m & 31;
            int gi = n0 + node;
            float4 v = make_float4(0.f, 0.f, 0.f, 0.f);
            if (gi < n) v = X4[gi * 32 + kq];
            Xs4[node * 32 + kq] = v;
        }
        __syncthreads();

        const int tx = tid & 15;
        const int ty = tid >> 4;
        float acc[8][8];
        #pragma unroll
        for (int s = 0; s < 8; s++)
            #pragma unroll
            for (int r = 0; r < 8; r++) acc[s][r] = 0.f;

        const float4* Ws4c = (const float4*)Ws;
        const float4* Xs4c = (const float4*)Xs;

        for (int k = 0; k < 128; k += 4) {
            float4 xv[8];
            #pragma unroll
            for (int s = 0; s < 8; s++)
                xv[s] = Xs4c[((ty + 16 * s) * 128 + k) >> 2];
            #pragma unroll
            for (int kk = 0; kk < 4; kk++) {
                float4 wa = Ws4c[((k + kk) * 128 >> 2) + tx];
                float4 wb = Ws4c[(((k + kk) * 128 + 64) >> 2) + tx];
                #pragma unroll
                for (int s = 0; s < 8; s++) {
                    float xs = (kk == 0) ? xv[s].x : (kk == 1) ? xv[s].y
                             : (kk == 2) ? xv[s].z : xv[s].w;
                    acc[s][0] = fmaf(xs, wa.x, acc[s][0]);
                    acc[s][1] = fmaf(xs, wa.y, acc[s][1]);
                    acc[s][2] = fmaf(xs, wa.z, acc[s][2]);
                    acc[s][3] = fmaf(xs, wa.w, acc[s][3]);
                    acc[s][4] = fmaf(xs, wb.x, acc[s][4]);
                    acc[s][5] = fmaf(xs, wb.y, acc[s][5]);
                    acc[s][6] = fmaf(xs, wb.z, acc[s][6]);
                    acc[s][7] = fmaf(xs, wb.w, acc[s][7]);
                }
            }
        }

        float4 bb = ((const float4*)bl)[tx];
        #pragma unroll
        for (int s = 0; s < 8; s++) {
            int gi = n0 + ty + 16 * s;
            if (gi >= n) continue;
            float4 v0 = make_float4(acc[s][0], acc[s][1], acc[s][2], acc[s][3]);
            float4 v1 = make_float4(acc[s][4] + bb.x, acc[s][5] + bb.y,
                                    acc[s][6] + bb.z, acc[s][7] + bb.w);
            ((float4*)g_y0)  [gi * 16 + tx] = v0;
            ((float4*)g_base)[gi * 16 + tx] = v1;
        }
    }
#endif
}

// ---------------------------------------------------------------------
// e0 = mean(x_emb, axis=1) @ We0^T + be0
__global__ void __launch_bounds__(128) k_emb0(
    const float* __restrict__ xe, const float* __restrict__ We,
    const float* __restrict__ be, int n)
{
    __shared__ __align__(16) float Ws[64 * 64];
    __shared__ __align__(16) float Xs[64 * 64];
    const int tid = threadIdx.x;
    const int n0 = blockIdx.x * 64;

    const float4* W4 = (const float4*)We;
    for (int m = tid; m < 64 * 16; m += 128) {
        int o  = m & 63;
        int kq = m >> 6;
        float4 a = W4[o * 16 + kq];
        int k = kq * 4;
        Ws[(k+0)*64 + o] = a.x;  Ws[(k+1)*64 + o] = a.y;
        Ws[(k+2)*64 + o] = a.z;  Ws[(k+3)*64 + o] = a.w;
    }
    const float4* E4 = (const float4*)xe;
    float4* Xs4 = (float4*)Xs;
    for (int m = tid; m < 64 * 16; m += 128) {
        int node = m >> 4;
        int kq   = m & 15;
        int gi = n0 + node;
        float4 v = make_float4(0.f, 0.f, 0.f, 0.f);
        if (gi < n) {
            float4 a = E4[gi * 32 + kq];
            float4 b = E4[gi * 32 + 16 + kq];
            v = make_float4(0.5f*(a.x+b.x), 0.5f*(a.y+b.y),
                            0.5f*(a.z+b.z), 0.5f*(a.w+b.w));
        }
        Xs4[node * 16 + kq] = v;
    }
    __syncthreads();

    const int tx = tid & 15;
    const int ty = tid >> 4;
    float acc[8][4];
    #pragma unroll
    for (int s = 0; s < 8; s++)
        #pragma unroll
        for (int r = 0; r < 4; r++) acc[s][r] = 0.f;

    const float4* Ws4c = (const float4*)Ws;
    const float4* Xs4c = (const float4*)Xs;

    for (int k = 0; k < 64; k += 4) {
        float4 xv[8];
        #pragma unroll
        for (int s = 0; s < 8; s++)
            xv[s] = Xs4c[((ty + 8 * s) * 64 + k) >> 2];
        #pragma unroll
        for (int kk = 0; kk < 4; kk++) {
            float4 w = Ws4c[((k + kk) * 64 >> 2) + tx];
            #pragma unroll
            for (int s = 0; s < 8; s++) {
                float xs = (kk == 0) ? xv[s].x : (kk == 1) ? xv[s].y
                         : (kk == 2) ? xv[s].z : xv[s].w;
                acc[s][0] = fmaf(xs, w.x, acc[s][0]);
                acc[s][1] = fmaf(xs, w.y, acc[s][1]);
                acc[s][2] = fmaf(xs, w.z, acc[s][2]);
                acc[s][3] = fmaf(xs, w.w, acc[s][3]);
            }
        }
    }

    float4 bb = ((const float4*)be)[tx];
    #pragma unroll
    for (int s = 0; s < 8; s++) {
        int gi = n0 + ty + 8 * s;
        if (gi >= n) continue;
        float4 v = make_float4(acc[s][0] + bb.x, acc[s][1] + bb.y,
                               acc[s][2] + bb.z, acc[s][3] + bb.w);
        ((float4*)g_e0)[gi * 16 + tx] = v;
    }
}

// ---------------------------------------------------------------------
// gather0 + combine0 fused: one warp per node, unroll 4.
__global__ void __launch_bounds__(256) k_gather0(int n) {
    int warp = (blockIdx.x * 256 + threadIdx.x) >> 5;
    int lane = threadIdx.x & 31;
    if (warp >= n) return;
    int beg = g_off[warp];
    int end = g_off[warp + 1];
    const float2* Y = (const float2*)g_y0;

    float2 acc = make_float2(0.f, 0.f);
    int e = beg;
    for (; e + 3 < end; e += 4) {
        int s0 = g_esrc[e];
        int s1 = g_esrc[e + 1];
        int s2 = g_esrc[e + 2];
        int s3 = g_esrc[e + 3];
        float2 v0 = Y[s0 * 32 + lane];
        float2 v1 = Y[s1 * 32 + lane];
        float2 v2 = Y[s2 * 32 + lane];
        float2 v3 = Y[s3 * 32 + lane];
        acc.x += (v0.x + v1.x) + (v2.x + v3.x);
        acc.y += (v0.y + v1.y) + (v2.y + v3.y);
    }
    for (; e < end; e++) {
        int s0 = g_esrc[e];
        float2 v0 = Y[s0 * 32 + lane];
        acc.x += v0.x;
        acc.y += v0.y;
    }
    float inv = 1.0f / fmaxf((float)(end - beg), 1.0f);
    float2 b = ((const float2*)g_base)[warp * 32 + lane];
    float2 e0 = ((const float2*)g_e0)[warp * 32 + lane];
    float2 h;
    h.x = fmaxf(fmaf(acc.x, inv, b.x + e0.x), 0.f);
    h.y = fmaxf(fmaf(acc.y, inv, b.y + e0.y), 0.f);
    ((float2*)g_h)[warp * 32 + lane] = h;
}

// ---------------------------------------------------------------------
// Layer-1 node transforms: y1 = h@Wl1^T, r1 = h@Wr1^T, er1 = e0@We1^T.
__global__ void __launch_bounds__(96) k_transform1(
    const float* __restrict__ Wl1, const float* __restrict__ Wr1,
    const float* __restrict__ We1, int n)
{
    __shared__ __align__(16) float Hs[64 * 64];
    __shared__ __align__(16) float Es[64 * 64];
    __shared__ __align__(16) float Ws[64 * 48];
    const int tid = threadIdx.x;
    const int n0 = blockIdx.x * 64;

    for (int m = tid; m < 48 * 16; m += 96) {
        int o  = m % 48;
        int kq = m / 48;
        const float4* src = (o < 16) ? ((const float4*)Wl1) + o * 16
                          : (o < 32) ? ((const float4*)Wr1) + (o - 16) * 16
                                     : ((const float4*)We1) + (o - 32) * 16;
        float4 a = src[kq];
        int k = kq * 4;
        Ws[(k+0)*48 + o] = a.x;  Ws[(k+1)*48 + o] = a.y;
        Ws[(k+2)*48 + o] = a.z;  Ws[(k+3)*48 + o] = a.w;
    }
    for (int m = tid; m < 64 * 16; m += 96) {
        int node = m >> 4;
        int kq   = m & 15;
        int gi = n0 + node;
        float4 v = make_float4(0.f, 0.f, 0.f, 0.f);
        float4 w = v;
        if (gi < n) {
            v = ((const float4*)g_h )[gi * 16 + kq];
            w = ((const float4*)g_e0)[gi * 16 + kq];
        }
        ((float4*)Hs)[node * 16 + kq] = v;
        ((float4*)Es)[node * 16 + kq] = w;
    }
    __syncthreads();

    const int g  = tid % 12;
    const int ty = tid / 12;
    const float* In = (g < 8) ? Hs : Es;
    float acc[8][4];
    #pragma unroll
    for (int s = 0; s < 8; s++)
        #pragma unroll
        for (int r = 0; r < 4; r++) acc[s][r] = 0.f;

    for (int k = 0; k < 64; k++) {
        float4 w = ((const float4*)Ws)[k * 12 + g];
        float xv[8];
        #pragma unroll
        for (int s = 0; s < 8; s++) xv[s] = In[(ty + 8 * s) * 64 + k];
        #pragma unroll
        for (int s = 0; s < 8; s++) {
            acc[s][0] = fmaf(xv[s], w.x, acc[s][0]);
            acc[s][1] = fmaf(xv[s], w.y, acc[s][1]);
            acc[s][2] = fmaf(xv[s], w.z, acc[s][2]);
            acc[s][3] = fmaf(xv[s], w.w, acc[s][3]);
        }
    }

    #pragma unroll
    for (int s = 0; s < 8; s++) {
        int gi = n0 + ty + 8 * s;
        if (gi >= n) continue;
        float4 v = make_float4(acc[s][0], acc[s][1], acc[s][2], acc[s][3]);
        if (g < 4)       ((float4*)g_y1 )[gi * 4 + g]       = v;
        else if (g < 8)  ((float4*)g_r1 )[gi * 4 + (g - 4)] = v;
        else             ((float4*)g_er1)[gi * 4 + (g - 8)] = v;
    }
}

// ---------------------------------------------------------------------
// gather1 + final fused: 8 lanes per node, unroll 2.
__global__ void __launch_bounds__(256) k_gather1(
    const float* __restrict__ bl1, const float* __restrict__ be1,
    float* __restrict__ out, int n)
{
    int t = blockIdx.x * 256 + threadIdx.x;
    int node = t >> 3;
    int sub = t & 7;
    if (node >= n) return;
    int beg = g_off[node];
    int end = g_off[node + 1];
    const float2* Y = (const float2*)g_y1;

    float2 acc = make_float2(0.f, 0.f);
    int e = beg;
    for (; e + 1 < end; e += 2) {
        int s0 = g_esrc[e];
        int s1 = g_esrc[e + 1];
        float2 v0 = Y[s0 * 8 + sub];
        float2 v1 = Y[s1 * 8 + sub];
        acc.x += v0.x + v1.x;
        acc.y += v0.y + v1.y;
    }
    if (e < end) {
        int s0 = g_esrc[e];
        float2 v0 = Y[s0 * 8 + sub];
        acc.x += v0.x;
        acc.y += v0.y;
    }
    float inv = 1.0f / fmaxf((float)(end - beg), 1.0f);
    float2 r = ((const float2*)g_r1 )[node * 8 + sub];
    float2 er = ((const float2*)g_er1)[node * 8 + sub];
    float2 o;
    o.x = fmaf(acc.x, inv, r.x + er.x + bl1[2*sub+0] + be1[2*sub+0]);
    o.y = fmaf(acc.y, inv, r.y + er.y + bl1[2*sub+1] + be1[2*sub+1]);
    ((float2*)out)[node * 8 + sub] = o;
}

// ---------------------------------------------------------------------
extern "C" void kernel_launch(void* const* d_in, const int* in_sizes, int n_in,
                              void* d_out, int out_size)
{
    const float* x_feat = (const float*)d_in[0];
    const float* x_emb  = (const float*)d_in[1];
    const int*   ei     = (const int*)  d_in[2];
    const float* Wl0 = (const float*)d_in[3];
    const float* bl0 = (const float*)d_in[4];
    const float* Wr0 = (const float*)d_in[5];
    const float* We0 = (const float*)d_in[6];
    const float* be0 = (const float*)d_in[7];
    const float* Wl1 = (const float*)d_in[8];
    const float* bl1 = (const float*)d_in[9];
    const float* Wr1 = (const float*)d_in[10];
    const float* We1 = (const float*)d_in[11];
    const float* be1 = (const float*)d_in[12];

    int n = in_sizes[0] / 128;
    int E = in_sizes[2] / 2;

    cudaFuncSetAttribute(k_transform0,
                         cudaFuncAttributeMaxDynamicSharedMemorySize, SM_TOTAL_MMA);

    // Side streams + events for DAG-parallel section; destroyed at the end
    // of this call so no device-side resources outlive the graph.
    cudaStream_t s2, s3;
    cudaStreamCreateWithFlags(&s2, cudaStreamNonBlocking);
    cudaStreamCreateWithFlags(&s3, cudaStreamNonBlocking);
    cudaEvent_t evFork, ev2, ev3;
    cudaEventCreateWithFlags(&evFork, cudaEventDisableTiming);
    cudaEventCreateWithFlags(&ev2, cudaEventDisableTiming);
    cudaEventCreateWithFlags(&ev3, cudaEventDisableTiming);

    // (1) CSR count+scan — cooperative kernel runs ALONE (co-residency safety)
    k_zero_cnt<<<(n + 255) / 256, 256>>>(n);
    {
        int G = (n + 255) / 256;
        void* args[] = { (void*)&ei, (void*)&n, (void*)&E };
        cudaLaunchCooperativeKernel((void*)k_csr_build, dim3(G), dim3(256), args, 0, 0);
    }

    // fork: fill (s2) and emb0 (s3) run concurrently with transform0 (main)
    cudaEventRecord(evFork, 0);
    cudaStreamWaitEvent(s2, evFork, 0);
    cudaStreamWaitEvent(s3, evFork, 0);

    k_fill<<<(E / 4 + 255) / 256, 256, 0, s2>>>(ei, E);
    cudaEventRecord(ev2, s2);

    k_emb0<<<(n + 63) / 64, 128, 0, s3>>>(x_emb, We0, be0, n);
    cudaEventRecord(ev3, s3);

    k_transform0<<<148, 256, SM_TOTAL_MMA>>>(x_feat, Wl0, Wr0, bl0, n);

    // join before gather0 (needs y0/base, e0, esrc)
    cudaStreamWaitEvent(0, ev2, 0);
    cudaStreamWaitEvent(0, ev3, 0);

    // (2) layer-0 aggregate + combine
    k_gather0<<<(n + 7) / 8, 256>>>(n);

    // (3)(4) layer 1
    k_transform1<<<(n + 63) / 64, 96>>>(Wl1, Wr1, We1, n);
    k_gather1<<<(n * 8 + 255) / 256, 256>>>(bl1, be1, (float*)d_out, n);

    // release host/driver objects (side branches already joined to stream 0)
    cudaEventDestroy(evFork);
    cudaEventDestroy(ev2);
    cudaEventDestroy(ev3);
    cudaStreamDestroy(s2);
    cudaStreamDestroy(s3);
}

// round 16
// speedup vs baseline: 1.3169x; 1.0900x over previous
#include <cuda_runtime.h>
#include <cuda_bf16.h>
#include <cooperative_groups.h>
#include <cstdint>

namespace cg = cooperative_groups;

#define NODES 100000
#define EDGES 1600000

// ---- device scratch (allocation-free contract: __device__ globals) ----
__device__ __align__(16) float g_y0  [NODES*64];
__device__ __align__(16) float g_base[NODES*64];
__device__ __align__(16) float g_e0  [NODES*64];
__device__ __align__(16) float g_h   [NODES*64];
__device__ __align__(16) float g_y1  [NODES*16];
__device__ __align__(16) float g_r1  [NODES*16];
__device__ __align__(16) float g_er1 [NODES*16];
// CSR-by-dst
__device__ int g_cnt [NODES];
__device__ int g_off [NODES + 1];
__device__ int g_cur [NODES];
__device__ int g_esrc[EDGES];
__device__ int g_bsum[1024];

#if defined(__CUDA_ARCH__) && (defined(__CUDA_ARCH_FEAT_SM103_ALL) || defined(__CUDA_ARCH_FEAT_SM100_ALL))
#define HAS_TCGEN05 1
#else
#define HAS_TCGEN05 0
#endif

// ======================= CSR build =====================================
__global__ void k_zero_cnt(int n) {
    int i = blockIdx.x * blockDim.x + threadIdx.x;
    if (i < n) g_cnt[i] = 0;
}

__global__ void __launch_bounds__(256) k_csr_build(const int* __restrict__ ei,
                                                   int n, int E)
{
    cg::grid_group grid = cg::this_grid();
    const int tid = threadIdx.x;
    const int b   = blockIdx.x;
    const int G   = gridDim.x;
    const int lane = tid & 31;
    const int w    = tid >> 5;
    __shared__ int ws[8];

    {
        const int4* D4 = (const int4*)(ei + E);
        int q = E >> 2;
        for (int i = b * 256 + tid; i < q; i += G * 256) {
            int4 d = D4[i];
            atomicAdd(&g_cnt[d.x], 1);
            atomicAdd(&g_cnt[d.y], 1);
            atomicAdd(&g_cnt[d.z], 1);
            atomicAdd(&g_cnt[d.w], 1);
        }
        for (int e = (q << 2) + b * 256 + tid; e < E; e += G * 256)
            atomicAdd(&g_cnt[ei[E + e]], 1);
    }
    grid.sync();

    {
        int i = b * 256 + tid;
        int v = (i < n) ? g_cnt[i] : 0;
        int x = v;
        #pragma unroll
        for (int d = 1; d < 32; d <<= 1) {
            int t = __shfl_up_sync(0xFFFFFFFF, x, d);
            if (lane >= d) x += t;
        }
        if (lane == 31) ws[w] = x;
        __syncthreads();
        int base = 0;
        #pragma unroll
        for (int k = 0; k < 8; k++) base += (k < w) ? ws[k] : 0;
        int incl = base + x;
        if (i < n) g_off[i] = incl - v;
        if (tid == 0) {
            int tot = 0;
            #pragma unroll
            for (int k = 0; k < 8; k++) tot += ws[k];
            g_bsum[b] = tot;
        }
    }
    grid.sync();

    if (b == 0) {
        int per = (G + 255) / 256;
        int s[4];
        int sum = 0;
        #pragma unroll 4
        for (int j = 0; j < per; j++) {
            int idx = tid * per + j;
            s[j] = (idx < G) ? g_bsum[idx] : 0;
            sum += s[j];
        }
        int x = sum;
        #pragma unroll
        for (int d = 1; d < 32; d <<= 1) {
            int t = __shfl_up_sync(0xFFFFFFFF, x, d);
            if (lane >= d) x += t;
        }
        if (lane == 31) ws[w] = x;
        __syncthreads();
        int base = 0;
        #pragma unroll
        for (int k = 0; k < 8; k++) base += (k < w) ? ws[k] : 0;
        int run = base + x - sum;
        #pragma unroll 4
        for (int j = 0; j < per; j++) {
            int idx = tid * per + j;
            if (idx < G) { g_bsum[idx] = run; run += s[j]; }
        }
    }
    grid.sync();

    {
        int i = b * 256 + tid;
        if (i < n) {
            int o = g_off[i] + g_bsum[b];
            g_off[i] = o;
            g_cur[i] = o;
        }
        if (b == 0 && tid == 0) g_off[n] = E;
    }
}

__global__ void k_fill(const int* __restrict__ ei, int E) {
    int q = E >> 2;
    int i = blockIdx.x * blockDim.x + threadIdx.x;
    const int4* S4 = (const int4*)ei;
    const int4* D4 = (const int4*)(ei + E);
    if (i < q) {
        int4 s = S4[i];
        int4 d = D4[i];
        g_esrc[atomicAdd(&g_cur[d.x], 1)] = s.x;
        g_esrc[atomicAdd(&g_cur[d.y], 1)] = s.y;
        g_esrc[atomicAdd(&g_cur[d.z], 1)] = s.z;
        g_esrc[atomicAdd(&g_cur[d.w], 1)] = s.w;
    }
    int e = (q << 2) + i;
    if (i < (E - (q << 2))) {
        int dst = ei[E + e];
        g_esrc[atomicAdd(&g_cur[dst], 1)] = ei[e];
    }
}

// ================= persistent transform0 smem layout =================
static constexpr int SM_BH   = 0;
static constexpr int SM_BL   = 32768;
static constexpr int SM_A0H  = 65536;
static constexpr int SM_A0L  = 98304;
static constexpr int SM_A1H  = 131072;
static constexpr int SM_A1L  = 163840;
static constexpr int SM_TMEM = 196608;
static constexpr int SM_MBAR0= 196616;
static constexpr int SM_MBAR1= 196624;
static constexpr int SM_TOTAL_MMA = 196640;

#if HAS_TCGEN05
__device__ __forceinline__ uint32_t smem_u32(const void* p) {
    uint32_t a;
    asm("{ .reg .u64 t; cvta.to.shared.u64 t, %1; cvt.u32.u64 %0, t; }"
        : "=r"(a) : "l"(p));
    return a;
}

__device__ __forceinline__ uint32_t elect_one() {
    uint32_t pred;
    asm volatile("{ .reg .pred p; elect.sync _|p, 0xFFFFFFFF; selp.b32 %0, 1, 0, p; }"
                 : "=r"(pred));
    return pred;
}

static constexpr uint32_t MMA_IDESC = (1u<<4) | (1u<<7) | (1u<<10)
                                    | ((128u/8u)<<17) | ((128u/16u)<<24);

static constexpr uint64_t DESC_BASE =
    (uint64_t(2) << 61) | (uint64_t(1) << 46) | (uint64_t(64) << 32) | (uint64_t(1) << 16);

__device__ __forceinline__ uint64_t make_desc(uint32_t addr) {
    return DESC_BASE | ((uint64_t)(addr >> 4) & 0x3FFF);
}

__device__ __forceinline__ void mma_bf16_ss(uint32_t d_tmem, uint64_t a_desc,
                                            uint64_t b_desc, uint32_t en) {
    asm volatile(
        "{\n\t"
        ".reg .pred p;\n\t"
        "setp.ne.u32 p, %4, 0;\n\t"
        "tcgen05.mma.cta_group::1.kind::f16 [%0], %1, %2, %3, {%5, %5, %5, %5}, p;\n\t"
        "}"
        :: "r"(d_tmem), "l"(a_desc), "l"(b_desc), "r"(MMA_IDESC),
           "r"(en), "r"(0u)
        : "memory");
}

__device__ __forceinline__ void mbar_wait(uint32_t mbar, uint32_t parity) {
    uint32_t done;
    asm volatile(
        "{\n\t.reg .pred p;\n\t"
        "mbarrier.try_wait.parity.acquire.cta.shared::cta.b64 p, [%1], %2;\n\t"
        "selp.b32 %0, 1, 0, p;\n\t}"
        : "=r"(done) : "r"(mbar), "r"(parity) : "memory");
    if (!done) {
        asm volatile(
            "{\n\t.reg .pred P1;\n\t"
            "WAIT_LOOP_%=:\n\t"
            "mbarrier.try_wait.parity.acquire.cta.shared::cta.b64 P1, [%0], %1, 0x989680;\n\t"
            "@P1 bra.uni WAIT_DONE_%=;\n\t"
            "bra.uni WAIT_LOOP_%=;\n\t"
            "WAIT_DONE_%=:\n\t}"
            :: "r"(mbar), "r"(parity) : "memory");
    }
}

#define TCLD_X32(r, addr) \
    asm volatile( \
        "tcgen05.ld.sync.aligned.32x32b.x32.b32 " \
        "{%0, %1, %2, %3, %4, %5, %6, %7, " \
        " %8, %9, %10, %11, %12, %13, %14, %15, " \
        " %16, %17, %18, %19, %20, %21, %22, %23, " \
        " %24, %25, %26, %27, %28, %29, %30, %31}, [%32];" \
        : "=r"((r)[0]), "=r"((r)[1]), "=r"((r)[2]), "=r"((r)[3]), \
          "=r"((r)[4]), "=r"((r)[5]), "=r"((r)[6]), "=r"((r)[7]), \
          "=r"((r)[8]), "=r"((r)[9]), "=r"((r)[10]), "=r"((r)[11]), \
          "=r"((r)[12]), "=r"((r)[13]), "=r"((r)[14]), "=r"((r)[15]), \
          "=r"((r)[16]), "=r"((r)[17]), "=r"((r)[18]), "=r"((r)[19]), \
          "=r"((r)[20]), "=r"((r)[21]), "=r"((r)[22]), "=r"((r)[23]), \
          "=r"((r)[24]), "=r"((r)[25]), "=r"((r)[26]), "=r"((r)[27]), \
          "=r"((r)[28]), "=r"((r)[29]), "=r"((r)[30]), "=r"((r)[31]) \
        : "r"(addr))
#endif

__device__ __forceinline__ uint32_t tile_off(int row, int k) {
    uint32_t off = (uint32_t)((row >> 3) + (k >> 6) * 16) * 1024
                 + (uint32_t)(row & 7) * 128 + (uint32_t)(k & 63) * 2;
    return off ^ ((off >> 3) & 0x70);
}

__device__ __forceinline__ void cvt_store_hl(char* ph, char* pl, float4 v) {
    __nv_bfloat16 h0 = __float2bfloat16(v.x);
    __nv_bfloat16 h1 = __float2bfloat16(v.y);
    __nv_bfloat16 h2 = __float2bfloat16(v.z);
    __nv_bfloat16 h3 = __float2bfloat16(v.w);
    __nv_bfloat16 l0 = __float2bfloat16(v.x - __bfloat162float(h0));
    __nv_bfloat16 l1 = __float2bfloat16(v.y - __bfloat162float(h1));
    __nv_bfloat16 l2 = __float2bfloat16(v.z - __bfloat162float(h2));
    __nv_bfloat16 l3 = __float2bfloat16(v.w - __bfloat162float(h3));
    union { __nv_bfloat162 b[2]; uint64_t u; } uh, ul;
    uh.b[0] = __halves2bfloat162(h0, h1);
    uh.b[1] = __halves2bfloat162(h2, h3);
    ul.b[0] = __halves2bfloat162(l0, l1);
    ul.b[1] = __halves2bfloat162(l2, l3);
    *(uint64_t*)ph = uh.u;
    *(uint64_t*)pl = ul.u;
}

// ---------------------------------------------------------------------
// persistent transform0: [y0 | base] = x_feat @ [Wl0 ; Wr0]^T
__global__ void __launch_bounds__(256) k_transform0(
    const float* __restrict__ x, const float* __restrict__ Wl,
    const float* __restrict__ Wr, const float* __restrict__ bl, int n)
{
    extern __shared__ __align__(1024) char smem[];
    const int tid = threadIdx.x;
    const int T = (n + 127) / 128;

#if HAS_TCGEN05
    const int wid = tid >> 5;
    const int lid = tid & 31;
    const uint32_t sbase = smem_u32(smem);

    if (wid == 0) {
        asm volatile("tcgen05.alloc.cta_group::1.sync.aligned.shared::cta.b32 [%0], %1;"
                     :: "r"(sbase + SM_TMEM), "r"(256u) : "memory");
    }
    if (tid == 0) {
        asm volatile("mbarrier.init.shared.b64 [%0], %1;"
                     :: "r"(sbase + SM_MBAR0), "r"(1u) : "memory");
        asm volatile("mbarrier.init.shared.b64 [%0], %1;"
                     :: "r"(sbase + SM_MBAR1), "r"(1u) : "memory");
    }

    const float4* Wl4 = (const float4*)Wl;
    const float4* Wr4 = (const float4*)Wr;
    for (int m = tid; m < 128 * 32; m += 256) {
        int row = m >> 5, kq = m & 31;
        float4 v = (row < 64) ? Wl4[row * 32 + kq] : Wr4[(row - 64) * 32 + kq];
        uint32_t off = tile_off(row, kq * 4);
        cvt_store_hl(smem + SM_BH + off, smem + SM_BL + off, v);
    }
    __syncthreads();

    uint32_t tmem_base;
    asm volatile("ld.shared.b32 %0, [%1];" : "=r"(tmem_base) : "r"(sbase + SM_TMEM));

    const float4* X4 = (const float4*)x;
    const uint32_t abufH[2] = { sbase + SM_A0H, sbase + SM_A1H };
    const uint32_t mbar[2]  = { sbase + SM_MBAR0, sbase + SM_MBAR1 };
    uint64_t dB_h = make_desc(sbase + SM_BH);
    uint64_t dB_l = make_desc(sbase + SM_BL);
    int ph0 = 0, ph1 = 0;

    #define STAGE_A(tile, buf) do {                                         \
        int _n0 = (tile) * 128;                                             \
        char* _ah = smem + SM_A0H + (buf) * 65536;                          \
        char* _al = _ah + 32768;                                            \
        _Pragma("unroll")                                                   \
        for (int c = 0; c < 4; c++) {                                       \
            float4 v[4];                                                    \
            uint32_t off[4];                                                \
            _Pragma("unroll")                                               \
            for (int j = 0; j < 4; j++) {                                   \
                int m = tid + (c * 4 + j) * 256;                            \
                int row = m >> 5, kq = m & 31;                              \
                int gi = _n0 + row;                                         \
                v[j] = make_float4(0.f, 0.f, 0.f, 0.f);                     \
                if (gi < n) v[j] = X4[gi * 32 + kq];                        \
                off[j] = tile_off(row, kq * 4);                             \
            }                                                               \
            _Pragma("unroll")                                               \
            for (int j = 0; j < 4; j++)                                     \
                cvt_store_hl(_ah + off[j], _al + off[j], v[j]);             \
        }                                                                   \
    } while (0)

    #define ISSUE_MMA(buf) do {                                             \
        if (wid == 0) {                                                      \
            if (elect_one()) {                                               \
                asm volatile("fence.proxy.async.shared::cta;" ::: "memory"); \
                uint64_t dAh = make_desc(abufH[buf]);                        \
                uint64_t dAl = make_desc(abufH[buf] + 32768);                \
                uint64_t pA[3] = { dAh, dAh, dAl };                          \
                uint64_t pB[3] = { dB_h, dB_l, dB_h };                       \
                uint32_t dst = tmem_base + (buf) * 128;                      \
                uint32_t en = 0;                                             \
                _Pragma("unroll")                                            \
                for (int p = 0; p < 3; p++) {                                \
                    _Pragma("unroll")                                        \
                    for (int ks = 0; ks < 8; ks++) {                         \
                        uint64_t doff = (uint64_t)((ks & 3) * 2 + (ks >> 2) * 1024); \
                        mma_bf16_ss(dst, pA[p] + doff, pB[p] + doff, en);    \
                        en = 1;                                              \
                    }                                                        \
                }                                                            \
                asm volatile(                                                \
                    "tcgen05.commit.cta_group::1.mbarrier::arrive::one.shared::cluster.b64 [%0];" \
                    :: "r"(mbar[buf]) : "memory");                           \
            }                                                                \
        }                                                                    \
    } while (0)

    int t = blockIdx.x;
    int k = 0;
    if (t < T) {
        STAGE_A(t, 0);
        __syncthreads();
        ISSUE_MMA(0);
    }
    for (; t < T; t += gridDim.x, k++) {
        int buf = k & 1;
        int tn = t + gridDim.x;
        if (tn < T) {
            STAGE_A(tn, buf ^ 1);
            __syncthreads();
            ISSUE_MMA(buf ^ 1);
        }
        if (buf == 0) { mbar_wait(mbar[0], ph0); ph0 ^= 1; }
        else          { mbar_wait(mbar[1], ph1); ph1 ^= 1; }
        asm volatile("tcgen05.fence::after_thread_sync;" ::: "memory");

        {
            int row = (wid & 3) * 32 + lid;
            int gi = t * 128 + row;
            uint32_t taddr = tmem_base + buf * 128 + ((uint32_t)(wid & 3) << 21)
                           + ((wid < 4) ? 0u : 64u);
            uint32_t r0[32], r1[32];
            TCLD_X32(r0, taddr);
            TCLD_X32(r1, taddr + 32);
            asm volatile("tcgen05.wait::ld.sync.aligned;" ::: "memory");
            if (gi < n) {
                if (wid < 4) {
                    #pragma unroll
                    for (int j = 0; j < 8; j++) {
                        float4 v = make_float4(__uint_as_float(r0[j*4+0]),
                                               __uint_as_float(r0[j*4+1]),
                                               __uint_as_float(r0[j*4+2]),
                                               __uint_as_float(r0[j*4+3]));
                        ((float4*)g_y0)[gi * 16 + j] = v;
                    }
                    #pragma unroll
                    for (int j = 0; j < 8; j++) {
                        float4 v = make_float4(__uint_as_float(r1[j*4+0]),
                                               __uint_as_float(r1[j*4+1]),
                                               __uint_as_float(r1[j*4+2]),
                                               __uint_as_float(r1[j*4+3]));
                        ((float4*)g_y0)[gi * 16 + 8 + j] = v;
                    }
                } else {
                    #pragma unroll
                    for (int j = 0; j < 8; j++) {
                        float4 bb = ((const float4*)bl)[j];
                        float4 v = make_float4(__uint_as_float(r0[j*4+0]) + bb.x,
                                               __uint_as_float(r0[j*4+1]) + bb.y,
                                               __uint_as_float(r0[j*4+2]) + bb.z,
                                               __uint_as_float(r0[j*4+3]) + bb.w);
                        ((float4*)g_base)[gi * 16 + j] = v;
                    }
                    #pragma unroll
                    for (int j = 0; j < 8; j++) {
                        float4 bb = ((const float4*)bl)[8 + j];
                        float4 v = make_float4(__uint_as_float(r1[j*4+0]) + bb.x,
                                               __uint_as_float(r1[j*4+1]) + bb.y,
                                               __uint_as_float(r1[j*4+2]) + bb.z,
                                               __uint_as_float(r1[j*4+3]) + bb.w);
                        ((float4*)g_base)[gi * 16 + 8 + j] = v;
                    }
                }
            }
            asm volatile("tcgen05.fence::before_thread_sync;" ::: "memory");
        }
        __syncthreads();
    }
    if (wid == 0) {
        asm volatile("tcgen05.dealloc.cta_group::1.sync.aligned.b32 %0, %1;"
                     :: "r"(tmem_base), "r"(256u));
    }
    #undef STAGE_A
    #undef ISSUE_MMA

#else  // ---------------- FFMA fallback (compute_103 PTX pass) ----------------
    float* Ws = (float*)smem;
    float* Xs = (float*)smem + 128 * 128;

    const float4* Wl4 = (const float4*)Wl;
    const float4* Wr4 = (const float4*)Wr;
    for (int m = tid; m < 64 * 32; m += 256) {
        int o  = m & 63;
        int kq = m >> 6;
        float4 a = Wl4[o * 32 + kq];
        float4 b = Wr4[o * 32 + kq];
        int k = kq * 4;
        Ws[(k+0)*128 + o] = a.x;  Ws[(k+1)*128 + o] = a.y;
        Ws[(k+2)*128 + o] = a.z;  Ws[(k+3)*128 + o] = a.w;
        Ws[(k+0)*128 + 64 + o] = b.x;  Ws[(k+1)*128 + 64 + o] = b.y;
        Ws[(k+2)*128 + 64 + o] = b.z;  Ws[(k+3)*128 + 64 + o] = b.w;
    }
    const float4* X4 = (const float4*)x;
    float4* Xs4 = (float4*)Xs;

    for (int t = blockIdx.x; t < T; t += gridDim.x) {
        int n0 = t * 128;
        __syncthreads();
        for (int m = tid; m < 128 * 32; m += 256) {
            int node = m >> 5;
            int kq   = m & 31;
            int gi = n0 + node;
            float4 v = make_float4(0.f, 0.f, 0.f, 0.f);
            if (gi < n) v = X4[gi * 32 + kq];
            Xs4[node * 32 + kq] = v;
        }
        __syncthreads();

        const int tx = tid & 15;
        const int ty = tid >> 4;
        float acc[8][8];
        #pragma unroll
        for (int s = 0; s < 8; s++)
            #pragma unroll
            for (int r = 0; r < 8; r++) acc[s][r] = 0.f;

        const float4* Ws4c = (const float4*)Ws;
        const float4* Xs4c = (const float4*)Xs;

        for (int k = 0; k < 128; k += 4) {
            float4 xv[8];
            #pragma unroll
            for (int s = 0; s < 8; s++)
                xv[s] = Xs4c[((ty + 16 * s) * 128 + k) >> 2];
            #pragma unroll
            for (int kk = 0; kk < 4; kk++) {
                float4 wa = Ws4c[((k + kk) * 128 >> 2) + tx];
                float4 wb = Ws4c[(((k + kk) * 128 + 64) >> 2) + tx];
                #pragma unroll
                for (int s = 0; s < 8; s++) {
                    float xs = (kk == 0) ? xv[s].x : (kk == 1) ? xv[s].y
                             : (kk == 2) ? xv[s].z : xv[s].w;
                    acc[s][0] = fmaf(xs, wa.x, acc[s][0]);
                    acc[s][1] = fmaf(xs, wa.y, acc[s][1]);
                    acc[s][2] = fmaf(xs, wa.z, acc[s][2]);
                    acc[s][3] = fmaf(xs, wa.w, acc[s][3]);
                    acc[s][4] = fmaf(xs, wb.x, acc[s][4]);
                    acc[s][5] = fmaf(xs, wb.y, acc[s][5]);
                    acc[s][6] = fmaf(xs, wb.z, acc[s][6]);
                    acc[s][7] = fmaf(xs, wb.w, acc[s][7]);
                }
            }
        }

        float4 bb = ((const float4*)bl)[tx];
        #pragma unroll
        for (int s = 0; s < 8; s++) {
            int gi = n0 + ty + 16 * s;
            if (gi >= n) continue;
            float4 v0 = make_float4(acc[s][0], acc[s][1], acc[s][2], acc[s][3]);
            float4 v1 = make_float4(acc[s][4] + bb.x, acc[s][5] + bb.y,
                                    acc[s][6] + bb.z, acc[s][7] + bb.w);
            ((float4*)g_y0)  [gi * 16 + tx] = v0;
            ((float4*)g_base)[gi * 16 + tx] = v1;
        }
    }
#endif
}

// ---------------------------------------------------------------------
// e0 = mean(x_emb, axis=1) @ We0^T + be0
__global__ void __launch_bounds__(128) k_emb0(
    const float* __restrict__ xe, const float* __restrict__ We,
    const float* __restrict__ be, int n)
{
    __shared__ __align__(16) float Ws[64 * 64];
    __shared__ __align__(16) float Xs[64 * 64];
    const int tid = threadIdx.x;
    const int n0 = blockIdx.x * 64;

    const float4* W4 = (const float4*)We;
    for (int m = tid; m < 64 * 16; m += 128) {
        int o  = m & 63;
        int kq = m >> 6;
        float4 a = W4[o * 16 + kq];
        int k = kq * 4;
        Ws[(k+0)*64 + o] = a.x;  Ws[(k+1)*64 + o] = a.y;
        Ws[(k+2)*64 + o] = a.z;  Ws[(k+3)*64 + o] = a.w;
    }
    const float4* E4 = (const float4*)xe;
    float4* Xs4 = (float4*)Xs;
    for (int m = tid; m < 64 * 16; m += 128) {
        int node = m >> 4;
        int kq   = m & 15;
        int gi = n0 + node;
        float4 v = make_float4(0.f, 0.f, 0.f, 0.f);
        if (gi < n) {
            float4 a = E4[gi * 32 + kq];
            float4 b = E4[gi * 32 + 16 + kq];
            v = make_float4(0.5f*(a.x+b.x), 0.5f*(a.y+b.y),
                            0.5f*(a.z+b.z), 0.5f*(a.w+b.w));
        }
        Xs4[node * 16 + kq] = v;
    }
    __syncthreads();

    const int tx = tid & 15;
    const int ty = tid >> 4;
    float acc[8][4];
    #pragma unroll
    for (int s = 0; s < 8; s++)
        #pragma unroll
        for (int r = 0; r < 4; r++) acc[s][r] = 0.f;

    const float4* Ws4c = (const float4*)Ws;
    const float4* Xs4c = (const float4*)Xs;

    for (int k = 0; k < 64; k += 4) {
        float4 xv[8];
        #pragma unroll
        for (int s = 0; s < 8; s++)
            xv[s] = Xs4c[((ty + 8 * s) * 64 + k) >> 2];
        #pragma unroll
        for (int kk = 0; kk < 4; kk++) {
            float4 w = Ws4c[((k + kk) * 64 >> 2) + tx];
            #pragma unroll
            for (int s = 0; s < 8; s++) {
                float xs = (kk == 0) ? xv[s].x : (kk == 1) ? xv[s].y
                         : (kk == 2) ? xv[s].z : xv[s].w;
                acc[s][0] = fmaf(xs, w.x, acc[s][0]);
                acc[s][1] = fmaf(xs, w.y, acc[s][1]);
                acc[s][2] = fmaf(xs, w.z, acc[s][2]);
                acc[s][3] = fmaf(xs, w.w, acc[s][3]);
            }
        }
    }

    float4 bb = ((const float4*)be)[tx];
    #pragma unroll
    for (int s = 0; s < 8; s++) {
        int gi = n0 + ty + 8 * s;
        if (gi >= n) continue;
        float4 v = make_float4(acc[s][0] + bb.x, acc[s][1] + bb.y,
                               acc[s][2] + bb.z, acc[s][3] + bb.w);
        ((float4*)g_e0)[gi * 16 + tx] = v;
    }
}

// ---------------------------------------------------------------------
// er1 = e0 @ We1^T  (16 outputs) — runs on side stream, hidden under t0.
__global__ void __launch_bounds__(128) k_er1(
    const float* __restrict__ We1, int n)
{
    __shared__ __align__(16) float Es[64 * 64];
    __shared__ __align__(16) float Ws[64 * 16];   // [k][o]
    const int tid = threadIdx.x;
    const int n0 = blockIdx.x * 64;

    const float4* W4 = (const float4*)We1;
    for (int m = tid; m < 16 * 16; m += 128) {
        int o  = m & 15;
        int kq = m >> 4;
        float4 a = W4[o * 16 + kq];
        int k = kq * 4;
        Ws[(k+0)*16 + o] = a.x;  Ws[(k+1)*16 + o] = a.y;
        Ws[(k+2)*16 + o] = a.z;  Ws[(k+3)*16 + o] = a.w;
    }
    float4* Es4 = (float4*)Es;
    for (int m = tid; m < 64 * 16; m += 128) {
        int node = m >> 4;
        int kq   = m & 15;
        int gi = n0 + node;
        float4 v = make_float4(0.f, 0.f, 0.f, 0.f);
        if (gi < n) v = ((const float4*)g_e0)[gi * 16 + kq];
        Es4[node * 16 + kq] = v;
    }
    __syncthreads();

    // g = output group of 4 (0..3), ty = row lane (0..31); rows = ty + 32*s
    const int g  = tid & 3;
    const int ty = tid >> 2;
    const float4* Ws4c = (const float4*)Ws;
    float acc[2][4];
    #pragma unroll
    for (int s = 0; s < 2; s++)
        #pragma unroll
        for (int r = 0; r < 4; r++) acc[s][r] = 0.f;

    for (int k = 0; k < 64; k++) {
        float4 w = Ws4c[k * 4 + g];
        float x0 = Es[ty * 64 + k];
        float x1 = Es[(ty + 32) * 64 + k];
        acc[0][0] = fmaf(x0, w.x, acc[0][0]);
        acc[0][1] = fmaf(x0, w.y, acc[0][1]);
        acc[0][2] = fmaf(x0, w.z, acc[0][2]);
        acc[0][3] = fmaf(x0, w.w, acc[0][3]);
        acc[1][0] = fmaf(x1, w.x, acc[1][0]);
        acc[1][1] = fmaf(x1, w.y, acc[1][1]);
        acc[1][2] = fmaf(x1, w.z, acc[1][2]);
        acc[1][3] = fmaf(x1, w.w, acc[1][3]);
    }

    #pragma unroll
    for (int s = 0; s < 2; s++) {
        int gi = n0 + ty + 32 * s;
        if (gi >= n) continue;
        ((float4*)g_er1)[gi * 4 + g] =
            make_float4(acc[s][0], acc[s][1], acc[s][2], acc[s][3]);
    }
}

// ---------------------------------------------------------------------
// gather0 + combine0 fused: one warp per node, unroll 4.
__global__ void __launch_bounds__(256) k_gather0(int n) {
    int warp = (blockIdx.x * 256 + threadIdx.x) >> 5;
    int lane = threadIdx.x & 31;
    if (warp >= n) return;
    int beg = g_off[warp];
    int end = g_off[warp + 1];
    const float2* Y = (const float2*)g_y0;

    float2 acc = make_float2(0.f, 0.f);
    int e = beg;
    for (; e + 3 < end; e += 4) {
        int s0 = g_esrc[e];
        int s1 = g_esrc[e + 1];
        int s2 = g_esrc[e + 2];
        int s3 = g_esrc[e + 3];
        float2 v0 = Y[s0 * 32 + lane];
        float2 v1 = Y[s1 * 32 + lane];
        float2 v2 = Y[s2 * 32 + lane];
        float2 v3 = Y[s3 * 32 + lane];
        acc.x += (v0.x + v1.x) + (v2.x + v3.x);
        acc.y += (v0.y + v1.y) + (v2.y + v3.y);
    }
    for (; e < end; e++) {
        int s0 = g_esrc[e];
        float2 v0 = Y[s0 * 32 + lane];
        acc.x += v0.x;
        acc.y += v0.y;
    }
    float inv = 1.0f / fmaxf((float)(end - beg), 1.0f);
    float2 b = ((const float2*)g_base)[warp * 32 + lane];
    float2 e0 = ((const float2*)g_e0)[warp * 32 + lane];
    float2 h;
    h.x = fmaxf(fmaf(acc.x, inv, b.x + e0.x), 0.f);
    h.y = fmaxf(fmaf(acc.y, inv, b.y + e0.y), 0.f);
    ((float2*)g_h)[warp * 32 + lane] = h;
}

// ---------------------------------------------------------------------
// Layer-1 node transforms (y1/r1 only; er1 moved to k_er1):
// y1 = h@Wl1^T, r1 = h@Wr1^T.  128 threads, 64 nodes/block.
__global__ void __launch_bounds__(128) k_transform1(
    const float* __restrict__ Wl1, const float* __restrict__ Wr1, int n)
{
    __shared__ __align__(16) float Hs[64 * 64];
    __shared__ __align__(16) float Ws[64 * 32];   // [k][o], o: 0-15 Wl1, 16-31 Wr1
    const int tid = threadIdx.x;
    const int n0 = blockIdx.x * 64;

    for (int m = tid; m < 32 * 16; m += 128) {
        int o  = m & 31;
        int kq = m >> 5;
        const float4* src = (o < 16) ? ((const float4*)Wl1) + o * 16
                                     : ((const float4*)Wr1) + (o - 16) * 16;
        float4 a = src[kq];
        int k = kq * 4;
        Ws[(k+0)*32 + o] = a.x;  Ws[(k+1)*32 + o] = a.y;
        Ws[(k+2)*32 + o] = a.z;  Ws[(k+3)*32 + o] = a.w;
    }
    float4* Hs4 = (float4*)Hs;
    for (int m = tid; m < 64 * 16; m += 128) {
        int node = m >> 4;
        int kq   = m & 15;
        int gi = n0 + node;
        float4 v = make_float4(0.f, 0.f, 0.f, 0.f);
        if (gi < n) v = ((const float4*)g_h)[gi * 16 + kq];
        Hs4[node * 16 + kq] = v;
    }
    __syncthreads();

    // g = output group of 4 (0..7: g<4 -> y1, else r1); ty = 0..15; rows = ty + 16*s
    const int g  = tid & 7;
    const int ty = tid >> 3;
    const float4* Ws4c = (const float4*)Ws;
    float acc[4][4];
    #pragma unroll
    for (int s = 0; s < 4; s++)
        #pragma unroll
        for (int r = 0; r < 4; r++) acc[s][r] = 0.f;

    for (int k = 0; k < 64; k++) {
        float4 w = Ws4c[k * 8 + g];
        float xv[4];
        #pragma unroll
        for (int s = 0; s < 4; s++) xv[s] = Hs[(ty + 16 * s) * 64 + k];
        #pragma unroll
        for (int s = 0; s < 4; s++) {
            acc[s][0] = fmaf(xv[s], w.x, acc[s][0]);
            acc[s][1] = fmaf(xv[s], w.y, acc[s][1]);
            acc[s][2] = fmaf(xv[s], w.z, acc[s][2]);
            acc[s][3] = fmaf(xv[s], w.w, acc[s][3]);
        }
    }

    #pragma unroll
    for (int s = 0; s < 4; s++) {
        int gi = n0 + ty + 16 * s;
        if (gi >= n) continue;
        float4 v = make_float4(acc[s][0], acc[s][1], acc[s][2], acc[s][3]);
        if (g < 4) ((float4*)g_y1)[gi * 4 + g]       = v;
        else       ((float4*)g_r1)[gi * 4 + (g - 4)] = v;
    }
}

// ---------------------------------------------------------------------
// gather1 + final fused: 8 lanes per node, unroll 2.
__global__ void __launch_bounds__(256) k_gather1(
    const float* __restrict__ bl1, const float* __restrict__ be1,
    float* __restrict__ out, int n)
{
    int t = blockIdx.x * 256 + threadIdx.x;
    int node = t >> 3;
    int sub = t & 7;
    if (node >= n) return;
    int beg = g_off[node];
    int end = g_off[node + 1];
    const float2* Y = (const float2*)g_y1;

    float2 acc = make_float2(0.f, 0.f);
    int e = beg;
    for (; e + 1 < end; e += 2) {
        int s0 = g_esrc[e];
        int s1 = g_esrc[e + 1];
        float2 v0 = Y[s0 * 8 + sub];
        float2 v1 = Y[s1 * 8 + sub];
        acc.x += v0.x + v1.x;
        acc.y += v0.y + v1.y;
    }
    if (e < end) {
        int s0 = g_esrc[e];
        float2 v0 = Y[s0 * 8 + sub];
        acc.x += v0.x;
        acc.y += v0.y;
    }
    float inv = 1.0f / fmaxf((float)(end - beg), 1.0f);
    float2 r = ((const float2*)g_r1 )[node * 8 + sub];
    float2 er = ((const float2*)g_er1)[node * 8 + sub];
    float2 o;
    o.x = fmaf(acc.x, inv, r.x + er.x + bl1[2*sub+0] + be1[2*sub+0]);
    o.y = fmaf(acc.y, inv, r.y + er.y + bl1[2*sub+1] + be1[2*sub+1]);
    ((float2*)out)[node * 8 + sub] = o;
}

// ---------------------------------------------------------------------
extern "C" void kernel_launch(void* const* d_in, const int* in_sizes, int n_in,
                              void* d_out, int out_size)
{
    const float* x_feat = (const float*)d_in[0];
    const float* x_emb  = (const float*)d_in[1];
    const int*   ei     = (const int*)  d_in[2];
    const float* Wl0 = (const float*)d_in[3];
    const float* bl0 = (const float*)d_in[4];
    const float* Wr0 = (const float*)d_in[5];
    const float* We0 = (const float*)d_in[6];
    const float* be0 = (const float*)d_in[7];
    const float* Wl1 = (const float*)d_in[8];
    const float* bl1 = (const float*)d_in[9];
    const float* Wr1 = (const float*)d_in[10];
    const float* We1 = (const float*)d_in[11];
    const float* be1 = (const float*)d_in[12];

    int n = in_sizes[0] / 128;
    int E = in_sizes[2] / 2;

    cudaFuncSetAttribute(k_transform0,
                         cudaFuncAttributeMaxDynamicSharedMemorySize, SM_TOTAL_MMA);

    cudaStream_t s2, s3;
    cudaStreamCreateWithFlags(&s2, cudaStreamNonBlocking);
    cudaStreamCreateWithFlags(&s3, cudaStreamNonBlocking);
    cudaEvent_t evFork, ev2, ev3;
    cudaEventCreateWithFlags(&evFork, cudaEventDisableTiming);
    cudaEventCreateWithFlags(&ev2, cudaEventDisableTiming);
    cudaEventCreateWithFlags(&ev3, cudaEventDisableTiming);

    // (1) CSR count+scan — cooperative kernel runs ALONE
    k_zero_cnt<<<(n + 255) / 256, 256>>>(n);
    {
        int G = (n + 255) / 256;
        void* args[] = { (void*)&ei, (void*)&n, (void*)&E };
        cudaLaunchCooperativeKernel((void*)k_csr_build, dim3(G), dim3(256), args, 0, 0);
    }

    // fork: fill (s2); emb0 + er1 (s3); transform0 (main)
    cudaEventRecord(evFork, 0);
    cudaStreamWaitEvent(s2, evFork, 0);
    cudaStreamWaitEvent(s3, evFork, 0);

    k_fill<<<(E / 4 + 255) / 256, 256, 0, s2>>>(ei, E);
    cudaEventRecord(ev2, s2);

    k_emb0<<<(n + 63) / 64, 128, 0, s3>>>(x_emb, We0, be0, n);
    k_er1<<<(n + 63) / 64, 128, 0, s3>>>(We1, n);
    cudaEventRecord(ev3, s3);

    k_transform0<<<148, 256, SM_TOTAL_MMA>>>(x_feat, Wl0, Wr0, bl0, n);

    // join before gather0
    cudaStreamWaitEvent(0, ev2, 0);
    cudaStreamWaitEvent(0, ev3, 0);

    // (2) layer-0 aggregate + combine
    k_gather0<<<(n + 7) / 8, 256>>>(n);

    // (3)(4) layer 1 (transform1 = y1/r1 only; er1 already done)
    k_transform1<<<(n + 63) / 64, 128>>>(Wl1, Wr1, n);
    k_gather1<<<(n * 8 + 255) / 256, 256>>>(bl1, be1, (float*)d_out, n);

    cudaEventDestroy(evFork);
    cudaEventDestroy(ev2);
    cudaEventDestroy(ev3);
    cudaStreamDestroy(s2);
    cudaStreamDestroy(s3);
}

// round 17
// speedup vs baseline: 1.3423x; 1.0193x over previous
#include <cuda_runtime.h>
#include <cuda_bf16.h>
#include <cooperative_groups.h>
#include <cstdint>

namespace cg = cooperative_groups;

#define NODES 100000
#define EDGES 1600000

// ---- device scratch (allocation-free contract: __device__ globals) ----
__device__ __align__(16) float g_y0  [NODES*64];
__device__ __align__(16) float g_base[NODES*64];
__device__ __align__(16) float g_e0  [NODES*64];
__device__ __align__(16) float g_h   [NODES*64];
__device__ __align__(16) float g_y1  [NODES*16];
__device__ __align__(16) float g_r1  [NODES*16];
__device__ __align__(16) float g_er1 [NODES*16];
// CSR-by-dst
__device__ int g_cnt [NODES];
__device__ int g_off [NODES + 1];
__device__ int g_cur [NODES];
__device__ int g_esrc[EDGES];
__device__ int g_bsum[1024];

#if defined(__CUDA_ARCH__) && (defined(__CUDA_ARCH_FEAT_SM103_ALL) || defined(__CUDA_ARCH_FEAT_SM100_ALL))
#define HAS_TCGEN05 1
#else
#define HAS_TCGEN05 0
#endif

// ======================= CSR build =====================================
__global__ void k_zero_cnt(int n) {
    int i = blockIdx.x * blockDim.x + threadIdx.x;
    if (i < n) g_cnt[i] = 0;
}

__global__ void __launch_bounds__(256) k_csr_build(const int* __restrict__ ei,
                                                   int n, int E)
{
    cg::grid_group grid = cg::this_grid();
    const int tid = threadIdx.x;
    const int b   = blockIdx.x;
    const int G   = gridDim.x;
    const int lane = tid & 31;
    const int w    = tid >> 5;
    __shared__ int ws[8];

    {
        const int4* D4 = (const int4*)(ei + E);
        int q = E >> 2;
        for (int i = b * 256 + tid; i < q; i += G * 256) {
            int4 d = D4[i];
            atomicAdd(&g_cnt[d.x], 1);
            atomicAdd(&g_cnt[d.y], 1);
            atomicAdd(&g_cnt[d.z], 1);
            atomicAdd(&g_cnt[d.w], 1);
        }
        for (int e = (q << 2) + b * 256 + tid; e < E; e += G * 256)
            atomicAdd(&g_cnt[ei[E + e]], 1);
    }
    grid.sync();

    {
        int i = b * 256 + tid;
        int v = (i < n) ? g_cnt[i] : 0;
        int x = v;
        #pragma unroll
        for (int d = 1; d < 32; d <<= 1) {
            int t = __shfl_up_sync(0xFFFFFFFF, x, d);
            if (lane >= d) x += t;
        }
        if (lane == 31) ws[w] = x;
        __syncthreads();
        int base = 0;
        #pragma unroll
        for (int k = 0; k < 8; k++) base += (k < w) ? ws[k] : 0;
        int incl = base + x;
        if (i < n) g_off[i] = incl - v;
        if (tid == 0) {
            int tot = 0;
            #pragma unroll
            for (int k = 0; k < 8; k++) tot += ws[k];
            g_bsum[b] = tot;
        }
    }
    grid.sync();

    if (b == 0) {
        int per = (G + 255) / 256;
        int s[4];
        int sum = 0;
        #pragma unroll 4
        for (int j = 0; j < per; j++) {
            int idx = tid * per + j;
            s[j] = (idx < G) ? g_bsum[idx] : 0;
            sum += s[j];
        }
        int x = sum;
        #pragma unroll
        for (int d = 1; d < 32; d <<= 1) {
            int t = __shfl_up_sync(0xFFFFFFFF, x, d);
            if (lane >= d) x += t;
        }
        if (lane == 31) ws[w] = x;
        __syncthreads();
        int base = 0;
        #pragma unroll
        for (int k = 0; k < 8; k++) base += (k < w) ? ws[k] : 0;
        int run = base + x - sum;
        #pragma unroll 4
        for (int j = 0; j < per; j++) {
            int idx = tid * per + j;
            if (idx < G) { g_bsum[idx] = run; run += s[j]; }
        }
    }
    grid.sync();

    {
        int i = b * 256 + tid;
        if (i < n) {
            int o = g_off[i] + g_bsum[b];
            g_off[i] = o;
            g_cur[i] = o;
        }
        if (b == 0 && tid == 0) g_off[n] = E;
    }
}

__global__ void k_fill(const int* __restrict__ ei, int E) {
    int q = E >> 2;
    int i = blockIdx.x * blockDim.x + threadIdx.x;
    const int4* S4 = (const int4*)ei;
    const int4* D4 = (const int4*)(ei + E);
    if (i < q) {
        int4 s = S4[i];
        int4 d = D4[i];
        g_esrc[atomicAdd(&g_cur[d.x], 1)] = s.x;
        g_esrc[atomicAdd(&g_cur[d.y], 1)] = s.y;
        g_esrc[atomicAdd(&g_cur[d.z], 1)] = s.z;
        g_esrc[atomicAdd(&g_cur[d.w], 1)] = s.w;
    }
    int e = (q << 2) + i;
    if (i < (E - (q << 2))) {
        int dst = ei[E + e];
        g_esrc[atomicAdd(&g_cur[dst], 1)] = ei[e];
    }
}

// ================= persistent transform0 smem layout =================
static constexpr int SM_BH   = 0;
static constexpr int SM_BL   = 32768;
static constexpr int SM_A0H  = 65536;
static constexpr int SM_A0L  = 98304;
static constexpr int SM_A1H  = 131072;
static constexpr int SM_A1L  = 163840;
static constexpr int SM_TMEM = 196608;
static constexpr int SM_MBAR0= 196616;
static constexpr int SM_MBAR1= 196624;
static constexpr int SM_TOTAL_MMA = 196640;

#if HAS_TCGEN05
__device__ __forceinline__ uint32_t smem_u32(const void* p) {
    uint32_t a;
    asm("{ .reg .u64 t; cvta.to.shared.u64 t, %1; cvt.u32.u64 %0, t; }"
        : "=r"(a) : "l"(p));
    return a;
}

__device__ __forceinline__ uint32_t elect_one() {
    uint32_t pred;
    asm volatile("{ .reg .pred p; elect.sync _|p, 0xFFFFFFFF; selp.b32 %0, 1, 0, p; }"
                 : "=r"(pred));
    return pred;
}

static constexpr uint32_t MMA_IDESC = (1u<<4) | (1u<<7) | (1u<<10)
                                    | ((128u/8u)<<17) | ((128u/16u)<<24);

static constexpr uint64_t DESC_BASE =
    (uint64_t(2) << 61) | (uint64_t(1) << 46) | (uint64_t(64) << 32) | (uint64_t(1) << 16);

__device__ __forceinline__ uint64_t make_desc(uint32_t addr) {
    return DESC_BASE | ((uint64_t)(addr >> 4) & 0x3FFF);
}

__device__ __forceinline__ void mma_bf16_ss(uint32_t d_tmem, uint64_t a_desc,
                                            uint64_t b_desc, uint32_t en) {
    asm volatile(
        "{\n\t"
        ".reg .pred p;\n\t"
        "setp.ne.u32 p, %4, 0;\n\t"
        "tcgen05.mma.cta_group::1.kind::f16 [%0], %1, %2, %3, {%5, %5, %5, %5}, p;\n\t"
        "}"
        :: "r"(d_tmem), "l"(a_desc), "l"(b_desc), "r"(MMA_IDESC),
           "r"(en), "r"(0u)
        : "memory");
}

__device__ __forceinline__ void mbar_wait(uint32_t mbar, uint32_t parity) {
    uint32_t done;
    asm volatile(
        "{\n\t.reg .pred p;\n\t"
        "mbarrier.try_wait.parity.acquire.cta.shared::cta.b64 p, [%1], %2;\n\t"
        "selp.b32 %0, 1, 0, p;\n\t}"
        : "=r"(done) : "r"(mbar), "r"(parity) : "memory");
    if (!done) {
        asm volatile(
            "{\n\t.reg .pred P1;\n\t"
            "WAIT_LOOP_%=:\n\t"
            "mbarrier.try_wait.parity.acquire.cta.shared::cta.b64 P1, [%0], %1, 0x989680;\n\t"
            "@P1 bra.uni WAIT_DONE_%=;\n\t"
            "bra.uni WAIT_LOOP_%=;\n\t"
            "WAIT_DONE_%=:\n\t}"
            :: "r"(mbar), "r"(parity) : "memory");
    }
}

#define TCLD_X32(r, addr) \
    asm volatile( \
        "tcgen05.ld.sync.aligned.32x32b.x32.b32 " \
        "{%0, %1, %2, %3, %4, %5, %6, %7, " \
        " %8, %9, %10, %11, %12, %13, %14, %15, " \
        " %16, %17, %18, %19, %20, %21, %22, %23, " \
        " %24, %25, %26, %27, %28, %29, %30, %31}, [%32];" \
        : "=r"((r)[0]), "=r"((r)[1]), "=r"((r)[2]), "=r"((r)[3]), \
          "=r"((r)[4]), "=r"((r)[5]), "=r"((r)[6]), "=r"((r)[7]), \
          "=r"((r)[8]), "=r"((r)[9]), "=r"((r)[10]), "=r"((r)[11]), \
          "=r"((r)[12]), "=r"((r)[13]), "=r"((r)[14]), "=r"((r)[15]), \
          "=r"((r)[16]), "=r"((r)[17]), "=r"((r)[18]), "=r"((r)[19]), \
          "=r"((r)[20]), "=r"((r)[21]), "=r"((r)[22]), "=r"((r)[23]), \
          "=r"((r)[24]), "=r"((r)[25]), "=r"((r)[26]), "=r"((r)[27]), \
          "=r"((r)[28]), "=r"((r)[29]), "=r"((r)[30]), "=r"((r)[31]) \
        : "r"(addr))
#endif

__device__ __forceinline__ uint32_t tile_off(int row, int k) {
    uint32_t off = (uint32_t)((row >> 3) + (k >> 6) * 16) * 1024
                 + (uint32_t)(row & 7) * 128 + (uint32_t)(k & 63) * 2;
    return off ^ ((off >> 3) & 0x70);
}

// exact RN split (used for B, staged once)
__device__ __forceinline__ void cvt_store_hl(char* ph, char* pl, float4 v) {
    __nv_bfloat16 h0 = __float2bfloat16(v.x);
    __nv_bfloat16 h1 = __float2bfloat16(v.y);
    __nv_bfloat16 h2 = __float2bfloat16(v.z);
    __nv_bfloat16 h3 = __float2bfloat16(v.w);
    __nv_bfloat16 l0 = __float2bfloat16(v.x - __bfloat162float(h0));
    __nv_bfloat16 l1 = __float2bfloat16(v.y - __bfloat162float(h1));
    __nv_bfloat16 l2 = __float2bfloat16(v.z - __bfloat162float(h2));
    __nv_bfloat16 l3 = __float2bfloat16(v.w - __bfloat162float(h3));
    union { __nv_bfloat162 b[2]; uint64_t u; } uh, ul;
    uh.b[0] = __halves2bfloat162(h0, h1);
    uh.b[1] = __halves2bfloat162(h2, h3);
    ul.b[0] = __halves2bfloat162(l0, l1);
    ul.b[1] = __halves2bfloat162(l2, l3);
    *(uint64_t*)ph = uh.u;
    *(uint64_t*)pl = ul.u;
}

#if HAS_TCGEN05
// fast truncation split (used for A, staged per-tile):
// hi = top 16 bits (PRMT pack), lo = rn(v - hi) via cvt.rn.bf16x2.f32
__device__ __forceinline__ void cvt_store_hl_fast(char* ph, char* pl, float4 v) {
    uint32_t ux = __float_as_uint(v.x);
    uint32_t uy = __float_as_uint(v.y);
    uint32_t uz = __float_as_uint(v.z);
    uint32_t uw = __float_as_uint(v.w);
    uint32_t hi01 = __byte_perm(ux, uy, 0x7632);   // [bf16(x) | bf16(y)]
    uint32_t hi23 = __byte_perm(uz, uw, 0x7632);
    float lx = v.x - __uint_as_float(ux & 0xFFFF0000u);
    float ly = v.y - __uint_as_float(uy & 0xFFFF0000u);
    float lz = v.z - __uint_as_float(uz & 0xFFFF0000u);
    float lw = v.w - __uint_as_float(uw & 0xFFFF0000u);
    uint32_t lo01, lo23;
    asm("cvt.rn.bf16x2.f32 %0, %1, %2;" : "=r"(lo01) : "f"(ly), "f"(lx));
    asm("cvt.rn.bf16x2.f32 %0, %1, %2;" : "=r"(lo23) : "f"(lw), "f"(lz));
    uint2 h2v = make_uint2(hi01, hi23);
    uint2 l2v = make_uint2(lo01, lo23);
    *(uint2*)ph = h2v;
    *(uint2*)pl = l2v;
}
#endif

// ---------------------------------------------------------------------
// persistent transform0: [y0 | base] = x_feat @ [Wl0 ; Wr0]^T
__global__ void __launch_bounds__(256) k_transform0(
    const float* __restrict__ x, const float* __restrict__ Wl,
    const float* __restrict__ Wr, const float* __restrict__ bl, int n)
{
    extern __shared__ __align__(1024) char smem[];
    const int tid = threadIdx.x;
    const int T = (n + 127) / 128;

#if HAS_TCGEN05
    const int wid = tid >> 5;
    const int lid = tid & 31;
    const uint32_t sbase = smem_u32(smem);

    if (wid == 0) {
        asm volatile("tcgen05.alloc.cta_group::1.sync.aligned.shared::cta.b32 [%0], %1;"
                     :: "r"(sbase + SM_TMEM), "r"(256u) : "memory");
    }
    if (tid == 0) {
        asm volatile("mbarrier.init.shared.b64 [%0], %1;"
                     :: "r"(sbase + SM_MBAR0), "r"(1u) : "memory");
        asm volatile("mbarrier.init.shared.b64 [%0], %1;"
                     :: "r"(sbase + SM_MBAR1), "r"(1u) : "memory");
    }

    const float4* Wl4 = (const float4*)Wl;
    const float4* Wr4 = (const float4*)Wr;
    for (int m = tid; m < 128 * 32; m += 256) {
        int row = m >> 5, kq = m & 31;
        float4 v = (row < 64) ? Wl4[row * 32 + kq] : Wr4[(row - 64) * 32 + kq];
        uint32_t off = tile_off(row, kq * 4);
        cvt_store_hl(smem + SM_BH + off, smem + SM_BL + off, v);
    }
    __syncthreads();

    uint32_t tmem_base;
    asm volatile("ld.shared.b32 %0, [%1];" : "=r"(tmem_base) : "r"(sbase + SM_TMEM));

    const float4* X4 = (const float4*)x;
    const uint32_t abufH[2] = { sbase + SM_A0H, sbase + SM_A1H };
    const uint32_t mbar[2]  = { sbase + SM_MBAR0, sbase + SM_MBAR1 };
    uint64_t dB_h = make_desc(sbase + SM_BH);
    uint64_t dB_l = make_desc(sbase + SM_BL);
    int ph0 = 0, ph1 = 0;

    #define STAGE_A(tile, buf) do {                                         \
        int _n0 = (tile) * 128;                                             \
        char* _ah = smem + SM_A0H + (buf) * 65536;                          \
        char* _al = _ah + 32768;                                            \
        _Pragma("unroll")                                                   \
        for (int c = 0; c < 4; c++) {                                       \
            float4 v[4];                                                    \
            uint32_t off[4];                                                \
            _Pragma("unroll")                                               \
            for (int j = 0; j < 4; j++) {                                   \
                int m = tid + (c * 4 + j) * 256;                            \
                int row = m >> 5, kq = m & 31;                              \
                int gi = _n0 + row;                                         \
                v[j] = make_float4(0.f, 0.f, 0.f, 0.f);                     \
                if (gi < n) v[j] = X4[gi * 32 + kq];                        \
                off[j] = tile_off(row, kq * 4);                             \
            }                                                               \
            _Pragma("unroll")                                               \
            for (int j = 0; j < 4; j++)                                     \
                cvt_store_hl_fast(_ah + off[j], _al + off[j], v[j]);        \
        }                                                                   \
    } while (0)

    #define ISSUE_MMA(buf) do {                                             \
        if (wid == 0) {                                                      \
            if (elect_one()) {                                               \
                asm volatile("fence.proxy.async.shared::cta;" ::: "memory"); \
                uint64_t dAh = make_desc(abufH[buf]);                        \
                uint64_t dAl = make_desc(abufH[buf] + 32768);                \
                uint64_t pA[3] = { dAh, dAh, dAl };                          \
                uint64_t pB[3] = { dB_h, dB_l, dB_h };                       \
                uint32_t dst = tmem_base + (buf) * 128;                      \
                uint32_t en = 0;                                             \
                _Pragma("unroll")                                            \
                for (int p = 0; p < 3; p++) {                                \
                    _Pragma("unroll")                                        \
                    for (int ks = 0; ks < 8; ks++) {                         \
                        uint64_t doff = (uint64_t)((ks & 3) * 2 + (ks >> 2) * 1024); \
                        mma_bf16_ss(dst, pA[p] + doff, pB[p] + doff, en);    \
                        en = 1;                                              \
                    }                                                        \
                }                                                            \
                asm volatile(                                                \
                    "tcgen05.commit.cta_group::1.mbarrier::arrive::one.shared::cluster.b64 [%0];" \
                    :: "r"(mbar[buf]) : "memory");                           \
            }                                                                \
        }                                                                    \
    } while (0)

    int t = blockIdx.x;
    int k = 0;
    if (t < T) {
        STAGE_A(t, 0);
        __syncthreads();
        ISSUE_MMA(0);
    }
    for (; t < T; t += gridDim.x, k++) {
        int buf = k & 1;
        int tn = t + gridDim.x;
        if (tn < T) {
            STAGE_A(tn, buf ^ 1);
            __syncthreads();
            ISSUE_MMA(buf ^ 1);
        }
        if (buf == 0) { mbar_wait(mbar[0], ph0); ph0 ^= 1; }
        else          { mbar_wait(mbar[1], ph1); ph1 ^= 1; }
        asm volatile("tcgen05.fence::after_thread_sync;" ::: "memory");

        {
            int row = (wid & 3) * 32 + lid;
            int gi = t * 128 + row;
            uint32_t taddr = tmem_base + buf * 128 + ((uint32_t)(wid & 3) << 21)
                           + ((wid < 4) ? 0u : 64u);
            uint32_t r0[32], r1[32];
            TCLD_X32(r0, taddr);
            TCLD_X32(r1, taddr + 32);
            asm volatile("tcgen05.wait::ld.sync.aligned;" ::: "memory");
            if (gi < n) {
                if (wid < 4) {
                    #pragma unroll
                    for (int j = 0; j < 8; j++) {
                        float4 v = make_float4(__uint_as_float(r0[j*4+0]),
                                               __uint_as_float(r0[j*4+1]),
                                               __uint_as_float(r0[j*4+2]),
                                               __uint_as_float(r0[j*4+3]));
                        ((float4*)g_y0)[gi * 16 + j] = v;
                    }
                    #pragma unroll
                    for (int j = 0; j < 8; j++) {
                        float4 v = make_float4(__uint_as_float(r1[j*4+0]),
                                               __uint_as_float(r1[j*4+1]),
                                               __uint_as_float(r1[j*4+2]),
                                               __uint_as_float(r1[j*4+3]));
                        ((float4*)g_y0)[gi * 16 + 8 + j] = v;
                    }
                } else {
                    #pragma unroll
                    for (int j = 0; j < 8; j++) {
                        float4 bb = ((const float4*)bl)[j];
                        float4 v = make_float4(__uint_as_float(r0[j*4+0]) + bb.x,
                                               __uint_as_float(r0[j*4+1]) + bb.y,
                                               __uint_as_float(r0[j*4+2]) + bb.z,
                                               __uint_as_float(r0[j*4+3]) + bb.w);
                        ((float4*)g_base)[gi * 16 + j] = v;
                    }
                    #pragma unroll
                    for (int j = 0; j < 8; j++) {
                        float4 bb = ((const float4*)bl)[8 + j];
                        float4 v = make_float4(__uint_as_float(r1[j*4+0]) + bb.x,
                                               __uint_as_float(r1[j*4+1]) + bb.y,
                                               __uint_as_float(r1[j*4+2]) + bb.z,
                                               __uint_as_float(r1[j*4+3]) + bb.w);
                        ((float4*)g_base)[gi * 16 + 8 + j] = v;
                    }
                }
            }
            asm volatile("tcgen05.fence::before_thread_sync;" ::: "memory");
        }
        __syncthreads();
    }
    if (wid == 0) {
        asm volatile("tcgen05.dealloc.cta_group::1.sync.aligned.b32 %0, %1;"
                     :: "r"(tmem_base), "r"(256u));
    }
    #undef STAGE_A
    #undef ISSUE_MMA

#else  // ---------------- FFMA fallback (compute_103 PTX pass) ----------------
    float* Ws = (float*)smem;
    float* Xs = (float*)smem + 128 * 128;

    const float4* Wl4 = (const float4*)Wl;
    const float4* Wr4 = (const float4*)Wr;
    for (int m = tid; m < 64 * 32; m += 256) {
        int o  = m & 63;
        int kq = m >> 6;
        float4 a = Wl4[o * 32 + kq];
        float4 b = Wr4[o * 32 + kq];
        int k = kq * 4;
        Ws[(k+0)*128 + o] = a.x;  Ws[(k+1)*128 + o] = a.y;
        Ws[(k+2)*128 + o] = a.z;  Ws[(k+3)*128 + o] = a.w;
        Ws[(k+0)*128 + 64 + o] = b.x;  Ws[(k+1)*128 + 64 + o] = b.y;
        Ws[(k+2)*128 + 64 + o] = b.z;  Ws[(k+3)*128 + 64 + o] = b.w;
    }
    const float4* X4 = (const float4*)x;
    float4* Xs4 = (float4*)Xs;

    for (int t = blockIdx.x; t < T; t += gridDim.x) {
        int n0 = t * 128;
        __syncthreads();
        for (int m = tid; m < 128 * 32; m += 256) {
            int node = m >> 5;
            int kq   = m & 31;
            int gi = n0 + node;
            float4 v = make_float4(0.f, 0.f, 0.f, 0.f);
            if (gi < n) v = X4[gi * 32 + kq];
            Xs4[node * 32 + kq] = v;
        }
        __syncthreads();

        const int tx = tid & 15;
        const int ty = tid >> 4;
        float acc[8][8];
        #pragma unroll
        for (int s = 0; s < 8; s++)
            #pragma unroll
            for (int r = 0; r < 8; r++) acc[s][r] = 0.f;

        const float4* Ws4c = (const float4*)Ws;
        const float4* Xs4c = (const float4*)Xs;

        for (int k = 0; k < 128; k += 4) {
            float4 xv[8];
            #pragma unroll
            for (int s = 0; s < 8; s++)
                xv[s] = Xs4c[((ty + 16 * s) * 128 + k) >> 2];
            #pragma unroll
            for (int kk = 0; kk < 4; kk++) {
                float4 wa = Ws4c[((k + kk) * 128 >> 2) + tx];
                float4 wb = Ws4c[(((k + kk) * 128 + 64) >> 2) + tx];
                #pragma unroll
                for (int s = 0; s < 8; s++) {
                    float xs = (kk == 0) ? xv[s].x : (kk == 1) ? xv[s].y
                             : (kk == 2) ? xv[s].z : xv[s].w;
                    acc[s][0] = fmaf(xs, wa.x, acc[s][0]);
                    acc[s][1] = fmaf(xs, wa.y, acc[s][1]);
                    acc[s][2] = fmaf(xs, wa.z, acc[s][2]);
                    acc[s][3] = fmaf(xs, wa.w, acc[s][3]);
                    acc[s][4] = fmaf(xs, wb.x, acc[s][4]);
                    acc[s][5] = fmaf(xs, wb.y, acc[s][5]);
                    acc[s][6] = fmaf(xs, wb.z, acc[s][6]);
                    acc[s][7] = fmaf(xs, wb.w, acc[s][7]);
                }
            }
        }

        float4 bb = ((const float4*)bl)[tx];
        #pragma unroll
        for (int s = 0; s < 8; s++) {
            int gi = n0 + ty + 16 * s;
            if (gi >= n) continue;
            float4 v0 = make_float4(acc[s][0], acc[s][1], acc[s][2], acc[s][3]);
            float4 v1 = make_float4(acc[s][4] + bb.x, acc[s][5] + bb.y,
                                    acc[s][6] + bb.z, acc[s][7] + bb.w);
            ((float4*)g_y0)  [gi * 16 + tx] = v0;
            ((float4*)g_base)[gi * 16 + tx] = v1;
        }
    }
#endif
}

// ---------------------------------------------------------------------
// e0 = mean(x_emb, axis=1) @ We0^T + be0
__global__ void __launch_bounds__(128) k_emb0(
    const float* __restrict__ xe, const float* __restrict__ We,
    const float* __restrict__ be, int n)
{
    __shared__ __align__(16) float Ws[64 * 64];
    __shared__ __align__(16) float Xs[64 * 64];
    const int tid = threadIdx.x;
    const int n0 = blockIdx.x * 64;

    const float4* W4 = (const float4*)We;
    for (int m = tid; m < 64 * 16; m += 128) {
        int o  = m & 63;
        int kq = m >> 6;
        float4 a = W4[o * 16 + kq];
        int k = kq * 4;
        Ws[(k+0)*64 + o] = a.x;  Ws[(k+1)*64 + o] = a.y;
        Ws[(k+2)*64 + o] = a.z;  Ws[(k+3)*64 + o] = a.w;
    }
    const float4* E4 = (const float4*)xe;
    float4* Xs4 = (float4*)Xs;
    for (int m = tid; m < 64 * 16; m += 128) {
        int node = m >> 4;
        int kq   = m & 15;
        int gi = n0 + node;
        float4 v = make_float4(0.f, 0.f, 0.f, 0.f);
        if (gi < n) {
            float4 a = E4[gi * 32 + kq];
            float4 b = E4[gi * 32 + 16 + kq];
            v = make_float4(0.5f*(a.x+b.x), 0.5f*(a.y+b.y),
                            0.5f*(a.z+b.z), 0.5f*(a.w+b.w));
        }
        Xs4[node * 16 + kq] = v;
    }
    __syncthreads();

    const int tx = tid & 15;
    const int ty = tid >> 4;
    float acc[8][4];
    #pragma unroll
    for (int s = 0; s < 8; s++)
        #pragma unroll
        for (int r = 0; r < 4; r++) acc[s][r] = 0.f;

    const float4* Ws4c = (const float4*)Ws;
    const float4* Xs4c = (const float4*)Xs;

    for (int k = 0; k < 64; k += 4) {
        float4 xv[8];
        #pragma unroll
        for (int s = 0; s < 8; s++)
            xv[s] = Xs4c[((ty + 8 * s) * 64 + k) >> 2];
        #pragma unroll
        for (int kk = 0; kk < 4; kk++) {
            float4 w = Ws4c[((k + kk) * 64 >> 2) + tx];
            #pragma unroll
            for (int s = 0; s < 8; s++) {
                float xs = (kk == 0) ? xv[s].x : (kk == 1) ? xv[s].y
                         : (kk == 2) ? xv[s].z : xv[s].w;
                acc[s][0] = fmaf(xs, w.x, acc[s][0]);
                acc[s][1] = fmaf(xs, w.y, acc[s][1]);
                acc[s][2] = fmaf(xs, w.z, acc[s][2]);
                acc[s][3] = fmaf(xs, w.w, acc[s][3]);
            }
        }
    }

    float4 bb = ((const float4*)be)[tx];
    #pragma unroll
    for (int s = 0; s < 8; s++) {
        int gi = n0 + ty + 8 * s;
        if (gi >= n) continue;
        float4 v = make_float4(acc[s][0] + bb.x, acc[s][1] + bb.y,
                               acc[s][2] + bb.z, acc[s][3] + bb.w);
        ((float4*)g_e0)[gi * 16 + tx] = v;
    }
}

// ---------------------------------------------------------------------
// er1 = e0 @ We1^T  (16 outputs) — side stream, hidden.
__global__ void __launch_bounds__(128) k_er1(
    const float* __restrict__ We1, int n)
{
    __shared__ __align__(16) float Es[64 * 64];
    __shared__ __align__(16) float Ws[64 * 16];
    const int tid = threadIdx.x;
    const int n0 = blockIdx.x * 64;

    const float4* W4 = (const float4*)We1;
    for (int m = tid; m < 16 * 16; m += 128) {
        int o  = m & 15;
        int kq = m >> 4;
        float4 a = W4[o * 16 + kq];
        int k = kq * 4;
        Ws[(k+0)*16 + o] = a.x;  Ws[(k+1)*16 + o] = a.y;
        Ws[(k+2)*16 + o] = a.z;  Ws[(k+3)*16 + o] = a.w;
    }
    float4* Es4 = (float4*)Es;
    for (int m = tid; m < 64 * 16; m += 128) {
        int node = m >> 4;
        int kq   = m & 15;
        int gi = n0 + node;
        float4 v = make_float4(0.f, 0.f, 0.f, 0.f);
        if (gi < n) v = ((const float4*)g_e0)[gi * 16 + kq];
        Es4[node * 16 + kq] = v;
    }
    __syncthreads();

    const int g  = tid & 3;
    const int ty = tid >> 2;
    const float4* Ws4c = (const float4*)Ws;
    float acc[2][4];
    #pragma unroll
    for (int s = 0; s < 2; s++)
        #pragma unroll
        for (int r = 0; r < 4; r++) acc[s][r] = 0.f;

    for (int k = 0; k < 64; k++) {
        float4 w = Ws4c[k * 4 + g];
        float x0 = Es[ty * 64 + k];
        float x1 = Es[(ty + 32) * 64 + k];
        acc[0][0] = fmaf(x0, w.x, acc[0][0]);
        acc[0][1] = fmaf(x0, w.y, acc[0][1]);
        acc[0][2] = fmaf(x0, w.z, acc[0][2]);
        acc[0][3] = fmaf(x0, w.w, acc[0][3]);
        acc[1][0] = fmaf(x1, w.x, acc[1][0]);
        acc[1][1] = fmaf(x1, w.y, acc[1][1]);
        acc[1][2] = fmaf(x1, w.z, acc[1][2]);
        acc[1][3] = fmaf(x1, w.w, acc[1][3]);
    }

    #pragma unroll
    for (int s = 0; s < 2; s++) {
        int gi = n0 + ty + 32 * s;
        if (gi >= n) continue;
        ((float4*)g_er1)[gi * 4 + g] =
            make_float4(acc[s][0], acc[s][1], acc[s][2], acc[s][3]);
    }
}

// ---------------------------------------------------------------------
// gather0 + combine0 fused: one warp per node, unroll 4.
__global__ void __launch_bounds__(256) k_gather0(int n) {
    int warp = (blockIdx.x * 256 + threadIdx.x) >> 5;
    int lane = threadIdx.x & 31;
    if (warp >= n) return;
    int beg = g_off[warp];
    int end = g_off[warp + 1];
    const float2* Y = (const float2*)g_y0;

    float2 acc = make_float2(0.f, 0.f);
    int e = beg;
    for (; e + 3 < end; e += 4) {
        int s0 = g_esrc[e];
        int s1 = g_esrc[e + 1];
        int s2 = g_esrc[e + 2];
        int s3 = g_esrc[e + 3];
        float2 v0 = Y[s0 * 32 + lane];
        float2 v1 = Y[s1 * 32 + lane];
        float2 v2 = Y[s2 * 32 + lane];
        float2 v3 = Y[s3 * 32 + lane];
        acc.x += (v0.x + v1.x) + (v2.x + v3.x);
        acc.y += (v0.y + v1.y) + (v2.y + v3.y);
    }
    for (; e < end; e++) {
        int s0 = g_esrc[e];
        float2 v0 = Y[s0 * 32 + lane];
        acc.x += v0.x;
        acc.y += v0.y;
    }
    float inv = 1.0f / fmaxf((float)(end - beg), 1.0f);
    float2 b = ((const float2*)g_base)[warp * 32 + lane];
    float2 e0 = ((const float2*)g_e0)[warp * 32 + lane];
    float2 h;
    h.x = fmaxf(fmaf(acc.x, inv, b.x + e0.x), 0.f);
    h.y = fmaxf(fmaf(acc.y, inv, b.y + e0.y), 0.f);
    ((float2*)g_h)[warp * 32 + lane] = h;
}

// ---------------------------------------------------------------------
// Layer-1 node transforms (y1/r1 only).
__global__ void __launch_bounds__(128) k_transform1(
    const float* __restrict__ Wl1, const float* __restrict__ Wr1, int n)
{
    __shared__ __align__(16) float Hs[64 * 64];
    __shared__ __align__(16) float Ws[64 * 32];
    const int tid = threadIdx.x;
    const int n0 = blockIdx.x * 64;

    for (int m = tid; m < 32 * 16; m += 128) {
        int o  = m & 31;
        int kq = m >> 5;
        const float4* src = (o < 16) ? ((const float4*)Wl1) + o * 16
                                     : ((const float4*)Wr1) + (o - 16) * 16;
        float4 a = src[kq];
        int k = kq * 4;
        Ws[(k+0)*32 + o] = a.x;  Ws[(k+1)*32 + o] = a.y;
        Ws[(k+2)*32 + o] = a.z;  Ws[(k+3)*32 + o] = a.w;
    }
    float4* Hs4 = (float4*)Hs;
    for (int m = tid; m < 64 * 16; m += 128) {
        int node = m >> 4;
        int kq   = m & 15;
        int gi = n0 + node;
        float4 v = make_float4(0.f, 0.f, 0.f, 0.f);
        if (gi < n) v = ((const float4*)g_h)[gi * 16 + kq];
        Hs4[node * 16 + kq] = v;
    }
    __syncthreads();

    const int g  = tid & 7;
    const int ty = tid >> 3;
    const float4* Ws4c = (const float4*)Ws;
    float acc[4][4];
    #pragma unroll
    for (int s = 0; s < 4; s++)
        #pragma unroll
        for (int r = 0; r < 4; r++) acc[s][r] = 0.f;

    for (int k = 0; k < 64; k++) {
        float4 w = Ws4c[k * 8 + g];
        float xv[4];
        #pragma unroll
        for (int s = 0; s < 4; s++) xv[s] = Hs[(ty + 16 * s) * 64 + k];
        #pragma unroll
        for (int s = 0; s < 4; s++) {
            acc[s][0] = fmaf(xv[s], w.x, acc[s][0]);
            acc[s][1] = fmaf(xv[s], w.y, acc[s][1]);
            acc[s][2] = fmaf(xv[s], w.z, acc[s][2]);
            acc[s][3] = fmaf(xv[s], w.w, acc[s][3]);
        }
    }

    #pragma unroll
    for (int s = 0; s < 4; s++) {
        int gi = n0 + ty + 16 * s;
        if (gi >= n) continue;
        float4 v = make_float4(acc[s][0], acc[s][1], acc[s][2], acc[s][3]);
        if (g < 4) ((float4*)g_y1)[gi * 4 + g]       = v;
        else       ((float4*)g_r1)[gi * 4 + (g - 4)] = v;
    }
}

// ---------------------------------------------------------------------
// gather1 + final fused: 8 lanes per node, unroll 2.
__global__ void __launch_bounds__(256) k_gather1(
    const float* __restrict__ bl1, const float* __restrict__ be1,
    float* __restrict__ out, int n)
{
    int t = blockIdx.x * 256 + threadIdx.x;
    int node = t >> 3;
    int sub = t & 7;
    if (node >= n) return;
    int beg = g_off[node];
    int end = g_off[node + 1];
    const float2* Y = (const float2*)g_y1;

    float2 acc = make_float2(0.f, 0.f);
    int e = beg;
    for (; e + 1 < end; e += 2) {
        int s0 = g_esrc[e];
        int s1 = g_esrc[e + 1];
        float2 v0 = Y[s0 * 8 + sub];
        float2 v1 = Y[s1 * 8 + sub];
        acc.x += v0.x + v1.x;
        acc.y += v0.y + v1.y;
    }
    if (e < end) {
        int s0 = g_esrc[e];
        float2 v0 = Y[s0 * 8 + sub];
        acc.x += v0.x;
        acc.y += v0.y;
    }
    float inv = 1.0f / fmaxf((float)(end - beg), 1.0f);
    float2 r = ((const float2*)g_r1 )[node * 8 + sub];
    float2 er = ((const float2*)g_er1)[node * 8 + sub];
    float2 o;
    o.x = fmaf(acc.x, inv, r.x + er.x + bl1[2*sub+0] + be1[2*sub+0]);
    o.y = fmaf(acc.y, inv, r.y + er.y + bl1[2*sub+1] + be1[2*sub+1]);
    ((float2*)out)[node * 8 + sub] = o;
}

// ---------------------------------------------------------------------
extern "C" void kernel_launch(void* const* d_in, const int* in_sizes, int n_in,
                              void* d_out, int out_size)
{
    const float* x_feat = (const float*)d_in[0];
    const float* x_emb  = (const float*)d_in[1];
    const int*   ei     = (const int*)  d_in[2];
    const float* Wl0 = (const float*)d_in[3];
    const float* bl0 = (const float*)d_in[4];
    const float* Wr0 = (const float*)d_in[5];
    const float* We0 = (const float*)d_in[6];
    const float* be0 = (const float*)d_in[7];
    const float* Wl1 = (const float*)d_in[8];
    const float* bl1 = (const float*)d_in[9];
    const float* Wr1 = (const float*)d_in[10];
    const float* We1 = (const float*)d_in[11];
    const float* be1 = (const float*)d_in[12];

    int n = in_sizes[0] / 128;
    int E = in_sizes[2] / 2;

    cudaFuncSetAttribute(k_transform0,
                         cudaFuncAttributeMaxDynamicSharedMemorySize, SM_TOTAL_MMA);

    cudaStream_t s2, s3;
    cudaStreamCreateWithFlags(&s2, cudaStreamNonBlocking);
    cudaStreamCreateWithFlags(&s3, cudaStreamNonBlocking);
    cudaEvent_t evStart, evFork, ev2, ev3;
    cudaEventCreateWithFlags(&evStart, cudaEventDisableTiming);
    cudaEventCreateWithFlags(&evFork, cudaEventDisableTiming);
    cudaEventCreateWithFlags(&ev2, cudaEventDisableTiming);
    cudaEventCreateWithFlags(&ev3, cudaEventDisableTiming);

    // fork s3 immediately: emb0 + er1 overlap zero+csr (no data deps)
    cudaEventRecord(evStart, 0);
    cudaStreamWaitEvent(s3, evStart, 0);
    k_emb0<<<(n + 63) / 64, 128, 0, s3>>>(x_emb, We0, be0, n);
    k_er1<<<(n + 63) / 64, 128, 0, s3>>>(We1, n);
    cudaEventRecord(ev3, s3);

    // (1) CSR count+scan (main stream)
    k_zero_cnt<<<(n + 255) / 256, 256>>>(n);
    {
        int G = (n + 255) / 256;
        void* args[] = { (void*)&ei, (void*)&n, (void*)&E };
        cudaLaunchCooperativeKernel((void*)k_csr_build, dim3(G), dim3(256), args, 0, 0);
    }

    // fork s2: fill runs concurrently with transform0
    cudaEventRecord(evFork, 0);
    cudaStreamWaitEvent(s2, evFork, 0);
    k_fill<<<(E / 4 + 255) / 256, 256, 0, s2>>>(ei, E);
    cudaEventRecord(ev2, s2);

    k_transform0<<<148, 256, SM_TOTAL_MMA>>>(x_feat, Wl0, Wr0, bl0, n);

    // join before gather0
    cudaStreamWaitEvent(0, ev2, 0);
    cudaStreamWaitEvent(0, ev3, 0);

    // (2) layer-0 aggregate + combine
    k_gather0<<<(n + 7) / 8, 256>>>(n);

    // (3)(4) layer 1
    k_transform1<<<(n + 63) / 64, 128>>>(Wl1, Wr1, n);
    k_gather1<<<(n * 8 + 255) / 256, 256>>>(bl1, be1, (float*)d_out, n);

    cudaEventDestroy(evStart);
    cudaEventDestroy(evFork);
    cudaEventDestroy(ev2);
    cudaEventDestroy(ev3);
    cudaStreamDestroy(s2);
    cudaStreamDestroy(s3);
}